// round 11
// baseline (speedup 1.0000x reference)
#include <cuda_runtime.h>
#include <cuda_fp16.h>
#include <cstdint>

typedef unsigned short u16;
typedef unsigned int   u32;

constexpr int STR = 72;   // smem row stride in halves (conflict-free for ldsm)

// ─── helpers ───────────────────────────────────────────────────────────────
__device__ __forceinline__ u32 smem_u32(const void* p){
    u32 a;
    asm("{ .reg .u64 t; cvta.to.shared.u64 t, %1; cvt.u32.u64 %0, t; }"
        : "=r"(a) : "l"(p));
    return a;
}
__device__ __forceinline__ void ldsm4(u32 addr, u32& r0, u32& r1, u32& r2, u32& r3){
    asm volatile("ldmatrix.sync.aligned.m8n8.x4.shared.b16 {%0,%1,%2,%3}, [%4];"
        : "=r"(r0), "=r"(r1), "=r"(r2), "=r"(r3) : "r"(addr));
}
__device__ __forceinline__ void mma_(float* c, const u32* a, u32 b0, u32 b1){
    asm volatile("mma.sync.aligned.m16n8k16.row.col.f32.f16.f16.f32 "
        "{%0,%1,%2,%3},{%4,%5,%6,%7},{%8,%9},{%0,%1,%2,%3};"
        : "+f"(c[0]), "+f"(c[1]), "+f"(c[2]), "+f"(c[3])
        : "r"(a[0]), "r"(a[1]), "r"(a[2]), "r"(a[3]), "r"(b0), "r"(b1));
}
// fp16-accumulate variant for low-order correction terms
__device__ __forceinline__ void mma_h(u32* c, const u32* a, u32 b0, u32 b1){
    asm volatile("mma.sync.aligned.m16n8k16.row.col.f16.f16.f16.f16 "
        "{%0,%1},{%2,%3,%4,%5},{%6,%7},{%0,%1};"
        : "+r"(c[0]), "+r"(c[1])
        : "r"(a[0]), "r"(a[1]), "r"(a[2]), "r"(a[3]), "r"(b0), "r"(b1));
}
#define CPA16(dst, src) \
    asm volatile("cp.async.cg.shared.global [%0], [%1], 16;" :: "r"(dst), "l"(src))
#define CPA_COMMIT()  asm volatile("cp.async.commit_group;" ::: "memory")
#define CPA_WAIT0()   asm volatile("cp.async.wait_group 0;" ::: "memory")
#define CPA_WAIT_G1() asm volatile("cp.async.wait_group 1;" ::: "memory")
#define CPA_WAIT() do { CPA_COMMIT(); CPA_WAIT0(); } while(0)

__device__ __forceinline__ void sp2(float a, float b, u32& H, u32& L){
    __half2 h = __floats2half2_rn(a, b);
    float2 hf = __half22float2(h);
    __half2 l = __floats2half2_rn(a - hf.x, b - hf.y);
    H = *(u32*)&h; L = *(u32*)&l;
}
__device__ __forceinline__ float2 dec(u32 v){
    __half2 h = *(__half2*)&v; return __half22float2(h);
}
__device__ __forceinline__ float hswish(float x){
    return x * __saturatef((x + 3.0f) * (1.0f / 6.0f));
}

// fragment loads: A = 8 regs (hi 4 + lo 4), B = 16 regs (hi 8 + lo 8)
__device__ __forceinline__ void ldA8(u32* A, u32 aH, u32 aL, int kc){
    ldsm4(aH + kc*32, A[0], A[1], A[2], A[3]);
    ldsm4(aL + kc*32, A[4], A[5], A[6], A[7]);
}
__device__ __forceinline__ void ldB16(u32* B, u32 bH, u32 bL, int kc, int jbp){
    const u32 off = kc*32 + jbp*32*STR*2;
    ldsm4(bH + off,            B[0],  B[1],  B[2],  B[3]);
    ldsm4(bH + off + 16*STR*2, B[4],  B[5],  B[6],  B[7]);
    ldsm4(bL + off,            B[8],  B[9],  B[10], B[11]);
    ldsm4(bL + off + 16*STR*2, B[12], B[13], B[14], B[15]);
}
// 12 MMAs of one chunk: 4 fp32-acc (hi*hi) + 8 fp16-acc (lo*hi, hi*lo)
__device__ __forceinline__ void mma12(float accF[8][4], u32 accH[8][2], int base,
                                      const u32* A, const u32* B){
    #pragma unroll
    for (int g = 0; g < 4; g++)
        mma_(accF[base+g], A, B[2*g], B[2*g+1]);
    #pragma unroll
    for (int g = 0; g < 4; g++)
        mma_h(accH[base+g], A+4, B[2*g], B[2*g+1]);
    #pragma unroll
    for (int g = 0; g < 4; g++)
        mma_h(accH[base+g], A, B[8+2*g], B[8+2*g+1]);
}
// register-double-buffered block (used by g1x1; 256 thr -> 128-reg budget)
__device__ __forceinline__ void gemm_block(float accF[8][4], u32 accH[8][2],
                                           u32 aH, u32 aL, u32 bH, u32 bL,
                                           u32 Ab[2][8], u32 Bb[2][16]){
    ldA8(Ab[0], aH, aL, 0);
    ldB16(Bb[0], bH, bL, 0, 0);
    #pragma unroll
    for (int ch = 0; ch < 8; ch++) {
        const int kc = ch >> 1, jbp = ch & 1;
        if (ch < 7) {
            const int nkc = (ch + 1) >> 1, njb = (ch + 1) & 1;
            if (njb == 0) ldA8(Ab[nkc & 1], aH, aL, nkc);
            ldB16(Bb[(ch + 1) & 1], bH, bL, nkc, njb);
        }
        mma12(accF, accH, 4*jbp, Ab[kc & 1], Bb[ch & 1]);
    }
}
// lean block for c3x3 (320 thr -> 102-reg budget): inline fragment loads
__device__ __forceinline__ void gemm_block_lean(float accF[8][4], u32 accH[8][2],
                                                u32 aH, u32 aL, u32 bH, u32 bL){
    #pragma unroll
    for (int kc = 0; kc < 4; kc++) {
        u32 A[8];
        ldA8(A, aH, aL, kc);
        #pragma unroll
        for (int jbp = 0; jbp < 2; jbp++) {
            u32 B[16];
            ldB16(B, bH, bL, kc, jbp);
            mma12(accF, accH, 4*jbp, A, B);
        }
    }
}

// ─── global scratch ────────────────────────────────────────────────────────
#define PXT 409600
#define TPAD (16*162*162)
#define WTOT 118784

__device__ __align__(16) u16 g_yh[PXT*64], g_yl[PXT*64];
__device__ __align__(16) u16 g_ah[PXT*64], g_al[PXT*64];
__device__ __align__(16) u16 g_bh[PXT*64], g_bl[PXT*64];
__device__ __align__(16) u16 g_th[TPAD*64], g_tl[TPAD*64];
__device__ __align__(16) u16 g_wh[WTOT], g_wl[WTOT];
__device__ float g_sb[1280];

#define WO_CV1   0
#define WO_M0A   8192
#define WO_M0B   12288
#define WO_M1A   49152
#define WO_M1B   53248
#define WO_CV3   90112
#define WO_CV2P  94208
#define WO_CV4   102400

#define SB_CV1   0
#define SB_M0A   128
#define SB_M0B   256
#define SB_M1A   384
#define SB_M1B   512
#define SB_CATA  640
#define SB_CATB  768
#define SB_CV4   896

// ─── single fused prep kernel ──────────────────────────────────────────────
__global__ void prep_all(
    const float* cv1w, const float* m0a, const float* m0b,
    const float* m1a,  const float* m1b, const float* cv3,
    const float* cv2p, const float* cv4,
    const float* c1bn, const float* a0bn, const float* b0bn,
    const float* a1bn, const float* b1bn, const float* catbn, const float* c4bn,
    u16* wh, u16* wl, float* sb, u16* th, u16* tl)
{
    const int bid = blockIdx.x, tid = threadIdx.x;
    if (bid < 29) {
        const float* src; u16 *dh, *dl; int CIN = 64, COUT = 64, b0;
        if      (bid < 2)  { src = cv1w; dh = wh+WO_CV1;  dl = wl+WO_CV1;  CIN = 128; b0 = 0; }
        else if (bid < 3)  { src = m0a;  dh = wh+WO_M0A;  dl = wl+WO_M0A;  b0 = 2; }
        else if (bid < 12) { src = m0b;  dh = wh+WO_M0B;  dl = wl+WO_M0B;  b0 = 3; }
        else if (bid < 13) { src = m1a;  dh = wh+WO_M1A;  dl = wl+WO_M1A;  b0 = 12; }
        else if (bid < 22) { src = m1b;  dh = wh+WO_M1B;  dl = wl+WO_M1B;  b0 = 13; }
        else if (bid < 23) { src = cv3;  dh = wh+WO_CV3;  dl = wl+WO_CV3;  b0 = 22; }
        else if (bid < 25) { src = cv2p; dh = wh+WO_CV2P; dl = wl+WO_CV2P; CIN = 128; b0 = 23; }
        else               { src = cv4;  dh = wh+WO_CV4;  dl = wl+WO_CV4;  CIN = 128; COUT = 128; b0 = 25; }
        const int base = (bid - b0) * 4096;
        const int per = CIN * COUT;
        #pragma unroll 4
        for (int j = 0; j < 16; j++) {
            int e = base + tid + j * 256;
            int tap = e / per, r = e - tap * per;
            int ci = r / COUT, co = r - ci * COUT;
            float w = src[e];
            __half h = __float2half_rn(w);
            __half l = __float2half_rn(w - __half2float(h));
            int d = tap * per + co * CIN + ci;
            dh[d] = *(u16*)&h; dl[d] = *(u16*)&l;
        }
    } else if (bid == 29) {
        auto seg = [&](int off, const float* s, int C, int stride, int choff){
            for (int c = tid; c < C; c += 256) {
                float g = s[choff + c], b = s[stride + choff + c];
                float m = s[2*stride + choff + c], v = s[3*stride + choff + c];
                float sc = g * rsqrtf(v + 1e-3f);
                sb[off + c] = sc; sb[off + C + c] = b - m * sc;
            }
        };
        seg(SB_CV1,  c1bn, 64, 64, 0);
        seg(SB_M0A,  a0bn, 64, 64, 0);
        seg(SB_M0B,  b0bn, 64, 64, 0);
        seg(SB_M1A,  a1bn, 64, 64, 0);
        seg(SB_M1B,  b1bn, 64, 64, 0);
        seg(SB_CATA, catbn, 64, 128, 0);
        seg(SB_CATB, catbn, 64, 128, 64);
        seg(SB_CV4,       c4bn, 64, 128, 0);
        seg(SB_CV4 + 128, c4bn, 64, 128, 64);
    } else {
        int i = (bid - 30) * 256 + tid;
        if (i >= 16 * 644) return;
        int img = i / 644, r = i - img * 644;
        int y, x;
        if      (r < 162) { y = 0;   x = r; }
        else if (r < 324) { y = 161; x = r - 162; }
        else if (r < 484) { x = 0;   y = r - 324 + 1; }
        else              { x = 161; y = r - 484 + 1; }
        long long q = (((long long)img * 162 + y) * 162 + x) * 64;
        uint4 z = make_uint4(0,0,0,0);
        #pragma unroll
        for (int c = 0; c < 8; c++) { *(uint4*)(th + q + c*8) = z; *(uint4*)(tl + q + c*8) = z; }
    }
}

// ─── 1x1 conv GEMM (HMMA): persistent CTAs, pipelined A, W preloaded ───────
template<int CIN, int SRC, int OUTM, int ACT>
__global__ void __launch_bounds__(256, 2) g1x1(
    const float* __restrict__ xf,
    const u16* __restrict__ pah, const u16* __restrict__ pal,
    const u16* __restrict__ pbh, const u16* __restrict__ pbl,
    const u16* __restrict__ wh,  const u16* __restrict__ wl,
    const float* __restrict__ sb,
    u16* __restrict__ oh, u16* __restrict__ ol, float* __restrict__ of,
    int ntiles)
{
    constexpr int KB  = CIN / 64;
    constexpr int APL = 128 * STR * 2;   // 18432 per plane
    constexpr int WPL = 64 * STR * 2;    // 9216  per plane

    extern __shared__ char sm[];
    float* sbs  = (float*)sm;
    char* Wbase = sm + 512;                  // [kb][hi|lo]
    char* Abase = Wbase + KB * 2 * WPL;      // [buf][hi|lo]

    const int tid = threadIdx.x;
    const int cy  = blockIdx.y;
    const u16* whp = wh + cy * 64 * CIN;
    const u16* wlp = wl + cy * 64 * CIN;

    for (int c = tid; c < 128; c += 256) sbs[c] = sb[cy * 128 + c];

    const u32 WA = smem_u32(Wbase), AA = smem_u32(Abase);

    #pragma unroll
    for (int kb = 0; kb < KB; kb++)
        for (int i = tid; i < 512; i += 256) {
            int n = i >> 3, c8 = i & 7;
            u32 off = kb * 2 * WPL + (n * STR + c8 * 8) * 2;
            CPA16(WA + off,       whp + n * CIN + kb * 64 + c8 * 8);
            CPA16(WA + off + WPL, wlp + n * CIN + kb * 64 + c8 * 8);
        }

    auto stageA = [&](int t, int kb, int buf){
        long long p0 = (long long)t * 128;
        const u32 AH = AA + buf * 2 * APL;
        char* AB = Abase + buf * 2 * APL;
        for (int i = tid; i < 1024; i += 256) {
            int row = i >> 3, c8 = i & 7;
            u32 off = (row * STR + c8 * 8) * 2;
            if (SRC == 0) {
                const float* g = xf + (p0 + row) * CIN + kb * 64 + c8 * 8;
                float4 f1 = *(const float4*)g, f2 = *(const float4*)(g + 4);
                uint4 H, L;
                sp2(f1.x, f1.y, H.x, L.x); sp2(f1.z, f1.w, H.y, L.y);
                sp2(f2.x, f2.y, H.z, L.z); sp2(f2.z, f2.w, H.w, L.w);
                *(uint4*)(AB + off) = H; *(uint4*)(AB + APL + off) = L;
            } else if (SRC == 1) {
                CPA16(AH + off,       pah + (p0 + row) * CIN + kb * 64 + c8 * 8);
                CPA16(AH + APL + off, pal + (p0 + row) * CIN + kb * 64 + c8 * 8);
            } else {
                const u16* shp = kb ? pbh : pah;
                const u16* slp = kb ? pbl : pal;
                long long so = (p0 + row) * 64 + c8 * 8;
                CPA16(AH + off,       shp + so);
                CPA16(AH + APL + off, slp + so);
            }
        }
    };

    const int warp = tid >> 5, lane = tid & 31;
    const int arow  = 16 * warp + (lane & 7) + ((lane & 8) ? 8 : 0);
    const int akoff = (lane & 16) ? 8 : 0;
    const u32 aOff = (arow * STR + akoff) * 2;
    const int brow  = (lane & 7) + ((lane & 16) ? 8 : 0);
    const int bkoff = (lane & 8) ? 8 : 0;
    const u32 bOff = (brow * STR + bkoff) * 2;

    const int gr = lane >> 2, c2l = (lane & 3) * 2;
    const int coff = cy * 64;

    const int t0 = blockIdx.x;
    if (t0 < ntiles) stageA(t0, 0, 0);
    CPA_COMMIT();

    int buf = 0;
    float accF[8][4];
    u32 accH[8][2];
    u32 Ab[2][8], Bb[2][16];

    for (int t = t0; t < ntiles; t += gridDim.x) {
        #pragma unroll
        for (int n = 0; n < 8; n++) {
            #pragma unroll
            for (int j = 0; j < 4; j++) accF[n][j] = 0.f;
            accH[n][0] = 0u; accH[n][1] = 0u;
        }

        #pragma unroll
        for (int kb = 0; kb < KB; kb++) {
            int nt = t, nkb = kb + 1;
            if (nkb == KB) { nkb = 0; nt = t + gridDim.x; }
            const bool hn = (nt < ntiles);
            if (hn) stageA(nt, nkb, buf ^ 1);
            CPA_COMMIT();
            if (hn) { CPA_WAIT_G1(); } else { CPA_WAIT0(); }
            __syncthreads();

            const u32 aH = AA + buf * 2 * APL + aOff;
            const u32 aL = aH + APL;
            const u32 bH = WA + kb * 2 * WPL + bOff;
            const u32 bL = bH + WPL;

            gemm_block(accF, accH, aH, aL, bH, bL, Ab, Bb);

            if (kb == KB - 1) {
                #pragma unroll
                for (int rs = 0; rs < 2; rs++) {
                    int row = 16*warp + 8*rs + gr;
                    long long p = (long long)t * 128 + row;
                    long long q = 0;
                    if (OUTM == 0) q = p * 64;
                    else if (OUTM == 1) {
                        int pi = (int)p;
                        int img = pi / 25600, r = pi - img * 25600;
                        int y = r / 160, x = r - y * 160;
                        q = (((long long)img * 162 + y + 1) * 162 + (x + 1)) * 64;
                    }
                    #pragma unroll
                    for (int nb = 0; nb < 8; nb++) {
                        float2 hc = dec(accH[nb][rs]);
                        float v0 = sbs[8*nb + c2l]     * (accF[nb][2*rs]     + hc.x) + sbs[64 + 8*nb + c2l];
                        float v1 = sbs[8*nb + c2l + 1] * (accF[nb][2*rs + 1] + hc.y) + sbs[64 + 8*nb + c2l + 1];
                        if (ACT == 0) { v0 = hswish(v0); v1 = hswish(v1); }
                        else { v0 = v0 >= 0.f ? v0 : 0.1f*v0; v1 = v1 >= 0.f ? v1 : 0.1f*v1; }
                        if (OUTM == 2) {
                            *(float2*)(of + p * 128 + coff + 8*nb + c2l) = make_float2(v0, v1);
                        } else {
                            u32 H, L; sp2(v0, v1, H, L);
                            *(u32*)(oh + q + 8*nb + c2l) = H;
                            *(u32*)(ol + q + 8*nb + c2l) = L;
                        }
                    }
                }
            }
            __syncthreads();
            buf ^= 1;
        }
    }
}

// ─── 3x3 conv + BN + hswish + residual: 320 thr (10 warps), tile 10x16 ─────
__global__ void __launch_bounds__(320, 2) c3x3(
    const u16* __restrict__ th, const u16* __restrict__ tl,
    const u16* __restrict__ wh, const u16* __restrict__ wl,
    const float* __restrict__ sb,
    u16* __restrict__ yh, u16* __restrict__ yl)
{
    constexpr int APL = 216 * STR * 2;   // 31104 per plane (12x18 halo rows)
    constexpr int WPL = 64 * STR * 2;    // 9216  per plane

    extern __shared__ char sm[];
    float* sbs = (float*)sm;
    char* Ah = sm + 512;
    char* Al = Ah + APL;
    char* Wb = Al + APL;                 // [buf][hi|lo]

    const int tid = threadIdx.x;
    const int blk = blockIdx.x;              // 16 imgs * 160 tiles (16x10)
    const int img = blk / 160, t = blk - img * 160;
    const int ty = t / 10, tx = t - ty * 10;
    const int y0 = ty * 10, x0 = tx * 16;

    for (int c = tid; c < 128; c += 320) sbs[c] = sb[c];

    const u32 AhA = smem_u32(Ah), AlA = smem_u32(Al), WbA = smem_u32(Wb);

    // halo 12x18 rows x 64ch, both planes (padded input: no predicates)
    for (int i = tid; i < 1728; i += 320) {
        int hr = i >> 3, c8 = i & 7;
        int hy = hr / 18, hx = hr - hy * 18;
        long long s = (((long long)img * 162 + y0 + hy) * 162 + (x0 + hx)) * 64 + c8 * 8;
        u32 off = (hr * STR + c8 * 8) * 2;
        CPA16(AhA + off, th + s);
        CPA16(AlA + off, tl + s);
    }
    for (int i = tid; i < 512; i += 320) {
        int n = i >> 3, c8 = i & 7;
        u32 off = (n * STR + c8 * 8) * 2;
        CPA16(WbA + off,       wh + n*64 + c8*8);
        CPA16(WbA + WPL + off, wl + n*64 + c8*8);
    }
    CPA_WAIT();
    __syncthreads();

    const int warp = tid >> 5, lane = tid & 31;   // warp 0..9 = row in tile
    const int acol  = lane & 15;
    const int akoff = (lane & 16) ? 8 : 0;
    const int brow  = (lane & 7) + ((lane & 16) ? 8 : 0);
    const int bkoff = (lane & 8) ? 8 : 0;
    const u32 bOff = (brow * STR + bkoff) * 2;

    float accF[8][4];
    u32 accH[8][2];
    #pragma unroll
    for (int n = 0; n < 8; n++) {
        #pragma unroll
        for (int j = 0; j < 4; j++) accF[n][j] = 0.f;
        accH[n][0] = 0u; accH[n][1] = 0u;
    }

    for (int tap = 0; tap < 9; tap++) {
        const int buf = tap & 1;
        if (tap < 8) {
            const u16* sh = wh + (tap+1)*4096;
            const u16* sl = wl + (tap+1)*4096;
            const u32 WA = WbA + (buf^1)*2*WPL;
            for (int i = tid; i < 512; i += 320) {
                int n = i >> 3, c8 = i & 7;
                u32 off = (n * STR + c8 * 8) * 2;
                CPA16(WA + off,       sh + n*64 + c8*8);
                CPA16(WA + WPL + off, sl + n*64 + c8*8);
            }
            CPA_COMMIT();
        }
        const int kh = tap / 3, kw = tap - kh * 3;
        const int hr = (warp + kh) * 18 + acol + kw;
        const u32 aH = AhA + (hr * STR + akoff) * 2;
        const u32 aL = AlA + (hr * STR + akoff) * 2;
        const u32 bH = WbA + buf*2*WPL + bOff;
        const u32 bL = bH + WPL;

        gemm_block_lean(accF, accH, aH, aL, bH, bL);

        if (tap < 8) {
            CPA_WAIT0();
            __syncthreads();
        }
    }

    const int gr = lane >> 2, c2l = (lane & 3) * 2;
    #pragma unroll
    for (int rs = 0; rs < 2; rs++) {
        int xx = 8*rs + gr;
        long long q = ((long long)img * 25600 + (y0 + warp) * 160 + (x0 + xx)) * 64;
        #pragma unroll
        for (int nb = 0; nb < 8; nb++) {
            float2 yv0 = dec(*(const u32*)(yh + q + 8*nb + c2l));
            float2 yv1 = dec(*(const u32*)(yl + q + 8*nb + c2l));
            float2 hc  = dec(accH[nb][rs]);
            float v0 = sbs[8*nb + c2l]     * (accF[nb][2*rs]     + hc.x) + sbs[64 + 8*nb + c2l];
            float v1 = sbs[8*nb + c2l + 1] * (accF[nb][2*rs + 1] + hc.y) + sbs[64 + 8*nb + c2l + 1];
            v0 = hswish(v0) + yv0.x + yv1.x;
            v1 = hswish(v1) + yv0.y + yv1.y;
            u32 H, L; sp2(v0, v1, H, L);
            *(u32*)(yh + q + 8*nb + c2l) = H;
            *(u32*)(yl + q + 8*nb + c2l) = L;
        }
    }
}

// ─── host ──────────────────────────────────────────────────────────────────
extern "C" void kernel_launch(void* const* d_in, const int* in_sizes, int n_in,
                              void* d_out, int out_size)
{
    (void)in_sizes; (void)n_in; (void)out_size;
    const float* x         = (const float*)d_in[0];
    const float* cv1_w     = (const float*)d_in[1];
    const float* cv1_bn    = (const float*)d_in[2];
    const float* m0_cv1_w  = (const float*)d_in[3];
    const float* m0_cv1_bn = (const float*)d_in[4];
    const float* m0_cv2_w  = (const float*)d_in[5];
    const float* m0_cv2_bn = (const float*)d_in[6];
    const float* m1_cv1_w  = (const float*)d_in[7];
    const float* m1_cv1_bn = (const float*)d_in[8];
    const float* m1_cv2_w  = (const float*)d_in[9];
    const float* m1_cv2_bn = (const float*)d_in[10];
    const float* cv3_w     = (const float*)d_in[11];
    const float* cv2p_w    = (const float*)d_in[12];
    const float* bn_cat    = (const float*)d_in[13];
    const float* cv4_w     = (const float*)d_in[14];
    const float* cv4_bn    = (const float*)d_in[15];
    float* out = (float*)d_out;

    u16 *yh, *yl, *ah, *al, *bh, *bl, *th, *tl, *wh, *wl;
    float* sb;
    cudaGetSymbolAddress((void**)&yh, g_yh); cudaGetSymbolAddress((void**)&yl, g_yl);
    cudaGetSymbolAddress((void**)&ah, g_ah); cudaGetSymbolAddress((void**)&al, g_al);
    cudaGetSymbolAddress((void**)&bh, g_bh); cudaGetSymbolAddress((void**)&bl, g_bl);
    cudaGetSymbolAddress((void**)&th, g_th); cudaGetSymbolAddress((void**)&tl, g_tl);
    cudaGetSymbolAddress((void**)&wh, g_wh); cudaGetSymbolAddress((void**)&wl, g_wl);
    cudaGetSymbolAddress((void**)&sb, g_sb);

    constexpr int S1_64  = 512 + 1*2*9216 + 2*2*18432;     // 92672
    constexpr int S1_128 = 512 + 2*2*9216 + 2*2*18432;     // 111104
    constexpr int S3     = 512 + 2*31104 + 4*9216;         // 99584
    constexpr int NT = 3200;
    constexpr int GP = 304;
    constexpr int GC3 = 2560;    // 16 imgs * 160 tiles (10x16 px each)

    cudaFuncSetAttribute(g1x1<128,0,0,0>, cudaFuncAttributeMaxDynamicSharedMemorySize, S1_128);
    cudaFuncSetAttribute(g1x1< 64,1,1,0>, cudaFuncAttributeMaxDynamicSharedMemorySize, S1_64);
    cudaFuncSetAttribute(g1x1< 64,1,0,1>, cudaFuncAttributeMaxDynamicSharedMemorySize, S1_64);
    cudaFuncSetAttribute(g1x1<128,0,0,1>, cudaFuncAttributeMaxDynamicSharedMemorySize, S1_128);
    cudaFuncSetAttribute(g1x1<128,2,2,0>, cudaFuncAttributeMaxDynamicSharedMemorySize, S1_128);
    cudaFuncSetAttribute(c3x3,            cudaFuncAttributeMaxDynamicSharedMemorySize, S3);

    prep_all<<<71, 256>>>(cv1_w, m0_cv1_w, m0_cv2_w, m1_cv1_w, m1_cv2_w,
                          cv3_w, cv2p_w, cv4_w,
                          cv1_bn, m0_cv1_bn, m0_cv2_bn, m1_cv1_bn, m1_cv2_bn,
                          bn_cat, cv4_bn, wh, wl, sb, th, tl);

    g1x1<128,0,0,0><<<GP,256,S1_128>>>(x, 0,0,0,0, wh+WO_CV1, wl+WO_CV1, sb+SB_CV1, yh, yl, 0, NT);
    g1x1<64,1,1,0><<<GP,256,S1_64>>>(0, yh,yl,0,0, wh+WO_M0A, wl+WO_M0A, sb+SB_M0A, th, tl, 0, NT);
    c3x3<<<GC3,320,S3>>>(th, tl, wh+WO_M0B, wl+WO_M0B, sb+SB_M0B, yh, yl);
    g1x1<64,1,1,0><<<GP,256,S1_64>>>(0, yh,yl,0,0, wh+WO_M1A, wl+WO_M1A, sb+SB_M1A, th, tl, 0, NT);
    c3x3<<<GC3,320,S3>>>(th, tl, wh+WO_M1B, wl+WO_M1B, sb+SB_M1B, yh, yl);
    g1x1<64,1,0,1><<<GP,256,S1_64>>>(0, yh,yl,0,0, wh+WO_CV3, wl+WO_CV3, sb+SB_CATA, ah, al, 0, NT);
    g1x1<128,0,0,1><<<GP,256,S1_128>>>(x, 0,0,0,0, wh+WO_CV2P, wl+WO_CV2P, sb+SB_CATB, bh, bl, 0, NT);
    g1x1<128,2,2,0><<<dim3(GP,2),256,S1_128>>>(0, ah,al, bh,bl, wh+WO_CV4, wl+WO_CV4, sb+SB_CV4, 0, 0, out, NT);
}

// round 12
// speedup vs baseline: 1.1550x; 1.1550x over previous
#include <cuda_runtime.h>
#include <cuda_fp16.h>
#include <cstdint>

typedef unsigned short u16;
typedef unsigned int   u32;

constexpr int STR = 72;   // smem row stride in halves (conflict-free for ldsm)

// ─── helpers ───────────────────────────────────────────────────────────────
__device__ __forceinline__ u32 smem_u32(const void* p){
    u32 a;
    asm("{ .reg .u64 t; cvta.to.shared.u64 t, %1; cvt.u32.u64 %0, t; }"
        : "=r"(a) : "l"(p));
    return a;
}
__device__ __forceinline__ void ldsm4(u32 addr, u32& r0, u32& r1, u32& r2, u32& r3){
    asm volatile("ldmatrix.sync.aligned.m8n8.x4.shared.b16 {%0,%1,%2,%3}, [%4];"
        : "=r"(r0), "=r"(r1), "=r"(r2), "=r"(r3) : "r"(addr));
}
__device__ __forceinline__ void mma_(float* c, const u32* a, u32 b0, u32 b1){
    asm volatile("mma.sync.aligned.m16n8k16.row.col.f32.f16.f16.f32 "
        "{%0,%1,%2,%3},{%4,%5,%6,%7},{%8,%9},{%0,%1,%2,%3};"
        : "+f"(c[0]), "+f"(c[1]), "+f"(c[2]), "+f"(c[3])
        : "r"(a[0]), "r"(a[1]), "r"(a[2]), "r"(a[3]), "r"(b0), "r"(b1));
}
// fp16-accumulate variant for low-order correction terms
__device__ __forceinline__ void mma_h(u32* c, const u32* a, u32 b0, u32 b1){
    asm volatile("mma.sync.aligned.m16n8k16.row.col.f16.f16.f16.f16 "
        "{%0,%1},{%2,%3,%4,%5},{%6,%7},{%0,%1};"
        : "+r"(c[0]), "+r"(c[1])
        : "r"(a[0]), "r"(a[1]), "r"(a[2]), "r"(a[3]), "r"(b0), "r"(b1));
}
#define CPA16(dst, src) \
    asm volatile("cp.async.cg.shared.global [%0], [%1], 16;" :: "r"(dst), "l"(src))
#define CPA_COMMIT()  asm volatile("cp.async.commit_group;" ::: "memory")
#define CPA_WAIT0()   asm volatile("cp.async.wait_group 0;" ::: "memory")
#define CPA_WAIT_G1() asm volatile("cp.async.wait_group 1;" ::: "memory")
#define CPA_WAIT() do { CPA_COMMIT(); CPA_WAIT0(); } while(0)

__device__ __forceinline__ void sp2(float a, float b, u32& H, u32& L){
    __half2 h = __floats2half2_rn(a, b);
    float2 hf = __half22float2(h);
    __half2 l = __floats2half2_rn(a - hf.x, b - hf.y);
    H = *(u32*)&h; L = *(u32*)&l;
}
__device__ __forceinline__ float2 dec(u32 v){
    __half2 h = *(__half2*)&v; return __half22float2(h);
}
__device__ __forceinline__ float hswish(float x){
    return x * __saturatef((x + 3.0f) * (1.0f / 6.0f));
}

// fragment loads: A = 8 regs (hi 4 + lo 4), B = 16 regs (hi 8 + lo 8) over N=32
__device__ __forceinline__ void ldA8(u32* A, u32 aH, u32 aL, int kc){
    ldsm4(aH + kc*32, A[0], A[1], A[2], A[3]);
    ldsm4(aL + kc*32, A[4], A[5], A[6], A[7]);
}
// bH/bL already offset to this warp's N-half (32 rows)
__device__ __forceinline__ void ldB16n(u32* B, u32 bH, u32 bL, int kc){
    const u32 off = kc*32;
    ldsm4(bH + off,            B[0],  B[1],  B[2],  B[3]);
    ldsm4(bH + off + 16*STR*2, B[4],  B[5],  B[6],  B[7]);
    ldsm4(bL + off,            B[8],  B[9],  B[10], B[11]);
    ldsm4(bL + off + 16*STR*2, B[12], B[13], B[14], B[15]);
}
// 12 MMAs per kc over N=32: 4 fp32-acc (hi*hi) + 8 fp16-acc (lo*hi, hi*lo)
__device__ __forceinline__ void mma12n(float accF[4][4], u32 accH[4][2],
                                       const u32* A, const u32* B){
    #pragma unroll
    for (int g = 0; g < 4; g++)
        mma_(accF[g], A, B[2*g], B[2*g+1]);
    #pragma unroll
    for (int g = 0; g < 4; g++)
        mma_h(accH[g], A+4, B[2*g], B[2*g+1]);
    #pragma unroll
    for (int g = 0; g < 4; g++)
        mma_h(accH[g], A, B[8+2*g], B[8+2*g+1]);
}
// register-double-buffered 4-kc block over this warp's N=32 half
__device__ __forceinline__ void gemm_block_n(float accF[4][4], u32 accH[4][2],
                                             u32 aH, u32 aL, u32 bH, u32 bL){
    u32 Ab[2][8], Bb[2][16];
    ldA8(Ab[0], aH, aL, 0);
    ldB16n(Bb[0], bH, bL, 0);
    #pragma unroll
    for (int kc = 0; kc < 4; kc++) {
        if (kc < 3) {
            ldA8(Ab[(kc+1) & 1], aH, aL, kc+1);
            ldB16n(Bb[(kc+1) & 1], bH, bL, kc+1);
        }
        mma12n(accF, accH, Ab[kc & 1], Bb[kc & 1]);
    }
}

// ─── global scratch ────────────────────────────────────────────────────────
#define PXT 409600
#define TPAD (16*162*162)
#define WTOT 118784

__device__ __align__(16) u16 g_yh[PXT*64], g_yl[PXT*64];
__device__ __align__(16) u16 g_ah[PXT*64], g_al[PXT*64];
__device__ __align__(16) u16 g_bh[PXT*64], g_bl[PXT*64];
__device__ __align__(16) u16 g_th[TPAD*64], g_tl[TPAD*64];
__device__ __align__(16) u16 g_wh[WTOT], g_wl[WTOT];
__device__ float g_sb[1280];

#define WO_CV1   0
#define WO_M0A   8192
#define WO_M0B   12288
#define WO_M1A   49152
#define WO_M1B   53248
#define WO_CV3   90112
#define WO_CV2P  94208
#define WO_CV4   102400

#define SB_CV1   0
#define SB_M0A   128
#define SB_M0B   256
#define SB_M1A   384
#define SB_M1B   512
#define SB_CATA  640
#define SB_CATB  768
#define SB_CV4   896

// ─── single fused prep kernel ──────────────────────────────────────────────
__global__ void prep_all(
    const float* cv1w, const float* m0a, const float* m0b,
    const float* m1a,  const float* m1b, const float* cv3,
    const float* cv2p, const float* cv4,
    const float* c1bn, const float* a0bn, const float* b0bn,
    const float* a1bn, const float* b1bn, const float* catbn, const float* c4bn,
    u16* wh, u16* wl, float* sb, u16* th, u16* tl)
{
    const int bid = blockIdx.x, tid = threadIdx.x;
    if (bid < 29) {
        const float* src; u16 *dh, *dl; int CIN = 64, COUT = 64, b0;
        if      (bid < 2)  { src = cv1w; dh = wh+WO_CV1;  dl = wl+WO_CV1;  CIN = 128; b0 = 0; }
        else if (bid < 3)  { src = m0a;  dh = wh+WO_M0A;  dl = wl+WO_M0A;  b0 = 2; }
        else if (bid < 12) { src = m0b;  dh = wh+WO_M0B;  dl = wl+WO_M0B;  b0 = 3; }
        else if (bid < 13) { src = m1a;  dh = wh+WO_M1A;  dl = wl+WO_M1A;  b0 = 12; }
        else if (bid < 22) { src = m1b;  dh = wh+WO_M1B;  dl = wl+WO_M1B;  b0 = 13; }
        else if (bid < 23) { src = cv3;  dh = wh+WO_CV3;  dl = wl+WO_CV3;  b0 = 22; }
        else if (bid < 25) { src = cv2p; dh = wh+WO_CV2P; dl = wl+WO_CV2P; CIN = 128; b0 = 23; }
        else               { src = cv4;  dh = wh+WO_CV4;  dl = wl+WO_CV4;  CIN = 128; COUT = 128; b0 = 25; }
        const int base = (bid - b0) * 4096;
        const int per = CIN * COUT;
        #pragma unroll 4
        for (int j = 0; j < 16; j++) {
            int e = base + tid + j * 256;
            int tap = e / per, r = e - tap * per;
            int ci = r / COUT, co = r - ci * COUT;
            float w = src[e];
            __half h = __float2half_rn(w);
            __half l = __float2half_rn(w - __half2float(h));
            int d = tap * per + co * CIN + ci;
            dh[d] = *(u16*)&h; dl[d] = *(u16*)&l;
        }
    } else if (bid == 29) {
        auto seg = [&](int off, const float* s, int C, int stride, int choff){
            for (int c = tid; c < C; c += 256) {
                float g = s[choff + c], b = s[stride + choff + c];
                float m = s[2*stride + choff + c], v = s[3*stride + choff + c];
                float sc = g * rsqrtf(v + 1e-3f);
                sb[off + c] = sc; sb[off + C + c] = b - m * sc;
            }
        };
        seg(SB_CV1,  c1bn, 64, 64, 0);
        seg(SB_M0A,  a0bn, 64, 64, 0);
        seg(SB_M0B,  b0bn, 64, 64, 0);
        seg(SB_M1A,  a1bn, 64, 64, 0);
        seg(SB_M1B,  b1bn, 64, 64, 0);
        seg(SB_CATA, catbn, 64, 128, 0);
        seg(SB_CATB, catbn, 64, 128, 64);
        seg(SB_CV4,       c4bn, 64, 128, 0);
        seg(SB_CV4 + 128, c4bn, 64, 128, 64);
    } else {
        int i = (bid - 30) * 256 + tid;
        if (i >= 16 * 644) return;
        int img = i / 644, r = i - img * 644;
        int y, x;
        if      (r < 162) { y = 0;   x = r; }
        else if (r < 324) { y = 161; x = r - 162; }
        else if (r < 484) { x = 0;   y = r - 324 + 1; }
        else              { x = 161; y = r - 484 + 1; }
        long long q = (((long long)img * 162 + y) * 162 + x) * 64;
        uint4 z = make_uint4(0,0,0,0);
        #pragma unroll
        for (int c = 0; c < 8; c++) { *(uint4*)(th + q + c*8) = z; *(uint4*)(tl + q + c*8) = z; }
    }
}

// ─── 1x1 conv GEMM (HMMA): persistent, 512 thr, warp = 16 rows x N32 ───────
template<int CIN, int SRC, int OUTM, int ACT>
__global__ void __launch_bounds__(512, 2) g1x1(
    const float* __restrict__ xf,
    const u16* __restrict__ pah, const u16* __restrict__ pal,
    const u16* __restrict__ pbh, const u16* __restrict__ pbl,
    const u16* __restrict__ wh,  const u16* __restrict__ wl,
    const float* __restrict__ sb,
    u16* __restrict__ oh, u16* __restrict__ ol, float* __restrict__ of,
    int ntiles)
{
    constexpr int KB  = CIN / 64;
    constexpr int APL = 128 * STR * 2;   // 18432 per plane
    constexpr int WPL = 64 * STR * 2;    // 9216  per plane

    extern __shared__ char sm[];
    float* sbs  = (float*)sm;
    char* Wbase = sm + 512;                  // [kb][hi|lo]
    char* Abase = Wbase + KB * 2 * WPL;      // [buf][hi|lo]

    const int tid = threadIdx.x;
    const int cy  = blockIdx.y;
    const u16* whp = wh + cy * 64 * CIN;
    const u16* wlp = wl + cy * 64 * CIN;

    for (int c = tid; c < 128; c += 512) sbs[c] = sb[cy * 128 + c];

    const u32 WA = smem_u32(Wbase), AA = smem_u32(Abase);

    #pragma unroll
    for (int kb = 0; kb < KB; kb++)
        for (int i = tid; i < 512; i += 512) {
            int n = i >> 3, c8 = i & 7;
            u32 off = kb * 2 * WPL + (n * STR + c8 * 8) * 2;
            CPA16(WA + off,       whp + n * CIN + kb * 64 + c8 * 8);
            CPA16(WA + off + WPL, wlp + n * CIN + kb * 64 + c8 * 8);
        }

    auto stageA = [&](int t, int kb, int buf){
        long long p0 = (long long)t * 128;
        const u32 AH = AA + buf * 2 * APL;
        char* AB = Abase + buf * 2 * APL;
        for (int i = tid; i < 1024; i += 512) {
            int row = i >> 3, c8 = i & 7;
            u32 off = (row * STR + c8 * 8) * 2;
            if (SRC == 0) {
                const float* g = xf + (p0 + row) * CIN + kb * 64 + c8 * 8;
                float4 f1 = *(const float4*)g, f2 = *(const float4*)(g + 4);
                uint4 H, L;
                sp2(f1.x, f1.y, H.x, L.x); sp2(f1.z, f1.w, H.y, L.y);
                sp2(f2.x, f2.y, H.z, L.z); sp2(f2.z, f2.w, H.w, L.w);
                *(uint4*)(AB + off) = H; *(uint4*)(AB + APL + off) = L;
            } else if (SRC == 1) {
                CPA16(AH + off,       pah + (p0 + row) * CIN + kb * 64 + c8 * 8);
                CPA16(AH + APL + off, pal + (p0 + row) * CIN + kb * 64 + c8 * 8);
            } else {
                const u16* shp = kb ? pbh : pah;
                const u16* slp = kb ? pbl : pal;
                long long so = (p0 + row) * 64 + c8 * 8;
                CPA16(AH + off,       shp + so);
                CPA16(AH + APL + off, slp + so);
            }
        }
    };

    const int warp = tid >> 5, lane = tid & 31;
    const int mrow = warp >> 1;          // 0..7 : 16-row block
    const int nh   = warp & 1;           // N-half
    const int arow  = 16 * mrow + (lane & 7) + ((lane & 8) ? 8 : 0);
    const int akoff = (lane & 16) ? 8 : 0;
    const u32 aOff = (arow * STR + akoff) * 2;
    const int brow  = (lane & 7) + ((lane & 16) ? 8 : 0);
    const int bkoff = (lane & 8) ? 8 : 0;
    const u32 bOff = ((nh * 32 + brow) * STR + bkoff) * 2;

    const int gr = lane >> 2, c2l = (lane & 3) * 2;
    const int coff = cy * 64 + nh * 32;

    const int t0 = blockIdx.x;
    if (t0 < ntiles) stageA(t0, 0, 0);
    CPA_COMMIT();

    int buf = 0;
    float accF[4][4];
    u32 accH[4][2];

    for (int t = t0; t < ntiles; t += gridDim.x) {
        #pragma unroll
        for (int n = 0; n < 4; n++) {
            #pragma unroll
            for (int j = 0; j < 4; j++) accF[n][j] = 0.f;
            accH[n][0] = 0u; accH[n][1] = 0u;
        }

        #pragma unroll
        for (int kb = 0; kb < KB; kb++) {
            int nt = t, nkb = kb + 1;
            if (nkb == KB) { nkb = 0; nt = t + gridDim.x; }
            const bool hn = (nt < ntiles);
            if (hn) stageA(nt, nkb, buf ^ 1);
            CPA_COMMIT();
            if (hn) { CPA_WAIT_G1(); } else { CPA_WAIT0(); }
            __syncthreads();

            const u32 aH = AA + buf * 2 * APL + aOff;
            const u32 aL = aH + APL;
            const u32 bH = WA + kb * 2 * WPL + bOff;
            const u32 bL = bH + WPL;

            gemm_block_n(accF, accH, aH, aL, bH, bL);

            if (kb == KB - 1) {
                #pragma unroll
                for (int rs = 0; rs < 2; rs++) {
                    int row = 16*mrow + 8*rs + gr;
                    long long p = (long long)t * 128 + row;
                    long long q = 0;
                    if (OUTM == 0) q = p * 64;
                    else if (OUTM == 1) {
                        int pi = (int)p;
                        int img = pi / 25600, r = pi - img * 25600;
                        int y = r / 160, x = r - y * 160;
                        q = (((long long)img * 162 + y + 1) * 162 + (x + 1)) * 64;
                    }
                    #pragma unroll
                    for (int nb = 0; nb < 4; nb++) {
                        int c = nh * 32 + 8*nb + c2l;
                        float2 hc = dec(accH[nb][rs]);
                        float v0 = sbs[c]     * (accF[nb][2*rs]     + hc.x) + sbs[64 + c];
                        float v1 = sbs[c + 1] * (accF[nb][2*rs + 1] + hc.y) + sbs[64 + c + 1];
                        if (ACT == 0) { v0 = hswish(v0); v1 = hswish(v1); }
                        else { v0 = v0 >= 0.f ? v0 : 0.1f*v0; v1 = v1 >= 0.f ? v1 : 0.1f*v1; }
                        if (OUTM == 2) {
                            *(float2*)(of + p * 128 + coff + 8*nb + c2l) = make_float2(v0, v1);
                        } else {
                            u32 H, L; sp2(v0, v1, H, L);
                            *(u32*)(oh + q + c) = H;
                            *(u32*)(ol + q + c) = L;
                        }
                    }
                }
            }
            __syncthreads();
            buf ^= 1;
        }
    }
}

// ─── 3x3 conv + BN + hswish + residual: 512 thr, warp = row x N32 ──────────
__global__ void __launch_bounds__(512, 2) c3x3(
    const u16* __restrict__ th, const u16* __restrict__ tl,
    const u16* __restrict__ wh, const u16* __restrict__ wl,
    const float* __restrict__ sb,
    u16* __restrict__ yh, u16* __restrict__ yl)
{
    constexpr int APL = 180 * STR * 2;   // 25920 per plane
    constexpr int WPL = 64 * STR * 2;    // 9216  per plane

    extern __shared__ char sm[];
    float* sbs = (float*)sm;
    char* Ah = sm + 512;
    char* Al = Ah + APL;
    char* Wb = Al + APL;                 // [buf][hi|lo]

    const int tid = threadIdx.x;
    const int blk = blockIdx.x;              // 16 imgs * 200 tiles (20x10)
    const int img = blk / 200, t = blk - img * 200;
    const int ty = t / 10, tx = t - ty * 10;
    const int y0 = ty * 8, x0 = tx * 16;

    for (int c = tid; c < 128; c += 512) sbs[c] = sb[c];

    const u32 AhA = smem_u32(Ah), AlA = smem_u32(Al), WbA = smem_u32(Wb);

    for (int i = tid; i < 1440; i += 512) {
        int hr = i >> 3, c8 = i & 7;
        int hy = hr / 18, hx = hr - hy * 18;
        long long s = (((long long)img * 162 + y0 + hy) * 162 + (x0 + hx)) * 64 + c8 * 8;
        u32 off = (hr * STR + c8 * 8) * 2;
        CPA16(AhA + off, th + s);
        CPA16(AlA + off, tl + s);
    }
    for (int i = tid; i < 512; i += 512) {
        int n = i >> 3, c8 = i & 7;
        u32 off = (n * STR + c8 * 8) * 2;
        CPA16(WbA + off,       wh + n*64 + c8*8);
        CPA16(WbA + WPL + off, wl + n*64 + c8*8);
    }
    CPA_WAIT();
    __syncthreads();

    const int warp = tid >> 5, lane = tid & 31;
    const int row = warp >> 1;           // 0..7 : y-row in tile
    const int nh  = warp & 1;            // N-half
    const int acol  = lane & 15;
    const int akoff = (lane & 16) ? 8 : 0;
    const int brow  = (lane & 7) + ((lane & 16) ? 8 : 0);
    const int bkoff = (lane & 8) ? 8 : 0;
    const u32 bOff = ((nh * 32 + brow) * STR + bkoff) * 2;

    float accF[4][4];
    u32 accH[4][2];
    #pragma unroll
    for (int n = 0; n < 4; n++) {
        #pragma unroll
        for (int j = 0; j < 4; j++) accF[n][j] = 0.f;
        accH[n][0] = 0u; accH[n][1] = 0u;
    }

    for (int tap = 0; tap < 9; tap++) {
        const int buf = tap & 1;
        if (tap < 8) {
            const u16* sh = wh + (tap+1)*4096;
            const u16* sl = wl + (tap+1)*4096;
            const u32 WA = WbA + (buf^1)*2*WPL;
            for (int i = tid; i < 512; i += 512) {
                int n = i >> 3, c8 = i & 7;
                u32 off = (n * STR + c8 * 8) * 2;
                CPA16(WA + off,       sh + n*64 + c8*8);
                CPA16(WA + WPL + off, sl + n*64 + c8*8);
            }
            CPA_COMMIT();
        }
        const int kh = tap / 3, kw = tap - kh * 3;
        const int hr = (row + kh) * 18 + acol + kw;
        const u32 aH = AhA + (hr * STR + akoff) * 2;
        const u32 aL = AlA + (hr * STR + akoff) * 2;
        const u32 bH = WbA + buf*2*WPL + bOff;
        const u32 bL = bH + WPL;

        gemm_block_n(accF, accH, aH, aL, bH, bL);

        if (tap < 8) {
            CPA_WAIT0();
            __syncthreads();
        }
    }

    const int gr = lane >> 2, c2l = (lane & 3) * 2;
    #pragma unroll
    for (int rs = 0; rs < 2; rs++) {
        int xx = 8*rs + gr;
        long long q = ((long long)img * 25600 + (y0 + row) * 160 + (x0 + xx)) * 64;
        #pragma unroll
        for (int nb = 0; nb < 4; nb++) {
            int c = nh * 32 + 8*nb + c2l;
            float2 yv0 = dec(*(const u32*)(yh + q + c));
            float2 yv1 = dec(*(const u32*)(yl + q + c));
            float2 hc  = dec(accH[nb][rs]);
            float v0 = sbs[c]     * (accF[nb][2*rs]     + hc.x) + sbs[64 + c];
            float v1 = sbs[c + 1] * (accF[nb][2*rs + 1] + hc.y) + sbs[64 + c + 1];
            v0 = hswish(v0) + yv0.x + yv1.x;
            v1 = hswish(v1) + yv0.y + yv1.y;
            u32 H, L; sp2(v0, v1, H, L);
            *(u32*)(yh + q + c) = H;
            *(u32*)(yl + q + c) = L;
        }
    }
}

// ─── host ──────────────────────────────────────────────────────────────────
extern "C" void kernel_launch(void* const* d_in, const int* in_sizes, int n_in,
                              void* d_out, int out_size)
{
    (void)in_sizes; (void)n_in; (void)out_size;
    const float* x         = (const float*)d_in[0];
    const float* cv1_w     = (const float*)d_in[1];
    const float* cv1_bn    = (const float*)d_in[2];
    const float* m0_cv1_w  = (const float*)d_in[3];
    const float* m0_cv1_bn = (const float*)d_in[4];
    const float* m0_cv2_w  = (const float*)d_in[5];
    const float* m0_cv2_bn = (const float*)d_in[6];
    const float* m1_cv1_w  = (const float*)d_in[7];
    const float* m1_cv1_bn = (const float*)d_in[8];
    const float* m1_cv2_w  = (const float*)d_in[9];
    const float* m1_cv2_bn = (const float*)d_in[10];
    const float* cv3_w     = (const float*)d_in[11];
    const float* cv2p_w    = (const float*)d_in[12];
    const float* bn_cat    = (const float*)d_in[13];
    const float* cv4_w     = (const float*)d_in[14];
    const float* cv4_bn    = (const float*)d_in[15];
    float* out = (float*)d_out;

    u16 *yh, *yl, *ah, *al, *bh, *bl, *th, *tl, *wh, *wl;
    float* sb;
    cudaGetSymbolAddress((void**)&yh, g_yh); cudaGetSymbolAddress((void**)&yl, g_yl);
    cudaGetSymbolAddress((void**)&ah, g_ah); cudaGetSymbolAddress((void**)&al, g_al);
    cudaGetSymbolAddress((void**)&bh, g_bh); cudaGetSymbolAddress((void**)&bl, g_bl);
    cudaGetSymbolAddress((void**)&th, g_th); cudaGetSymbolAddress((void**)&tl, g_tl);
    cudaGetSymbolAddress((void**)&wh, g_wh); cudaGetSymbolAddress((void**)&wl, g_wl);
    cudaGetSymbolAddress((void**)&sb, g_sb);

    constexpr int S1_64  = 512 + 1*2*9216 + 2*2*18432;     // 92672
    constexpr int S1_128 = 512 + 2*2*9216 + 2*2*18432;     // 111104
    constexpr int S3     = 512 + 2*25920 + 4*9216;         // 89216
    constexpr int NT = 3200;
    constexpr int GP = 304;

    cudaFuncSetAttribute(g1x1<128,0,0,0>, cudaFuncAttributeMaxDynamicSharedMemorySize, S1_128);
    cudaFuncSetAttribute(g1x1< 64,1,1,0>, cudaFuncAttributeMaxDynamicSharedMemorySize, S1_64);
    cudaFuncSetAttribute(g1x1< 64,1,0,1>, cudaFuncAttributeMaxDynamicSharedMemorySize, S1_64);
    cudaFuncSetAttribute(g1x1<128,0,0,1>, cudaFuncAttributeMaxDynamicSharedMemorySize, S1_128);
    cudaFuncSetAttribute(g1x1<128,2,2,0>, cudaFuncAttributeMaxDynamicSharedMemorySize, S1_128);
    cudaFuncSetAttribute(c3x3,            cudaFuncAttributeMaxDynamicSharedMemorySize, S3);

    prep_all<<<71, 256>>>(cv1_w, m0_cv1_w, m0_cv2_w, m1_cv1_w, m1_cv2_w,
                          cv3_w, cv2p_w, cv4_w,
                          cv1_bn, m0_cv1_bn, m0_cv2_bn, m1_cv1_bn, m1_cv2_bn,
                          bn_cat, cv4_bn, wh, wl, sb, th, tl);

    g1x1<128,0,0,0><<<GP,512,S1_128>>>(x, 0,0,0,0, wh+WO_CV1, wl+WO_CV1, sb+SB_CV1, yh, yl, 0, NT);
    g1x1<64,1,1,0><<<GP,512,S1_64>>>(0, yh,yl,0,0, wh+WO_M0A, wl+WO_M0A, sb+SB_M0A, th, tl, 0, NT);
    c3x3<<<3200,512,S3>>>(th, tl, wh+WO_M0B, wl+WO_M0B, sb+SB_M0B, yh, yl);
    g1x1<64,1,1,0><<<GP,512,S1_64>>>(0, yh,yl,0,0, wh+WO_M1A, wl+WO_M1A, sb+SB_M1A, th, tl, 0, NT);
    c3x3<<<3200,512,S3>>>(th, tl, wh+WO_M1B, wl+WO_M1B, sb+SB_M1B, yh, yl);
    g1x1<64,1,0,1><<<GP,512,S1_64>>>(0, yh,yl,0,0, wh+WO_CV3, wl+WO_CV3, sb+SB_CATA, ah, al, 0, NT);
    g1x1<128,0,0,1><<<GP,512,S1_128>>>(x, 0,0,0,0, wh+WO_CV2P, wl+WO_CV2P, sb+SB_CATB, bh, bl, 0, NT);
    g1x1<128,2,2,0><<<dim3(GP,2),512,S1_128>>>(0, ah,al, bh,bl, wh+WO_CV4, wl+WO_CV4, sb+SB_CV4, 0, 0, out, NT);
}

// round 13
// speedup vs baseline: 1.3845x; 1.1987x over previous
#include <cuda_runtime.h>
#include <cuda_fp16.h>
#include <cstdint>

typedef unsigned short u16;
typedef unsigned int   u32;

constexpr int STR = 72;   // smem row stride in halves (conflict-free for ldsm)

// ─── helpers ───────────────────────────────────────────────────────────────
__device__ __forceinline__ u32 smem_u32(const void* p){
    u32 a;
    asm("{ .reg .u64 t; cvta.to.shared.u64 t, %1; cvt.u32.u64 %0, t; }"
        : "=r"(a) : "l"(p));
    return a;
}
__device__ __forceinline__ void ldsm4(u32 addr, u32& r0, u32& r1, u32& r2, u32& r3){
    asm volatile("ldmatrix.sync.aligned.m8n8.x4.shared.b16 {%0,%1,%2,%3}, [%4];"
        : "=r"(r0), "=r"(r1), "=r"(r2), "=r"(r3) : "r"(addr));
}
__device__ __forceinline__ void mma_(float* c, const u32* a, u32 b0, u32 b1){
    asm volatile("mma.sync.aligned.m16n8k16.row.col.f32.f16.f16.f32 "
        "{%0,%1,%2,%3},{%4,%5,%6,%7},{%8,%9},{%0,%1,%2,%3};"
        : "+f"(c[0]), "+f"(c[1]), "+f"(c[2]), "+f"(c[3])
        : "r"(a[0]), "r"(a[1]), "r"(a[2]), "r"(a[3]), "r"(b0), "r"(b1));
}
__device__ __forceinline__ void mma_h(u32* c, const u32* a, u32 b0, u32 b1){
    asm volatile("mma.sync.aligned.m16n8k16.row.col.f16.f16.f16.f16 "
        "{%0,%1},{%2,%3,%4,%5},{%6,%7},{%0,%1};"
        : "+r"(c[0]), "+r"(c[1])
        : "r"(a[0]), "r"(a[1]), "r"(a[2]), "r"(a[3]), "r"(b0), "r"(b1));
}
#define CPA16(dst, src) \
    asm volatile("cp.async.cg.shared.global [%0], [%1], 16;" :: "r"(dst), "l"(src))
#define CPA_COMMIT()  asm volatile("cp.async.commit_group;" ::: "memory")
#define CPA_WAIT0()   asm volatile("cp.async.wait_group 0;" ::: "memory")
#define CPA_WAIT_G1() asm volatile("cp.async.wait_group 1;" ::: "memory")
#define CPA_WAIT() do { CPA_COMMIT(); CPA_WAIT0(); } while(0)

__device__ __forceinline__ void sp2(float a, float b, u32& H, u32& L){
    __half2 h = __floats2half2_rn(a, b);
    float2 hf = __half22float2(h);
    __half2 l = __floats2half2_rn(a - hf.x, b - hf.y);
    H = *(u32*)&h; L = *(u32*)&l;
}
__device__ __forceinline__ float2 dec(u32 v){
    __half2 h = *(__half2*)&v; return __half22float2(h);
}
__device__ __forceinline__ float hswish(float x){
    return x * __saturatef((x + 3.0f) * (1.0f / 6.0f));
}

// fragment loads: A = 8 regs (hi 4 + lo 4), B = 16 regs (hi 8 + lo 8) over N=32
__device__ __forceinline__ void ldA8(u32* A, u32 aH, u32 aL, int kc){
    ldsm4(aH + kc*32, A[0], A[1], A[2], A[3]);
    ldsm4(aL + kc*32, A[4], A[5], A[6], A[7]);
}
__device__ __forceinline__ void ldB16n(u32* B, u32 bH, u32 bL, int kc){
    const u32 off = kc*32;
    ldsm4(bH + off,            B[0],  B[1],  B[2],  B[3]);
    ldsm4(bH + off + 16*STR*2, B[4],  B[5],  B[6],  B[7]);
    ldsm4(bL + off,            B[8],  B[9],  B[10], B[11]);
    ldsm4(bL + off + 16*STR*2, B[12], B[13], B[14], B[15]);
}
__device__ __forceinline__ void mma12n(float accF[4][4], u32 accH[4][2],
                                       const u32* A, const u32* B){
    #pragma unroll
    for (int g = 0; g < 4; g++)
        mma_(accF[g], A, B[2*g], B[2*g+1]);
    #pragma unroll
    for (int g = 0; g < 4; g++)
        mma_h(accH[g], A+4, B[2*g], B[2*g+1]);
    #pragma unroll
    for (int g = 0; g < 4; g++)
        mma_h(accH[g], A, B[8+2*g], B[8+2*g+1]);
}
__device__ __forceinline__ void gemm_block_n(float accF[4][4], u32 accH[4][2],
                                             u32 aH, u32 aL, u32 bH, u32 bL){
    u32 Ab[2][8], Bb[2][16];
    ldA8(Ab[0], aH, aL, 0);
    ldB16n(Bb[0], bH, bL, 0);
    #pragma unroll
    for (int kc = 0; kc < 4; kc++) {
        if (kc < 3) {
            ldA8(Ab[(kc+1) & 1], aH, aL, kc+1);
            ldB16n(Bb[(kc+1) & 1], bH, bL, kc+1);
        }
        mma12n(accF, accH, Ab[kc & 1], Bb[kc & 1]);
    }
}

// ─── global scratch ────────────────────────────────────────────────────────
#define PXT 409600
#define TPAD (16*162*162)
#define WTOT 118784

__device__ __align__(16) u16 g_yh[PXT*64], g_yl[PXT*64];
__device__ __align__(16) u16 g_ah[PXT*64], g_al[PXT*64];
__device__ __align__(16) u16 g_bh[PXT*64], g_bl[PXT*64];
__device__ __align__(16) u16 g_th[TPAD*64], g_tl[TPAD*64];
__device__ __align__(16) u16 g_uh[TPAD*64], g_ul[TPAD*64];   // t2 (ping-pong)
__device__ __align__(16) u16 g_wh[WTOT], g_wl[WTOT];
__device__ float g_sb[1280];

#define WO_CV1   0
#define WO_M0A   8192
#define WO_M0B   12288
#define WO_M1A   49152
#define WO_M1B   53248
#define WO_CV3   90112
#define WO_CV2P  94208
#define WO_CV4   102400

#define SB_CV1   0
#define SB_M0A   128
#define SB_M0B   256
#define SB_M1A   384
#define SB_M1B   512
#define SB_CATA  640
#define SB_CATB  768
#define SB_CV4   896

// ─── single fused prep kernel ──────────────────────────────────────────────
__global__ void prep_all(
    const float* cv1w, const float* m0a, const float* m0b,
    const float* m1a,  const float* m1b, const float* cv3,
    const float* cv2p, const float* cv4,
    const float* c1bn, const float* a0bn, const float* b0bn,
    const float* a1bn, const float* b1bn, const float* catbn, const float* c4bn,
    u16* wh, u16* wl, float* sb, u16* th, u16* tl, u16* uh, u16* ul)
{
    const int bid = blockIdx.x, tid = threadIdx.x;
    if (bid < 29) {
        const float* src; u16 *dh, *dl; int CIN = 64, COUT = 64, b0;
        if      (bid < 2)  { src = cv1w; dh = wh+WO_CV1;  dl = wl+WO_CV1;  CIN = 128; b0 = 0; }
        else if (bid < 3)  { src = m0a;  dh = wh+WO_M0A;  dl = wl+WO_M0A;  b0 = 2; }
        else if (bid < 12) { src = m0b;  dh = wh+WO_M0B;  dl = wl+WO_M0B;  b0 = 3; }
        else if (bid < 13) { src = m1a;  dh = wh+WO_M1A;  dl = wl+WO_M1A;  b0 = 12; }
        else if (bid < 22) { src = m1b;  dh = wh+WO_M1B;  dl = wl+WO_M1B;  b0 = 13; }
        else if (bid < 23) { src = cv3;  dh = wh+WO_CV3;  dl = wl+WO_CV3;  b0 = 22; }
        else if (bid < 25) { src = cv2p; dh = wh+WO_CV2P; dl = wl+WO_CV2P; CIN = 128; b0 = 23; }
        else               { src = cv4;  dh = wh+WO_CV4;  dl = wl+WO_CV4;  CIN = 128; COUT = 128; b0 = 25; }
        const int base = (bid - b0) * 4096;
        const int per = CIN * COUT;
        #pragma unroll 4
        for (int j = 0; j < 16; j++) {
            int e = base + tid + j * 256;
            int tap = e / per, r = e - tap * per;
            int ci = r / COUT, co = r - ci * COUT;
            float w = src[e];
            __half h = __float2half_rn(w);
            __half l = __float2half_rn(w - __half2float(h));
            int d = tap * per + co * CIN + ci;
            dh[d] = *(u16*)&h; dl[d] = *(u16*)&l;
        }
    } else if (bid == 29) {
        auto seg = [&](int off, const float* s, int C, int stride, int choff){
            for (int c = tid; c < C; c += 256) {
                float g = s[choff + c], b = s[stride + choff + c];
                float m = s[2*stride + choff + c], v = s[3*stride + choff + c];
                float sc = g * rsqrtf(v + 1e-3f);
                sb[off + c] = sc; sb[off + C + c] = b - m * sc;
            }
        };
        seg(SB_CV1,  c1bn, 64, 64, 0);
        seg(SB_M0A,  a0bn, 64, 64, 0);
        seg(SB_M0B,  b0bn, 64, 64, 0);
        seg(SB_M1A,  a1bn, 64, 64, 0);
        seg(SB_M1B,  b1bn, 64, 64, 0);
        seg(SB_CATA, catbn, 64, 128, 0);
        seg(SB_CATB, catbn, 64, 128, 64);
        seg(SB_CV4,       c4bn, 64, 128, 0);
        seg(SB_CV4 + 128, c4bn, 64, 128, 64);
    } else {
        int i = (bid - 30) * 256 + tid;
        if (i >= 16 * 644) return;
        int img = i / 644, r = i - img * 644;
        int y, x;
        if      (r < 162) { y = 0;   x = r; }
        else if (r < 324) { y = 161; x = r - 162; }
        else if (r < 484) { x = 0;   y = r - 324 + 1; }
        else              { x = 161; y = r - 484 + 1; }
        long long q = (((long long)img * 162 + y) * 162 + x) * 64;
        uint4 z = make_uint4(0,0,0,0);
        #pragma unroll
        for (int c = 0; c < 8; c++) {
            *(uint4*)(th + q + c*8) = z; *(uint4*)(tl + q + c*8) = z;
            *(uint4*)(uh + q + c*8) = z; *(uint4*)(ul + q + c*8) = z;
        }
    }
}

// ─── 1x1 conv GEMM (HMMA): persistent, 512 thr, warp = 16 rows x N32 ───────
template<int CIN, int SRC, int OUTM, int ACT>
__global__ void __launch_bounds__(512, 2) g1x1(
    const float* __restrict__ xf,
    const u16* __restrict__ pah, const u16* __restrict__ pal,
    const u16* __restrict__ pbh, const u16* __restrict__ pbl,
    const u16* __restrict__ wh,  const u16* __restrict__ wl,
    const float* __restrict__ sb,
    u16* __restrict__ oh, u16* __restrict__ ol, float* __restrict__ of,
    int ntiles)
{
    constexpr int KB  = CIN / 64;
    constexpr int APL = 128 * STR * 2;   // 18432 per plane
    constexpr int WPL = 64 * STR * 2;    // 9216  per plane

    extern __shared__ char sm[];
    float* sbs  = (float*)sm;
    char* Wbase = sm + 512;                  // [kb][hi|lo]
    char* Abase = Wbase + KB * 2 * WPL;      // [buf][hi|lo]

    const int tid = threadIdx.x;
    const int cy  = blockIdx.y;
    const u16* whp = wh + cy * 64 * CIN;
    const u16* wlp = wl + cy * 64 * CIN;

    for (int c = tid; c < 128; c += 512) sbs[c] = sb[cy * 128 + c];

    const u32 WA = smem_u32(Wbase), AA = smem_u32(Abase);

    #pragma unroll
    for (int kb = 0; kb < KB; kb++)
        for (int i = tid; i < 512; i += 512) {
            int n = i >> 3, c8 = i & 7;
            u32 off = kb * 2 * WPL + (n * STR + c8 * 8) * 2;
            CPA16(WA + off,       whp + n * CIN + kb * 64 + c8 * 8);
            CPA16(WA + off + WPL, wlp + n * CIN + kb * 64 + c8 * 8);
        }

    auto stageA = [&](int t, int kb, int buf){
        long long p0 = (long long)t * 128;
        const u32 AH = AA + buf * 2 * APL;
        char* AB = Abase + buf * 2 * APL;
        for (int i = tid; i < 1024; i += 512) {
            int row = i >> 3, c8 = i & 7;
            u32 off = (row * STR + c8 * 8) * 2;
            if (SRC == 0) {
                const float* g = xf + (p0 + row) * CIN + kb * 64 + c8 * 8;
                float4 f1 = *(const float4*)g, f2 = *(const float4*)(g + 4);
                uint4 H, L;
                sp2(f1.x, f1.y, H.x, L.x); sp2(f1.z, f1.w, H.y, L.y);
                sp2(f2.x, f2.y, H.z, L.z); sp2(f2.z, f2.w, H.w, L.w);
                *(uint4*)(AB + off) = H; *(uint4*)(AB + APL + off) = L;
            } else if (SRC == 1) {
                CPA16(AH + off,       pah + (p0 + row) * CIN + kb * 64 + c8 * 8);
                CPA16(AH + APL + off, pal + (p0 + row) * CIN + kb * 64 + c8 * 8);
            } else {
                const u16* shp = kb ? pbh : pah;
                const u16* slp = kb ? pbl : pal;
                long long so = (p0 + row) * 64 + c8 * 8;
                CPA16(AH + off,       shp + so);
                CPA16(AH + APL + off, slp + so);
            }
        }
    };

    const int warp = tid >> 5, lane = tid & 31;
    const int mrow = warp >> 1;
    const int nh   = warp & 1;
    const int arow  = 16 * mrow + (lane & 7) + ((lane & 8) ? 8 : 0);
    const int akoff = (lane & 16) ? 8 : 0;
    const u32 aOff = (arow * STR + akoff) * 2;
    const int brow  = (lane & 7) + ((lane & 16) ? 8 : 0);
    const int bkoff = (lane & 8) ? 8 : 0;
    const u32 bOff = ((nh * 32 + brow) * STR + bkoff) * 2;

    const int gr = lane >> 2, c2l = (lane & 3) * 2;
    const int coff = cy * 64 + nh * 32;

    const int t0 = blockIdx.x;
    if (t0 < ntiles) stageA(t0, 0, 0);
    CPA_COMMIT();

    int buf = 0;
    float accF[4][4];
    u32 accH[4][2];

    for (int t = t0; t < ntiles; t += gridDim.x) {
        #pragma unroll
        for (int n = 0; n < 4; n++) {
            #pragma unroll
            for (int j = 0; j < 4; j++) accF[n][j] = 0.f;
            accH[n][0] = 0u; accH[n][1] = 0u;
        }

        #pragma unroll
        for (int kb = 0; kb < KB; kb++) {
            int nt = t, nkb = kb + 1;
            if (nkb == KB) { nkb = 0; nt = t + gridDim.x; }
            const bool hn = (nt < ntiles);
            if (hn) stageA(nt, nkb, buf ^ 1);
            CPA_COMMIT();
            if (hn) { CPA_WAIT_G1(); } else { CPA_WAIT0(); }
            __syncthreads();

            const u32 aH = AA + buf * 2 * APL + aOff;
            const u32 aL = aH + APL;
            const u32 bH = WA + kb * 2 * WPL + bOff;
            const u32 bL = bH + WPL;

            gemm_block_n(accF, accH, aH, aL, bH, bL);

            if (kb == KB - 1) {
                #pragma unroll
                for (int rs = 0; rs < 2; rs++) {
                    int row = 16*mrow + 8*rs + gr;
                    long long p = (long long)t * 128 + row;
                    long long q = 0;
                    if (OUTM == 0) q = p * 64;
                    else if (OUTM == 1) {
                        int pi = (int)p;
                        int img = pi / 25600, r = pi - img * 25600;
                        int y = r / 160, x = r - y * 160;
                        q = (((long long)img * 162 + y + 1) * 162 + (x + 1)) * 64;
                    }
                    #pragma unroll
                    for (int nb = 0; nb < 4; nb++) {
                        int c = nh * 32 + 8*nb + c2l;
                        float2 hc = dec(accH[nb][rs]);
                        float v0 = sbs[c]     * (accF[nb][2*rs]     + hc.x) + sbs[64 + c];
                        float v1 = sbs[c + 1] * (accF[nb][2*rs + 1] + hc.y) + sbs[64 + c + 1];
                        if (ACT == 0) { v0 = hswish(v0); v1 = hswish(v1); }
                        else { v0 = v0 >= 0.f ? v0 : 0.1f*v0; v1 = v1 >= 0.f ? v1 : 0.1f*v1; }
                        if (OUTM == 2) {
                            *(float2*)(of + p * 128 + coff + 8*nb + c2l) = make_float2(v0, v1);
                        } else {
                            u32 H, L; sp2(v0, v1, H, L);
                            *(u32*)(oh + q + c) = H;
                            *(u32*)(ol + q + c) = L;
                        }
                    }
                }
            }
            __syncthreads();
            buf ^= 1;
        }
    }
}

// ─── fused 3x3 conv (+BN+hswish+residual) + tile-local 1x1 conv ────────────
// DST=0: fused 1x1 -> hswish -> padded t2 planes (o2). keeps y gmem write.
// DST=1: fused 1x1 -> leaky(bn_cat) -> unpadded planes (o2). y write skipped.
template<int DST>
__global__ void __launch_bounds__(512, 2) c3x3f(
    const u16* __restrict__ th, const u16* __restrict__ tl,
    const u16* __restrict__ wh, const u16* __restrict__ wl,
    const u16* __restrict__ w1h, const u16* __restrict__ w1l,
    const float* __restrict__ sb, const float* __restrict__ sb2,
    u16* __restrict__ yh, u16* __restrict__ yl,
    u16* __restrict__ o2h, u16* __restrict__ o2l)
{
    constexpr int APL = 180 * STR * 2;   // 25920 per halo plane
    constexpr int WPL = 64 * STR * 2;    // 9216  per weight plane
    constexpr int YPL = 128 * STR * 2;   // 18432 per y-smem plane

    extern __shared__ char sm[];
    float* sbs = (float*)sm;             // 256 floats
    char* Ah = sm + 1024;
    char* Al = Ah + APL;
    char* Wb = Al + APL;                 // taps: [buf][hi|lo]; later: y-smem hi|lo

    const int tid = threadIdx.x;
    const int blk = blockIdx.x;              // 16 imgs * 200 tiles (20x10)
    const int img = blk / 200, t = blk - img * 200;
    const int ty = t / 10, tx = t - ty * 10;
    const int y0 = ty * 8, x0 = tx * 16;

    for (int c = tid; c < 128; c += 512) { sbs[c] = sb[c]; sbs[128 + c] = sb2[c]; }

    const u32 AhA = smem_u32(Ah), AlA = smem_u32(Al), WbA = smem_u32(Wb);

    for (int i = tid; i < 1440; i += 512) {
        int hr = i >> 3, c8 = i & 7;
        int hy = hr / 18, hx = hr - hy * 18;
        long long s = (((long long)img * 162 + y0 + hy) * 162 + (x0 + hx)) * 64 + c8 * 8;
        u32 off = (hr * STR + c8 * 8) * 2;
        CPA16(AhA + off, th + s);
        CPA16(AlA + off, tl + s);
    }
    for (int i = tid; i < 512; i += 512) {
        int n = i >> 3, c8 = i & 7;
        u32 off = (n * STR + c8 * 8) * 2;
        CPA16(WbA + off,       wh + n*64 + c8*8);
        CPA16(WbA + WPL + off, wl + n*64 + c8*8);
    }
    CPA_WAIT();
    __syncthreads();

    const int warp = tid >> 5, lane = tid & 31;
    const int row = warp >> 1;           // 0..7 : y-row in tile
    const int nh  = warp & 1;            // N-half
    const int acol  = lane & 15;
    const int akoff = (lane & 16) ? 8 : 0;
    const int brow  = (lane & 7) + ((lane & 16) ? 8 : 0);
    const int bkoff = (lane & 8) ? 8 : 0;
    const u32 bOff = ((nh * 32 + brow) * STR + bkoff) * 2;

    float accF[4][4];
    u32 accH[4][2];
    #pragma unroll
    for (int n = 0; n < 4; n++) {
        #pragma unroll
        for (int j = 0; j < 4; j++) accF[n][j] = 0.f;
        accH[n][0] = 0u; accH[n][1] = 0u;
    }

    for (int tap = 0; tap < 9; tap++) {
        const int buf = tap & 1;
        if (tap < 8) {
            const u16* sh = wh + (tap+1)*4096;
            const u16* sl = wl + (tap+1)*4096;
            const u32 WA = WbA + (buf^1)*2*WPL;
            for (int i = tid; i < 512; i += 512) {
                int n = i >> 3, c8 = i & 7;
                u32 off = (n * STR + c8 * 8) * 2;
                CPA16(WA + off,       sh + n*64 + c8*8);
                CPA16(WA + WPL + off, sl + n*64 + c8*8);
            }
            CPA_COMMIT();
        }
        const int kh = tap / 3, kw = tap - kh * 3;
        const int hr = (row + kh) * 18 + acol + kw;
        const u32 aH = AhA + (hr * STR + akoff) * 2;
        const u32 aL = AlA + (hr * STR + akoff) * 2;
        const u32 bH = WbA + buf*2*WPL + bOff;
        const u32 bL = bH + WPL;

        gemm_block_n(accF, accH, aH, aL, bH, bL);

        if (tap < 8) {
            CPA_WAIT0();
            __syncthreads();
        }
    }
    __syncthreads();   // all gemm reads of Wb + halo done (tap 8 had no sync)

    // ── epilogue 1: BN + hswish + residual; stash new y into smem (Wb) ─────
    const int gr = lane >> 2, c2l = (lane & 3) * 2;
    #pragma unroll
    for (int rs = 0; rs < 2; rs++) {
        int xx = 8*rs + gr;
        int px = row * 16 + xx;
        long long q = ((long long)img * 25600 + (y0 + row) * 160 + (x0 + xx)) * 64;
        #pragma unroll
        for (int nb = 0; nb < 4; nb++) {
            int c = nh * 32 + 8*nb + c2l;
            float2 yv0 = dec(*(const u32*)(yh + q + c));
            float2 yv1 = dec(*(const u32*)(yl + q + c));
            float2 hc  = dec(accH[nb][rs]);
            float v0 = sbs[c]     * (accF[nb][2*rs]     + hc.x) + sbs[64 + c];
            float v1 = sbs[c + 1] * (accF[nb][2*rs + 1] + hc.y) + sbs[64 + c + 1];
            v0 = hswish(v0) + yv0.x + yv1.x;
            v1 = hswish(v1) + yv0.y + yv1.y;
            u32 H, L; sp2(v0, v1, H, L);
            if (DST == 0) {
                *(u32*)(yh + q + c) = H;
                *(u32*)(yl + q + c) = L;
            }
            u32 off = (px * STR + c) * 2;
            *(u32*)(Wb + off)       = H;
            *(u32*)(Wb + YPL + off) = L;
        }
    }

    // stage 1x1 weights into (free) halo region
    for (int i = tid; i < 512; i += 512) {
        int n = i >> 3, c8 = i & 7;
        u32 off = (n * STR + c8 * 8) * 2;
        CPA16(AhA + off,       w1h + n*64 + c8*8);
        CPA16(AhA + WPL + off, w1l + n*64 + c8*8);
    }
    CPA_WAIT();
    __syncthreads();   // y-smem + W1 visible

    // ── fused 1x1 GEMM over this tile's 128 px ─────────────────────────────
    {
        const int mblk = warp >> 1;
        const int arow2 = 16 * mblk + (lane & 7) + ((lane & 8) ? 8 : 0);
        const u32 aOff2 = (arow2 * STR + akoff) * 2;
        #pragma unroll
        for (int n = 0; n < 4; n++) {
            #pragma unroll
            for (int j = 0; j < 4; j++) accF[n][j] = 0.f;
            accH[n][0] = 0u; accH[n][1] = 0u;
        }
        gemm_block_n(accF, accH, WbA + aOff2, WbA + YPL + aOff2,
                     AhA + bOff, AhA + WPL + bOff);

        #pragma unroll
        for (int rs = 0; rs < 2; rs++) {
            int px = 16 * mblk + 8*rs + gr;
            int yy = px >> 4, xx = px & 15;
            long long q2;
            if (DST == 0)
                q2 = (((long long)img * 162 + y0 + yy + 1) * 162 + (x0 + xx + 1)) * 64;
            else
                q2 = ((long long)img * 25600 + (y0 + yy) * 160 + (x0 + xx)) * 64;
            #pragma unroll
            for (int nb = 0; nb < 4; nb++) {
                int c = nh * 32 + 8*nb + c2l;
                float2 hc = dec(accH[nb][rs]);
                float v0 = sbs[128 + c]     * (accF[nb][2*rs]     + hc.x) + sbs[192 + c];
                float v1 = sbs[128 + c + 1] * (accF[nb][2*rs + 1] + hc.y) + sbs[192 + c + 1];
                if (DST == 0) { v0 = hswish(v0); v1 = hswish(v1); }
                else { v0 = v0 >= 0.f ? v0 : 0.1f*v0; v1 = v1 >= 0.f ? v1 : 0.1f*v1; }
                u32 H, L; sp2(v0, v1, H, L);
                *(u32*)(o2h + q2 + c) = H;
                *(u32*)(o2l + q2 + c) = L;
            }
        }
    }
}

// ─── host ──────────────────────────────────────────────────────────────────
extern "C" void kernel_launch(void* const* d_in, const int* in_sizes, int n_in,
                              void* d_out, int out_size)
{
    (void)in_sizes; (void)n_in; (void)out_size;
    const float* x         = (const float*)d_in[0];
    const float* cv1_w     = (const float*)d_in[1];
    const float* cv1_bn    = (const float*)d_in[2];
    const float* m0_cv1_w  = (const float*)d_in[3];
    const float* m0_cv1_bn = (const float*)d_in[4];
    const float* m0_cv2_w  = (const float*)d_in[5];
    const float* m0_cv2_bn = (const float*)d_in[6];
    const float* m1_cv1_w  = (const float*)d_in[7];
    const float* m1_cv1_bn = (const float*)d_in[8];
    const float* m1_cv2_w  = (const float*)d_in[9];
    const float* m1_cv2_bn = (const float*)d_in[10];
    const float* cv3_w     = (const float*)d_in[11];
    const float* cv2p_w    = (const float*)d_in[12];
    const float* bn_cat    = (const float*)d_in[13];
    const float* cv4_w     = (const float*)d_in[14];
    const float* cv4_bn    = (const float*)d_in[15];
    float* out = (float*)d_out;

    u16 *yh, *yl, *ah, *al, *bh, *bl, *th, *tl, *uh, *ul, *wh, *wl;
    float* sb;
    cudaGetSymbolAddress((void**)&yh, g_yh); cudaGetSymbolAddress((void**)&yl, g_yl);
    cudaGetSymbolAddress((void**)&ah, g_ah); cudaGetSymbolAddress((void**)&al, g_al);
    cudaGetSymbolAddress((void**)&bh, g_bh); cudaGetSymbolAddress((void**)&bl, g_bl);
    cudaGetSymbolAddress((void**)&th, g_th); cudaGetSymbolAddress((void**)&tl, g_tl);
    cudaGetSymbolAddress((void**)&uh, g_uh); cudaGetSymbolAddress((void**)&ul, g_ul);
    cudaGetSymbolAddress((void**)&wh, g_wh); cudaGetSymbolAddress((void**)&wl, g_wl);
    cudaGetSymbolAddress((void**)&sb, g_sb);

    constexpr int S1_64  = 512 + 1*2*9216 + 2*2*18432;     // 92672
    constexpr int S1_128 = 512 + 2*2*9216 + 2*2*18432;     // 111104
    constexpr int S3     = 1024 + 2*25920 + 4*9216;        // 89728
    constexpr int NT = 3200;
    constexpr int GP = 304;

    cudaFuncSetAttribute(g1x1<128,0,0,0>, cudaFuncAttributeMaxDynamicSharedMemorySize, S1_128);
    cudaFuncSetAttribute(g1x1< 64,1,1,0>, cudaFuncAttributeMaxDynamicSharedMemorySize, S1_64);
    cudaFuncSetAttribute(g1x1<128,0,0,1>, cudaFuncAttributeMaxDynamicSharedMemorySize, S1_128);
    cudaFuncSetAttribute(g1x1<128,2,2,0>, cudaFuncAttributeMaxDynamicSharedMemorySize, S1_128);
    cudaFuncSetAttribute(c3x3f<0>,        cudaFuncAttributeMaxDynamicSharedMemorySize, S3);
    cudaFuncSetAttribute(c3x3f<1>,        cudaFuncAttributeMaxDynamicSharedMemorySize, S3);

    prep_all<<<71, 256>>>(cv1_w, m0_cv1_w, m0_cv2_w, m1_cv1_w, m1_cv2_w,
                          cv3_w, cv2p_w, cv4_w,
                          cv1_bn, m0_cv1_bn, m0_cv2_bn, m1_cv1_bn, m1_cv2_bn,
                          bn_cat, cv4_bn, wh, wl, sb, th, tl, uh, ul);

    // cv1: x -> y planes
    g1x1<128,0,0,0><<<GP,512,S1_128>>>(x, 0,0,0,0, wh+WO_CV1, wl+WO_CV1, sb+SB_CV1, yh, yl, 0, NT);
    // m0_cv1: y -> t (padded)
    g1x1<64,1,1,0><<<GP,512,S1_64>>>(0, yh,yl,0,0, wh+WO_M0A, wl+WO_M0A, sb+SB_M0A, th, tl, 0, NT);
    // bottleneck0 3x3 (taps m0b) + residual -> y ; fused m1_cv1(y) -> t2 (padded)
    c3x3f<0><<<3200,512,S3>>>(th, tl, wh+WO_M0B, wl+WO_M0B,
                              wh+WO_M1A, wl+WO_M1A,
                              sb+SB_M0B, sb+SB_M1A, yh, yl, uh, ul);
    // bottleneck1 3x3 (taps m1b, reads t2) + residual -> y ; fused cv3(y)+bn_cat[0:64]+leaky -> a
    c3x3f<1><<<3200,512,S3>>>(uh, ul, wh+WO_M1B, wl+WO_M1B,
                              wh+WO_CV3, wl+WO_CV3,
                              sb+SB_M1B, sb+SB_CATA, yh, yl, ah, al);
    // x2 = cv2p(x) + bn_cat[64:128]+leaky -> b planes
    g1x1<128,0,0,1><<<GP,512,S1_128>>>(x, 0,0,0,0, wh+WO_CV2P, wl+WO_CV2P, sb+SB_CATB, bh, bl, 0, NT);
    // cv4: concat(a,b) 128->128 BN+hswish -> out fp32
    g1x1<128,2,2,0><<<dim3(GP,2),512,S1_128>>>(0, ah,al, bh,bl, wh+WO_CV4, wl+WO_CV4, sb+SB_CV4, 0, 0, out, NT);
}

// round 14
// speedup vs baseline: 1.3949x; 1.0075x over previous
#include <cuda_runtime.h>
#include <cuda_fp16.h>
#include <cstdint>

typedef unsigned short u16;
typedef unsigned int   u32;

constexpr int STR = 72;   // smem row stride in halves (conflict-free for ldsm)

// ─── helpers ───────────────────────────────────────────────────────────────
__device__ __forceinline__ u32 smem_u32(const void* p){
    u32 a;
    asm("{ .reg .u64 t; cvta.to.shared.u64 t, %1; cvt.u32.u64 %0, t; }"
        : "=r"(a) : "l"(p));
    return a;
}
__device__ __forceinline__ void ldsm4(u32 addr, u32& r0, u32& r1, u32& r2, u32& r3){
    asm volatile("ldmatrix.sync.aligned.m8n8.x4.shared.b16 {%0,%1,%2,%3}, [%4];"
        : "=r"(r0), "=r"(r1), "=r"(r2), "=r"(r3) : "r"(addr));
}
__device__ __forceinline__ void mma_(float* c, const u32* a, u32 b0, u32 b1){
    asm volatile("mma.sync.aligned.m16n8k16.row.col.f32.f16.f16.f32 "
        "{%0,%1,%2,%3},{%4,%5,%6,%7},{%8,%9},{%0,%1,%2,%3};"
        : "+f"(c[0]), "+f"(c[1]), "+f"(c[2]), "+f"(c[3])
        : "r"(a[0]), "r"(a[1]), "r"(a[2]), "r"(a[3]), "r"(b0), "r"(b1));
}
__device__ __forceinline__ void mma_h(u32* c, const u32* a, u32 b0, u32 b1){
    asm volatile("mma.sync.aligned.m16n8k16.row.col.f16.f16.f16.f16 "
        "{%0,%1},{%2,%3,%4,%5},{%6,%7},{%0,%1};"
        : "+r"(c[0]), "+r"(c[1])
        : "r"(a[0]), "r"(a[1]), "r"(a[2]), "r"(a[3]), "r"(b0), "r"(b1));
}
#define CPA16(dst, src) \
    asm volatile("cp.async.cg.shared.global [%0], [%1], 16;" :: "r"(dst), "l"(src))
#define CPA_COMMIT()  asm volatile("cp.async.commit_group;" ::: "memory")
#define CPA_WAIT0()   asm volatile("cp.async.wait_group 0;" ::: "memory")
#define CPA_WAIT_G1() asm volatile("cp.async.wait_group 1;" ::: "memory")
#define CPA_WAIT() do { CPA_COMMIT(); CPA_WAIT0(); } while(0)

__device__ __forceinline__ void sp2(float a, float b, u32& H, u32& L){
    __half2 h = __floats2half2_rn(a, b);
    float2 hf = __half22float2(h);
    __half2 l = __floats2half2_rn(a - hf.x, b - hf.y);
    H = *(u32*)&h; L = *(u32*)&l;
}
__device__ __forceinline__ float2 dec(u32 v){
    __half2 h = *(__half2*)&v; return __half22float2(h);
}
__device__ __forceinline__ float hswish(float x){
    return x * __saturatef((x + 3.0f) * (1.0f / 6.0f));
}

// fragment loads: A = 8 regs (hi 4 + lo 4), B = 16 regs (hi 8 + lo 8) over N=32
__device__ __forceinline__ void ldA8(u32* A, u32 aH, u32 aL, int kc){
    ldsm4(aH + kc*32, A[0], A[1], A[2], A[3]);
    ldsm4(aL + kc*32, A[4], A[5], A[6], A[7]);
}
__device__ __forceinline__ void ldB16n(u32* B, u32 bH, u32 bL, int kc){
    const u32 off = kc*32;
    ldsm4(bH + off,            B[0],  B[1],  B[2],  B[3]);
    ldsm4(bH + off + 16*STR*2, B[4],  B[5],  B[6],  B[7]);
    ldsm4(bL + off,            B[8],  B[9],  B[10], B[11]);
    ldsm4(bL + off + 16*STR*2, B[12], B[13], B[14], B[15]);
}
__device__ __forceinline__ void mma12n(float accF[4][4], u32 accH[4][2],
                                       const u32* A, const u32* B){
    #pragma unroll
    for (int g = 0; g < 4; g++)
        mma_(accF[g], A, B[2*g], B[2*g+1]);
    #pragma unroll
    for (int g = 0; g < 4; g++)
        mma_h(accH[g], A+4, B[2*g], B[2*g+1]);
    #pragma unroll
    for (int g = 0; g < 4; g++)
        mma_h(accH[g], A, B[8+2*g], B[8+2*g+1]);
}
__device__ __forceinline__ void gemm_block_n(float accF[4][4], u32 accH[4][2],
                                             u32 aH, u32 aL, u32 bH, u32 bL){
    u32 Ab[2][8], Bb[2][16];
    ldA8(Ab[0], aH, aL, 0);
    ldB16n(Bb[0], bH, bL, 0);
    #pragma unroll
    for (int kc = 0; kc < 4; kc++) {
        if (kc < 3) {
            ldA8(Ab[(kc+1) & 1], aH, aL, kc+1);
            ldB16n(Bb[(kc+1) & 1], bH, bL, kc+1);
        }
        mma12n(accF, accH, Ab[kc & 1], Bb[kc & 1]);
    }
}

// ─── global scratch ────────────────────────────────────────────────────────
#define PXT 409600
#define TPAD (16*162*162)
#define WTOT 118784

__device__ __align__(16) u16 g_yh[PXT*64], g_yl[PXT*64];
__device__ __align__(16) u16 g_ah[PXT*64], g_al[PXT*64];
__device__ __align__(16) u16 g_bh[PXT*64], g_bl[PXT*64];
__device__ __align__(16) u16 g_th[TPAD*64], g_tl[TPAD*64];
__device__ __align__(16) u16 g_uh[TPAD*64], g_ul[TPAD*64];
__device__ __align__(16) u16 g_wh[WTOT], g_wl[WTOT];
__device__ float g_sb[1280];

#define WO_CV1   0
#define WO_M0A   8192
#define WO_M0B   12288
#define WO_M1A   49152
#define WO_M1B   53248
#define WO_CV3   90112
#define WO_CV2P  94208
#define WO_CV4   102400

#define SB_CV1   0
#define SB_M0A   128
#define SB_M0B   256
#define SB_M1A   384
#define SB_M1B   512
#define SB_CATA  640
#define SB_CATB  768
#define SB_CV4   896

// ─── single fused prep kernel ──────────────────────────────────────────────
__global__ void prep_all(
    const float* cv1w, const float* m0a, const float* m0b,
    const float* m1a,  const float* m1b, const float* cv3,
    const float* cv2p, const float* cv4,
    const float* c1bn, const float* a0bn, const float* b0bn,
    const float* a1bn, const float* b1bn, const float* catbn, const float* c4bn,
    u16* wh, u16* wl, float* sb, u16* th, u16* tl, u16* uh, u16* ul)
{
    const int bid = blockIdx.x, tid = threadIdx.x;
    if (bid < 29) {
        const float* src; u16 *dh, *dl; int CIN = 64, COUT = 64, b0;
        if      (bid < 2)  { src = cv1w; dh = wh+WO_CV1;  dl = wl+WO_CV1;  CIN = 128; b0 = 0; }
        else if (bid < 3)  { src = m0a;  dh = wh+WO_M0A;  dl = wl+WO_M0A;  b0 = 2; }
        else if (bid < 12) { src = m0b;  dh = wh+WO_M0B;  dl = wl+WO_M0B;  b0 = 3; }
        else if (bid < 13) { src = m1a;  dh = wh+WO_M1A;  dl = wl+WO_M1A;  b0 = 12; }
        else if (bid < 22) { src = m1b;  dh = wh+WO_M1B;  dl = wl+WO_M1B;  b0 = 13; }
        else if (bid < 23) { src = cv3;  dh = wh+WO_CV3;  dl = wl+WO_CV3;  b0 = 22; }
        else if (bid < 25) { src = cv2p; dh = wh+WO_CV2P; dl = wl+WO_CV2P; CIN = 128; b0 = 23; }
        else               { src = cv4;  dh = wh+WO_CV4;  dl = wl+WO_CV4;  CIN = 128; COUT = 128; b0 = 25; }
        const int base = (bid - b0) * 4096;
        const int per = CIN * COUT;
        #pragma unroll 4
        for (int j = 0; j < 16; j++) {
            int e = base + tid + j * 256;
            int tap = e / per, r = e - tap * per;
            int ci = r / COUT, co = r - ci * COUT;
            float w = src[e];
            __half h = __float2half_rn(w);
            __half l = __float2half_rn(w - __half2float(h));
            int d = tap * per + co * CIN + ci;
            dh[d] = *(u16*)&h; dl[d] = *(u16*)&l;
        }
    } else if (bid == 29) {
        auto seg = [&](int off, const float* s, int C, int stride, int choff){
            for (int c = tid; c < C; c += 256) {
                float g = s[choff + c], b = s[stride + choff + c];
                float m = s[2*stride + choff + c], v = s[3*stride + choff + c];
                float sc = g * rsqrtf(v + 1e-3f);
                sb[off + c] = sc; sb[off + C + c] = b - m * sc;
            }
        };
        seg(SB_CV1,  c1bn, 64, 64, 0);
        seg(SB_M0A,  a0bn, 64, 64, 0);
        seg(SB_M0B,  b0bn, 64, 64, 0);
        seg(SB_M1A,  a1bn, 64, 64, 0);
        seg(SB_M1B,  b1bn, 64, 64, 0);
        seg(SB_CATA, catbn, 64, 128, 0);
        seg(SB_CATB, catbn, 64, 128, 64);
        seg(SB_CV4,       c4bn, 64, 128, 0);
        seg(SB_CV4 + 128, c4bn, 64, 128, 64);
    } else {
        int i = (bid - 30) * 256 + tid;
        if (i >= 16 * 644) return;
        int img = i / 644, r = i - img * 644;
        int y, x;
        if      (r < 162) { y = 0;   x = r; }
        else if (r < 324) { y = 161; x = r - 162; }
        else if (r < 484) { x = 0;   y = r - 324 + 1; }
        else              { x = 161; y = r - 484 + 1; }
        long long q = (((long long)img * 162 + y) * 162 + x) * 64;
        uint4 z = make_uint4(0,0,0,0);
        #pragma unroll
        for (int c = 0; c < 8; c++) {
            *(uint4*)(th + q + c*8) = z; *(uint4*)(tl + q + c*8) = z;
            *(uint4*)(uh + q + c*8) = z; *(uint4*)(ul + q + c*8) = z;
        }
    }
}

// ─── 1x1 conv GEMM (HMMA): persistent, 512 thr, warp = 16 rows x N32 ───────
template<int CIN, int SRC, int OUTM, int ACT>
__global__ void __launch_bounds__(512, 2) g1x1(
    const float* __restrict__ xf,
    const u16* __restrict__ pah, const u16* __restrict__ pal,
    const u16* __restrict__ pbh, const u16* __restrict__ pbl,
    const u16* __restrict__ wh,  const u16* __restrict__ wl,
    const float* __restrict__ sb,
    u16* __restrict__ oh, u16* __restrict__ ol, float* __restrict__ of,
    int ntiles)
{
    constexpr int KB  = CIN / 64;
    constexpr int APL = 128 * STR * 2;
    constexpr int WPL = 64 * STR * 2;

    extern __shared__ char sm[];
    float* sbs  = (float*)sm;
    char* Wbase = sm + 512;
    char* Abase = Wbase + KB * 2 * WPL;

    const int tid = threadIdx.x;
    const int cy  = blockIdx.y;
    const u16* whp = wh + cy * 64 * CIN;
    const u16* wlp = wl + cy * 64 * CIN;

    for (int c = tid; c < 128; c += 512) sbs[c] = sb[cy * 128 + c];

    const u32 WA = smem_u32(Wbase), AA = smem_u32(Abase);

    #pragma unroll
    for (int kb = 0; kb < KB; kb++)
        for (int i = tid; i < 512; i += 512) {
            int n = i >> 3, c8 = i & 7;
            u32 off = kb * 2 * WPL + (n * STR + c8 * 8) * 2;
            CPA16(WA + off,       whp + n * CIN + kb * 64 + c8 * 8);
            CPA16(WA + off + WPL, wlp + n * CIN + kb * 64 + c8 * 8);
        }

    auto stageA = [&](int t, int kb, int buf){
        long long p0 = (long long)t * 128;
        const u32 AH = AA + buf * 2 * APL;
        char* AB = Abase + buf * 2 * APL;
        for (int i = tid; i < 1024; i += 512) {
            int row = i >> 3, c8 = i & 7;
            u32 off = (row * STR + c8 * 8) * 2;
            if (SRC == 0) {
                const float* g = xf + (p0 + row) * CIN + kb * 64 + c8 * 8;
                float4 f1 = *(const float4*)g, f2 = *(const float4*)(g + 4);
                uint4 H, L;
                sp2(f1.x, f1.y, H.x, L.x); sp2(f1.z, f1.w, H.y, L.y);
                sp2(f2.x, f2.y, H.z, L.z); sp2(f2.z, f2.w, H.w, L.w);
                *(uint4*)(AB + off) = H; *(uint4*)(AB + APL + off) = L;
            } else {
                const u16* shp = kb ? pbh : pah;
                const u16* slp = kb ? pbl : pal;
                long long so = (p0 + row) * 64 + c8 * 8;
                CPA16(AH + off,       shp + so);
                CPA16(AH + APL + off, slp + so);
            }
        }
    };

    const int warp = tid >> 5, lane = tid & 31;
    const int mrow = warp >> 1;
    const int nh   = warp & 1;
    const int arow  = 16 * mrow + (lane & 7) + ((lane & 8) ? 8 : 0);
    const int akoff = (lane & 16) ? 8 : 0;
    const u32 aOff = (arow * STR + akoff) * 2;
    const int brow  = (lane & 7) + ((lane & 16) ? 8 : 0);
    const int bkoff = (lane & 8) ? 8 : 0;
    const u32 bOff = ((nh * 32 + brow) * STR + bkoff) * 2;

    const int gr = lane >> 2, c2l = (lane & 3) * 2;
    const int coff = cy * 64 + nh * 32;

    const int t0 = blockIdx.x;
    if (t0 < ntiles) stageA(t0, 0, 0);
    CPA_COMMIT();

    int buf = 0;
    float accF[4][4];
    u32 accH[4][2];

    for (int t = t0; t < ntiles; t += gridDim.x) {
        #pragma unroll
        for (int n = 0; n < 4; n++) {
            #pragma unroll
            for (int j = 0; j < 4; j++) accF[n][j] = 0.f;
            accH[n][0] = 0u; accH[n][1] = 0u;
        }

        #pragma unroll
        for (int kb = 0; kb < KB; kb++) {
            int nt = t, nkb = kb + 1;
            if (nkb == KB) { nkb = 0; nt = t + gridDim.x; }
            const bool hn = (nt < ntiles);
            if (hn) stageA(nt, nkb, buf ^ 1);
            CPA_COMMIT();
            if (hn) { CPA_WAIT_G1(); } else { CPA_WAIT0(); }
            __syncthreads();

            const u32 aH = AA + buf * 2 * APL + aOff;
            const u32 aL = aH + APL;
            const u32 bH = WA + kb * 2 * WPL + bOff;
            const u32 bL = bH + WPL;

            gemm_block_n(accF, accH, aH, aL, bH, bL);

            if (kb == KB - 1) {
                #pragma unroll
                for (int rs = 0; rs < 2; rs++) {
                    int row = 16*mrow + 8*rs + gr;
                    long long p = (long long)t * 128 + row;
                    #pragma unroll
                    for (int nb = 0; nb < 4; nb++) {
                        int c = nh * 32 + 8*nb + c2l;
                        float2 hc = dec(accH[nb][rs]);
                        float v0 = sbs[c]     * (accF[nb][2*rs]     + hc.x) + sbs[64 + c];
                        float v1 = sbs[c + 1] * (accF[nb][2*rs + 1] + hc.y) + sbs[64 + c + 1];
                        if (ACT == 0) { v0 = hswish(v0); v1 = hswish(v1); }
                        else { v0 = v0 >= 0.f ? v0 : 0.1f*v0; v1 = v1 >= 0.f ? v1 : 0.1f*v1; }
                        if (OUTM == 2) {
                            *(float2*)(of + p * 128 + coff + 8*nb + c2l) = make_float2(v0, v1);
                        } else {
                            u32 H, L; sp2(v0, v1, H, L);
                            *(u32*)(oh + p * 64 + c) = H;
                            *(u32*)(ol + p * 64 + c) = L;
                        }
                    }
                }
            }
            __syncthreads();
            buf ^= 1;
        }
    }
}

// ─── cv1f: cv1 (x 128->64, BN+hswish) -> y, fused m0_cv1 (64->64) -> t pad ──
__global__ void __launch_bounds__(512, 2) cv1f(
    const float* __restrict__ xf,
    const u16* __restrict__ wh, const u16* __restrict__ wl,     // cv1 (2 kb)
    const u16* __restrict__ w1h, const u16* __restrict__ w1l,   // m0_cv1
    const float* __restrict__ sb, const float* __restrict__ sb2,
    u16* __restrict__ yh, u16* __restrict__ yl,
    u16* __restrict__ o2h, u16* __restrict__ o2l)
{
    constexpr int APL = 128 * STR * 2;   // 18432 per plane
    constexpr int WPL = 64 * STR * 2;    // 9216  per plane

    extern __shared__ char sm[];
    float* sbs = (float*)sm;             // 256 floats
    char* Ab = sm + 1024;                // [kb][hi|lo] : 4 * APL = 73728
    char* Wb = Ab + 4 * APL;             // cv1 W [kb][hi|lo] : 4*WPL; later y stash

    const int tid = threadIdx.x;
    const long long p0 = (long long)blockIdx.x * 128;

    for (int c = tid; c < 128; c += 512) { sbs[c] = sb[c]; sbs[128 + c] = sb2[c]; }

    const u32 AbA = smem_u32(Ab), WbA = smem_u32(Wb);

    // stage cv1 W (both kb, both planes) via cp.async
    for (int i = tid; i < 1024; i += 512) {
        int kb = i >> 9, r = i & 511;
        int n = r >> 3, c8 = r & 7;
        u32 off = kb * 2 * WPL + (n * STR + c8 * 8) * 2;
        CPA16(WbA + off,       wh + n * 128 + kb * 64 + c8 * 8);
        CPA16(WbA + off + WPL, wl + n * 128 + kb * 64 + c8 * 8);
    }
    CPA_COMMIT();
    // stage x (split fp32 -> hi/lo, kb blocks)
    for (int i = tid; i < 2048; i += 512) {
        int row = i >> 4, c16 = i & 15;
        int kb = c16 >> 3, c8 = c16 & 7;
        const float* g = xf + (p0 + row) * 128 + c16 * 8;
        float4 f1 = *(const float4*)g, f2 = *(const float4*)(g + 4);
        uint4 H, L;
        sp2(f1.x, f1.y, H.x, L.x); sp2(f1.z, f1.w, H.y, L.y);
        sp2(f2.x, f2.y, H.z, L.z); sp2(f2.z, f2.w, H.w, L.w);
        u32 off = kb * 2 * APL + (row * STR + c8 * 8) * 2;
        *(uint4*)(Ab + off) = H; *(uint4*)(Ab + APL + off) = L;
    }
    CPA_WAIT0();
    __syncthreads();

    const int warp = tid >> 5, lane = tid & 31;
    const int mrow = warp >> 1;
    const int nh   = warp & 1;
    const int arow  = 16 * mrow + (lane & 7) + ((lane & 8) ? 8 : 0);
    const int akoff = (lane & 16) ? 8 : 0;
    const u32 aOff = (arow * STR + akoff) * 2;
    const int brow  = (lane & 7) + ((lane & 16) ? 8 : 0);
    const int bkoff = (lane & 8) ? 8 : 0;
    const u32 bOff = ((nh * 32 + brow) * STR + bkoff) * 2;
    const int gr = lane >> 2, c2l = (lane & 3) * 2;

    float accF[4][4];
    u32 accH[4][2];
    #pragma unroll
    for (int n = 0; n < 4; n++) {
        #pragma unroll
        for (int j = 0; j < 4; j++) accF[n][j] = 0.f;
        accH[n][0] = 0u; accH[n][1] = 0u;
    }

    #pragma unroll
    for (int kb = 0; kb < 2; kb++)
        gemm_block_n(accF, accH,
                     AbA + kb * 2 * APL + aOff, AbA + kb * 2 * APL + APL + aOff,
                     WbA + kb * 2 * WPL + bOff, WbA + kb * 2 * WPL + WPL + bOff);
    __syncthreads();   // all W/A reads done

    // epilogue 1: BN + hswish -> y planes gmem + stash into Wb
    #pragma unroll
    for (int rs = 0; rs < 2; rs++) {
        int px = 16 * mrow + 8*rs + gr;
        long long p = p0 + px;
        #pragma unroll
        for (int nb = 0; nb < 4; nb++) {
            int c = nh * 32 + 8*nb + c2l;
            float2 hc = dec(accH[nb][rs]);
            float v0 = sbs[c]     * (accF[nb][2*rs]     + hc.x) + sbs[64 + c];
            float v1 = sbs[c + 1] * (accF[nb][2*rs + 1] + hc.y) + sbs[64 + c + 1];
            v0 = hswish(v0); v1 = hswish(v1);
            u32 H, L; sp2(v0, v1, H, L);
            *(u32*)(yh + p * 64 + c) = H;
            *(u32*)(yl + p * 64 + c) = L;
            u32 off = (px * STR + c) * 2;
            *(u32*)(Wb + off)       = H;
            *(u32*)(Wb + APL + off) = L;
        }
    }

    // stage m0_cv1 weights into (free) A region
    for (int i = tid; i < 512; i += 512) {
        int n = i >> 3, c8 = i & 7;
        u32 off = (n * STR + c8 * 8) * 2;
        CPA16(AbA + off,       w1h + n*64 + c8*8);
        CPA16(AbA + WPL + off, w1l + n*64 + c8*8);
    }
    CPA_WAIT();
    __syncthreads();

    // fused 1x1 GEMM: y (smem) x m0_cv1 -> t padded, BN+hswish
    #pragma unroll
    for (int n = 0; n < 4; n++) {
        #pragma unroll
        for (int j = 0; j < 4; j++) accF[n][j] = 0.f;
        accH[n][0] = 0u; accH[n][1] = 0u;
    }
    gemm_block_n(accF, accH, WbA + aOff, WbA + APL + aOff,
                 AbA + bOff, AbA + WPL + bOff);

    #pragma unroll
    for (int rs = 0; rs < 2; rs++) {
        int px = 16 * mrow + 8*rs + gr;
        long long p = p0 + px;
        int pi = (int)p;
        int img = pi / 25600, r = pi - img * 25600;
        int y = r / 160, x = r - y * 160;
        long long q2 = (((long long)img * 162 + y + 1) * 162 + (x + 1)) * 64;
        #pragma unroll
        for (int nb = 0; nb < 4; nb++) {
            int c = nh * 32 + 8*nb + c2l;
            float2 hc = dec(accH[nb][rs]);
            float v0 = sbs[128 + c]     * (accF[nb][2*rs]     + hc.x) + sbs[192 + c];
            float v1 = sbs[128 + c + 1] * (accF[nb][2*rs + 1] + hc.y) + sbs[192 + c + 1];
            v0 = hswish(v0); v1 = hswish(v1);
            u32 H, L; sp2(v0, v1, H, L);
            *(u32*)(o2h + q2 + c) = H;
            *(u32*)(o2l + q2 + c) = L;
        }
    }
}

// ─── fused 3x3 conv (+BN+hswish+residual) + tile-local 1x1 conv ────────────
template<int DST>
__global__ void __launch_bounds__(512, 2) c3x3f(
    const u16* __restrict__ th, const u16* __restrict__ tl,
    const u16* __restrict__ wh, const u16* __restrict__ wl,
    const u16* __restrict__ w1h, const u16* __restrict__ w1l,
    const float* __restrict__ sb, const float* __restrict__ sb2,
    u16* __restrict__ yh, u16* __restrict__ yl,
    u16* __restrict__ o2h, u16* __restrict__ o2l)
{
    constexpr int APL = 180 * STR * 2;
    constexpr int WPL = 64 * STR * 2;
    constexpr int YPL = 128 * STR * 2;

    extern __shared__ char sm[];
    float* sbs = (float*)sm;
    char* Ah = sm + 1024;
    char* Al = Ah + APL;
    char* Wb = Al + APL;

    const int tid = threadIdx.x;
    const int blk = blockIdx.x;
    const int img = blk / 200, t = blk - img * 200;
    const int ty = t / 10, tx = t - ty * 10;
    const int y0 = ty * 8, x0 = tx * 16;

    for (int c = tid; c < 128; c += 512) { sbs[c] = sb[c]; sbs[128 + c] = sb2[c]; }

    const u32 AhA = smem_u32(Ah), AlA = smem_u32(Al), WbA = smem_u32(Wb);

    for (int i = tid; i < 1440; i += 512) {
        int hr = i >> 3, c8 = i & 7;
        int hy = hr / 18, hx = hr - hy * 18;
        long long s = (((long long)img * 162 + y0 + hy) * 162 + (x0 + hx)) * 64 + c8 * 8;
        u32 off = (hr * STR + c8 * 8) * 2;
        CPA16(AhA + off, th + s);
        CPA16(AlA + off, tl + s);
    }
    for (int i = tid; i < 512; i += 512) {
        int n = i >> 3, c8 = i & 7;
        u32 off = (n * STR + c8 * 8) * 2;
        CPA16(WbA + off,       wh + n*64 + c8*8);
        CPA16(WbA + WPL + off, wl + n*64 + c8*8);
    }
    CPA_WAIT();
    __syncthreads();

    const int warp = tid >> 5, lane = tid & 31;
    const int row = warp >> 1;
    const int nh  = warp & 1;
    const int acol  = lane & 15;
    const int akoff = (lane & 16) ? 8 : 0;
    const int brow  = (lane & 7) + ((lane & 16) ? 8 : 0);
    const int bkoff = (lane & 8) ? 8 : 0;
    const u32 bOff = ((nh * 32 + brow) * STR + bkoff) * 2;

    float accF[4][4];
    u32 accH[4][2];
    #pragma unroll
    for (int n = 0; n < 4; n++) {
        #pragma unroll
        for (int j = 0; j < 4; j++) accF[n][j] = 0.f;
        accH[n][0] = 0u; accH[n][1] = 0u;
    }

    for (int tap = 0; tap < 9; tap++) {
        const int buf = tap & 1;
        if (tap < 8) {
            const u16* sh = wh + (tap+1)*4096;
            const u16* sl = wl + (tap+1)*4096;
            const u32 WA = WbA + (buf^1)*2*WPL;
            for (int i = tid; i < 512; i += 512) {
                int n = i >> 3, c8 = i & 7;
                u32 off = (n * STR + c8 * 8) * 2;
                CPA16(WA + off,       sh + n*64 + c8*8);
                CPA16(WA + WPL + off, sl + n*64 + c8*8);
            }
            CPA_COMMIT();
        }
        const int kh = tap / 3, kw = tap - kh * 3;
        const int hr = (row + kh) * 18 + acol + kw;
        const u32 aH = AhA + (hr * STR + akoff) * 2;
        const u32 aL = AlA + (hr * STR + akoff) * 2;
        const u32 bH = WbA + buf*2*WPL + bOff;
        const u32 bL = bH + WPL;

        gemm_block_n(accF, accH, aH, aL, bH, bL);

        if (tap < 8) {
            CPA_WAIT0();
            __syncthreads();
        }
    }
    __syncthreads();

    const int gr = lane >> 2, c2l = (lane & 3) * 2;
    #pragma unroll
    for (int rs = 0; rs < 2; rs++) {
        int xx = 8*rs + gr;
        int px = row * 16 + xx;
        long long q = ((long long)img * 25600 + (y0 + row) * 160 + (x0 + xx)) * 64;
        #pragma unroll
        for (int nb = 0; nb < 4; nb++) {
            int c = nh * 32 + 8*nb + c2l;
            float2 yv0 = dec(*(const u32*)(yh + q + c));
            float2 yv1 = dec(*(const u32*)(yl + q + c));
            float2 hc  = dec(accH[nb][rs]);
            float v0 = sbs[c]     * (accF[nb][2*rs]     + hc.x) + sbs[64 + c];
            float v1 = sbs[c + 1] * (accF[nb][2*rs + 1] + hc.y) + sbs[64 + c + 1];
            v0 = hswish(v0) + yv0.x + yv1.x;
            v1 = hswish(v1) + yv0.y + yv1.y;
            u32 H, L; sp2(v0, v1, H, L);
            if (DST == 0) {
                *(u32*)(yh + q + c) = H;
                *(u32*)(yl + q + c) = L;
            }
            u32 off = (px * STR + c) * 2;
            *(u32*)(Wb + off)       = H;
            *(u32*)(Wb + YPL + off) = L;
        }
    }

    for (int i = tid; i < 512; i += 512) {
        int n = i >> 3, c8 = i & 7;
        u32 off = (n * STR + c8 * 8) * 2;
        CPA16(AhA + off,       w1h + n*64 + c8*8);
        CPA16(AhA + WPL + off, w1l + n*64 + c8*8);
    }
    CPA_WAIT();
    __syncthreads();

    {
        const int mblk = warp >> 1;
        const int arow2 = 16 * mblk + (lane & 7) + ((lane & 8) ? 8 : 0);
        const u32 aOff2 = (arow2 * STR + akoff) * 2;
        #pragma unroll
        for (int n = 0; n < 4; n++) {
            #pragma unroll
            for (int j = 0; j < 4; j++) accF[n][j] = 0.f;
            accH[n][0] = 0u; accH[n][1] = 0u;
        }
        gemm_block_n(accF, accH, WbA + aOff2, WbA + YPL + aOff2,
                     AhA + bOff, AhA + WPL + bOff);

        #pragma unroll
        for (int rs = 0; rs < 2; rs++) {
            int px = 16 * mblk + 8*rs + gr;
            int yy = px >> 4, xx = px & 15;
            long long q2;
            if (DST == 0)
                q2 = (((long long)img * 162 + y0 + yy + 1) * 162 + (x0 + xx + 1)) * 64;
            else
                q2 = ((long long)img * 25600 + (y0 + yy) * 160 + (x0 + xx)) * 64;
            #pragma unroll
            for (int nb = 0; nb < 4; nb++) {
                int c = nh * 32 + 8*nb + c2l;
                float2 hc = dec(accH[nb][rs]);
                float v0 = sbs[128 + c]     * (accF[nb][2*rs]     + hc.x) + sbs[192 + c];
                float v1 = sbs[128 + c + 1] * (accF[nb][2*rs + 1] + hc.y) + sbs[192 + c + 1];
                if (DST == 0) { v0 = hswish(v0); v1 = hswish(v1); }
                else { v0 = v0 >= 0.f ? v0 : 0.1f*v0; v1 = v1 >= 0.f ? v1 : 0.1f*v1; }
                u32 H, L; sp2(v0, v1, H, L);
                *(u32*)(o2h + q2 + c) = H;
                *(u32*)(o2l + q2 + c) = L;
            }
        }
    }
}

// ─── host ──────────────────────────────────────────────────────────────────
extern "C" void kernel_launch(void* const* d_in, const int* in_sizes, int n_in,
                              void* d_out, int out_size)
{
    (void)in_sizes; (void)n_in; (void)out_size;
    const float* x         = (const float*)d_in[0];
    const float* cv1_w     = (const float*)d_in[1];
    const float* cv1_bn    = (const float*)d_in[2];
    const float* m0_cv1_w  = (const float*)d_in[3];
    const float* m0_cv1_bn = (const float*)d_in[4];
    const float* m0_cv2_w  = (const float*)d_in[5];
    const float* m0_cv2_bn = (const float*)d_in[6];
    const float* m1_cv1_w  = (const float*)d_in[7];
    const float* m1_cv1_bn = (const float*)d_in[8];
    const float* m1_cv2_w  = (const float*)d_in[9];
    const float* m1_cv2_bn = (const float*)d_in[10];
    const float* cv3_w     = (const float*)d_in[11];
    const float* cv2p_w    = (const float*)d_in[12];
    const float* bn_cat    = (const float*)d_in[13];
    const float* cv4_w     = (const float*)d_in[14];
    const float* cv4_bn    = (const float*)d_in[15];
    float* out = (float*)d_out;

    u16 *yh, *yl, *ah, *al, *bh, *bl, *th, *tl, *uh, *ul, *wh, *wl;
    float* sb;
    cudaGetSymbolAddress((void**)&yh, g_yh); cudaGetSymbolAddress((void**)&yl, g_yl);
    cudaGetSymbolAddress((void**)&ah, g_ah); cudaGetSymbolAddress((void**)&al, g_al);
    cudaGetSymbolAddress((void**)&bh, g_bh); cudaGetSymbolAddress((void**)&bl, g_bl);
    cudaGetSymbolAddress((void**)&th, g_th); cudaGetSymbolAddress((void**)&tl, g_tl);
    cudaGetSymbolAddress((void**)&uh, g_uh); cudaGetSymbolAddress((void**)&ul, g_ul);
    cudaGetSymbolAddress((void**)&wh, g_wh); cudaGetSymbolAddress((void**)&wl, g_wl);
    cudaGetSymbolAddress((void**)&sb, g_sb);

    constexpr int S1_128 = 512 + 2*2*9216 + 2*2*18432;     // 111104
    constexpr int SCV1   = 1024 + 4*18432 + 4*9216;        // 111616
    constexpr int S3     = 1024 + 2*25920 + 4*9216;        // 89728
    constexpr int NT = 3200;
    constexpr int GP = 304;

    cudaFuncSetAttribute(cv1f,            cudaFuncAttributeMaxDynamicSharedMemorySize, SCV1);
    cudaFuncSetAttribute(g1x1<128,0,2,1>, cudaFuncAttributeMaxDynamicSharedMemorySize, S1_128);
    cudaFuncSetAttribute(g1x1<128,0,0,1>, cudaFuncAttributeMaxDynamicSharedMemorySize, S1_128);
    cudaFuncSetAttribute(g1x1<128,2,2,0>, cudaFuncAttributeMaxDynamicSharedMemorySize, S1_128);
    cudaFuncSetAttribute(c3x3f<0>,        cudaFuncAttributeMaxDynamicSharedMemorySize, S3);
    cudaFuncSetAttribute(c3x3f<1>,        cudaFuncAttributeMaxDynamicSharedMemorySize, S3);

    prep_all<<<71, 256>>>(cv1_w, m0_cv1_w, m0_cv2_w, m1_cv1_w, m1_cv2_w,
                          cv3_w, cv2p_w, cv4_w,
                          cv1_bn, m0_cv1_bn, m0_cv2_bn, m1_cv1_bn, m1_cv2_bn,
                          bn_cat, cv4_bn, wh, wl, sb, th, tl, uh, ul);

    // cv1 + fused m0_cv1: x -> y planes, t padded
    cv1f<<<3200,512,SCV1>>>(x, wh+WO_CV1, wl+WO_CV1, wh+WO_M0A, wl+WO_M0A,
                            sb+SB_CV1, sb+SB_M0A, yh, yl, th, tl);
    // bottleneck0 3x3 + residual -> y ; fused m1_cv1(y) -> u (padded)
    c3x3f<0><<<3200,512,S3>>>(th, tl, wh+WO_M0B, wl+WO_M0B,
                              wh+WO_M1A, wl+WO_M1A,
                              sb+SB_M0B, sb+SB_M1A, yh, yl, uh, ul);
    // bottleneck1 3x3 (reads u) + residual -> y ; fused cv3(y)+bn_cat[0:64]+leaky -> a
    c3x3f<1><<<3200,512,S3>>>(uh, ul, wh+WO_M1B, wl+WO_M1B,
                              wh+WO_CV3, wl+WO_CV3,
                              sb+SB_M1B, sb+SB_CATA, yh, yl, ah, al);
    // x2 = cv2p(x) + bn_cat[64:128]+leaky -> b planes
    g1x1<128,0,0,1><<<GP,512,S1_128>>>(x, 0,0,0,0, wh+WO_CV2P, wl+WO_CV2P, sb+SB_CATB, bh, bl, 0, NT);
    // cv4: concat(a,b) 128->128 BN+hswish -> out fp32
    g1x1<128,2,2,0><<<dim3(GP,2),512,S1_128>>>(0, ah,al, bh,bl, wh+WO_CV4, wl+WO_CV4, sb+SB_CV4, 0, 0, out, NT);
}

// round 15
// speedup vs baseline: 1.4527x; 1.0415x over previous
#include <cuda_runtime.h>
#include <cuda_fp16.h>
#include <cstdint>

typedef unsigned short u16;
typedef unsigned int   u32;

constexpr int STR = 72;   // smem row stride in halves (conflict-free for ldsm)

// ─── helpers ───────────────────────────────────────────────────────────────
__device__ __forceinline__ u32 smem_u32(const void* p){
    u32 a;
    asm("{ .reg .u64 t; cvta.to.shared.u64 t, %1; cvt.u32.u64 %0, t; }"
        : "=r"(a) : "l"(p));
    return a;
}
__device__ __forceinline__ void ldsm4(u32 addr, u32& r0, u32& r1, u32& r2, u32& r3){
    asm volatile("ldmatrix.sync.aligned.m8n8.x4.shared.b16 {%0,%1,%2,%3}, [%4];"
        : "=r"(r0), "=r"(r1), "=r"(r2), "=r"(r3) : "r"(addr));
}
__device__ __forceinline__ void mma_(float* c, const u32* a, u32 b0, u32 b1){
    asm volatile("mma.sync.aligned.m16n8k16.row.col.f32.f16.f16.f32 "
        "{%0,%1,%2,%3},{%4,%5,%6,%7},{%8,%9},{%0,%1,%2,%3};"
        : "+f"(c[0]), "+f"(c[1]), "+f"(c[2]), "+f"(c[3])
        : "r"(a[0]), "r"(a[1]), "r"(a[2]), "r"(a[3]), "r"(b0), "r"(b1));
}
__device__ __forceinline__ void mma_h(u32* c, const u32* a, u32 b0, u32 b1){
    asm volatile("mma.sync.aligned.m16n8k16.row.col.f16.f16.f16.f16 "
        "{%0,%1},{%2,%3,%4,%5},{%6,%7},{%0,%1};"
        : "+r"(c[0]), "+r"(c[1])
        : "r"(a[0]), "r"(a[1]), "r"(a[2]), "r"(a[3]), "r"(b0), "r"(b1));
}
#define CPA16(dst, src) \
    asm volatile("cp.async.cg.shared.global [%0], [%1], 16;" :: "r"(dst), "l"(src))
#define CPA_COMMIT()  asm volatile("cp.async.commit_group;" ::: "memory")
#define CPA_WAIT0()   asm volatile("cp.async.wait_group 0;" ::: "memory")
#define CPA_WAIT_G1() asm volatile("cp.async.wait_group 1;" ::: "memory")
#define CPA_WAIT() do { CPA_COMMIT(); CPA_WAIT0(); } while(0)

__device__ __forceinline__ void sp2(float a, float b, u32& H, u32& L){
    __half2 h = __floats2half2_rn(a, b);
    float2 hf = __half22float2(h);
    __half2 l = __floats2half2_rn(a - hf.x, b - hf.y);
    H = *(u32*)&h; L = *(u32*)&l;
}
__device__ __forceinline__ float2 dec(u32 v){
    __half2 h = *(__half2*)&v; return __half22float2(h);
}
__device__ __forceinline__ float hswish(float x){
    return x * __saturatef((x + 3.0f) * (1.0f / 6.0f));
}

// fragment loads: A = 8 regs (hi 4 + lo 4), B = 16 regs (hi 8 + lo 8) over N=32
__device__ __forceinline__ void ldA8(u32* A, u32 aH, u32 aL, int kc){
    ldsm4(aH + kc*32, A[0], A[1], A[2], A[3]);
    ldsm4(aL + kc*32, A[4], A[5], A[6], A[7]);
}
__device__ __forceinline__ void ldB16n(u32* B, u32 bH, u32 bL, int kc){
    const u32 off = kc*32;
    ldsm4(bH + off,            B[0],  B[1],  B[2],  B[3]);
    ldsm4(bH + off + 16*STR*2, B[4],  B[5],  B[6],  B[7]);
    ldsm4(bL + off,            B[8],  B[9],  B[10], B[11]);
    ldsm4(bL + off + 16*STR*2, B[12], B[13], B[14], B[15]);
}
__device__ __forceinline__ void mma12n(float accF[4][4], u32 accH[4][2],
                                       const u32* A, const u32* B){
    #pragma unroll
    for (int g = 0; g < 4; g++)
        mma_(accF[g], A, B[2*g], B[2*g+1]);
    #pragma unroll
    for (int g = 0; g < 4; g++)
        mma_h(accH[g], A+4, B[2*g], B[2*g+1]);
    #pragma unroll
    for (int g = 0; g < 4; g++)
        mma_h(accH[g], A, B[8+2*g], B[8+2*g+1]);
}
__device__ __forceinline__ void gemm_block_n(float accF[4][4], u32 accH[4][2],
                                             u32 aH, u32 aL, u32 bH, u32 bL){
    u32 Ab[2][8], Bb[2][16];
    ldA8(Ab[0], aH, aL, 0);
    ldB16n(Bb[0], bH, bL, 0);
    #pragma unroll
    for (int kc = 0; kc < 4; kc++) {
        if (kc < 3) {
            ldA8(Ab[(kc+1) & 1], aH, aL, kc+1);
            ldB16n(Bb[(kc+1) & 1], bH, bL, kc+1);
        }
        mma12n(accF, accH, Ab[kc & 1], Bb[kc & 1]);
    }
}

// ─── global scratch ────────────────────────────────────────────────────────
#define PXT 409600
#define TPAD (16*162*162)
#define WTOT 118784

__device__ __align__(16) u16 g_yh[PXT*64], g_yl[PXT*64];
__device__ __align__(16) u16 g_ah[PXT*64], g_al[PXT*64];
__device__ __align__(16) u16 g_bh[PXT*64], g_bl[PXT*64];
__device__ __align__(16) u16 g_th[TPAD*64], g_tl[TPAD*64];
__device__ __align__(16) u16 g_uh[TPAD*64], g_ul[TPAD*64];
__device__ __align__(16) u16 g_wh[WTOT], g_wl[WTOT];
__device__ float g_sb[1280];

#define WO_CV1   0
#define WO_M0A   8192
#define WO_M0B   12288
#define WO_M1A   49152
#define WO_M1B   53248
#define WO_CV3   90112
#define WO_CV2P  94208
#define WO_CV4   102400

#define SB_CV1   0
#define SB_M0A   128
#define SB_M0B   256
#define SB_M1A   384
#define SB_M1B   512
#define SB_CATA  640
#define SB_CATB  768
#define SB_CV4   896

// ─── single fused prep kernel ──────────────────────────────────────────────
__global__ void prep_all(
    const float* cv1w, const float* m0a, const float* m0b,
    const float* m1a,  const float* m1b, const float* cv3,
    const float* cv2p, const float* cv4,
    const float* c1bn, const float* a0bn, const float* b0bn,
    const float* a1bn, const float* b1bn, const float* catbn, const float* c4bn,
    u16* wh, u16* wl, float* sb, u16* th, u16* tl, u16* uh, u16* ul)
{
    const int bid = blockIdx.x, tid = threadIdx.x;
    if (bid < 29) {
        const float* src; u16 *dh, *dl; int CIN = 64, COUT = 64, b0;
        if      (bid < 2)  { src = cv1w; dh = wh+WO_CV1;  dl = wl+WO_CV1;  CIN = 128; b0 = 0; }
        else if (bid < 3)  { src = m0a;  dh = wh+WO_M0A;  dl = wl+WO_M0A;  b0 = 2; }
        else if (bid < 12) { src = m0b;  dh = wh+WO_M0B;  dl = wl+WO_M0B;  b0 = 3; }
        else if (bid < 13) { src = m1a;  dh = wh+WO_M1A;  dl = wl+WO_M1A;  b0 = 12; }
        else if (bid < 22) { src = m1b;  dh = wh+WO_M1B;  dl = wl+WO_M1B;  b0 = 13; }
        else if (bid < 23) { src = cv3;  dh = wh+WO_CV3;  dl = wl+WO_CV3;  b0 = 22; }
        else if (bid < 25) { src = cv2p; dh = wh+WO_CV2P; dl = wl+WO_CV2P; CIN = 128; b0 = 23; }
        else               { src = cv4;  dh = wh+WO_CV4;  dl = wl+WO_CV4;  CIN = 128; COUT = 128; b0 = 25; }
        const int base = (bid - b0) * 4096;
        const int per = CIN * COUT;
        #pragma unroll 4
        for (int j = 0; j < 16; j++) {
            int e = base + tid + j * 256;
            int tap = e / per, r = e - tap * per;
            int ci = r / COUT, co = r - ci * COUT;
            float w = src[e];
            __half h = __float2half_rn(w);
            __half l = __float2half_rn(w - __half2float(h));
            int d = tap * per + co * CIN + ci;
            dh[d] = *(u16*)&h; dl[d] = *(u16*)&l;
        }
    } else if (bid == 29) {
        auto seg = [&](int off, const float* s, int C, int stride, int choff){
            for (int c = tid; c < C; c += 256) {
                float g = s[choff + c], b = s[stride + choff + c];
                float m = s[2*stride + choff + c], v = s[3*stride + choff + c];
                float sc = g * rsqrtf(v + 1e-3f);
                sb[off + c] = sc; sb[off + C + c] = b - m * sc;
            }
        };
        seg(SB_CV1,  c1bn, 64, 64, 0);
        seg(SB_M0A,  a0bn, 64, 64, 0);
        seg(SB_M0B,  b0bn, 64, 64, 0);
        seg(SB_M1A,  a1bn, 64, 64, 0);
        seg(SB_M1B,  b1bn, 64, 64, 0);
        seg(SB_CATA, catbn, 64, 128, 0);
        seg(SB_CATB, catbn, 64, 128, 64);
        seg(SB_CV4,       c4bn, 64, 128, 0);
        seg(SB_CV4 + 128, c4bn, 64, 128, 64);
    } else {
        int i = (bid - 30) * 256 + tid;
        if (i >= 16 * 644) return;
        int img = i / 644, r = i - img * 644;
        int y, x;
        if      (r < 162) { y = 0;   x = r; }
        else if (r < 324) { y = 161; x = r - 162; }
        else if (r < 484) { x = 0;   y = r - 324 + 1; }
        else              { x = 161; y = r - 484 + 1; }
        long long q = (((long long)img * 162 + y) * 162 + x) * 64;
        uint4 z = make_uint4(0,0,0,0);
        #pragma unroll
        for (int c = 0; c < 8; c++) {
            *(uint4*)(th + q + c*8) = z; *(uint4*)(tl + q + c*8) = z;
            *(uint4*)(uh + q + c*8) = z; *(uint4*)(ul + q + c*8) = z;
        }
    }
}

// ─── 1x1 conv GEMM (HMMA): persistent, 512 thr, warp = 16 rows x N32 ───────
template<int CIN, int SRC, int OUTM, int ACT>
__global__ void __launch_bounds__(512, 2) g1x1(
    const float* __restrict__ xf,
    const u16* __restrict__ pah, const u16* __restrict__ pal,
    const u16* __restrict__ pbh, const u16* __restrict__ pbl,
    const u16* __restrict__ wh,  const u16* __restrict__ wl,
    const float* __restrict__ sb,
    u16* __restrict__ oh, u16* __restrict__ ol, float* __restrict__ of,
    int ntiles)
{
    constexpr int KB  = CIN / 64;
    constexpr int APL = 128 * STR * 2;
    constexpr int WPL = 64 * STR * 2;

    extern __shared__ char sm[];
    float* sbs  = (float*)sm;
    char* Wbase = sm + 512;
    char* Abase = Wbase + KB * 2 * WPL;

    const int tid = threadIdx.x;
    const int cy  = blockIdx.y;
    const u16* whp = wh + cy * 64 * CIN;
    const u16* wlp = wl + cy * 64 * CIN;

    for (int c = tid; c < 128; c += 512) sbs[c] = sb[cy * 128 + c];

    const u32 WA = smem_u32(Wbase), AA = smem_u32(Abase);

    #pragma unroll
    for (int kb = 0; kb < KB; kb++)
        for (int i = tid; i < 512; i += 512) {
            int n = i >> 3, c8 = i & 7;
            u32 off = kb * 2 * WPL + (n * STR + c8 * 8) * 2;
            CPA16(WA + off,       whp + n * CIN + kb * 64 + c8 * 8);
            CPA16(WA + off + WPL, wlp + n * CIN + kb * 64 + c8 * 8);
        }

    auto stageA = [&](int t, int kb, int buf){
        long long p0 = (long long)t * 128;
        const u32 AH = AA + buf * 2 * APL;
        for (int i = tid; i < 1024; i += 512) {
            int row = i >> 3, c8 = i & 7;
            u32 off = (row * STR + c8 * 8) * 2;
            const u16* shp = kb ? pbh : pah;
            const u16* slp = kb ? pbl : pal;
            long long so = (p0 + row) * 64 + c8 * 8;
            CPA16(AH + off,       shp + so);
            CPA16(AH + APL + off, slp + so);
        }
    };

    const int warp = tid >> 5, lane = tid & 31;
    const int mrow = warp >> 1;
    const int nh   = warp & 1;
    const int arow  = 16 * mrow + (lane & 7) + ((lane & 8) ? 8 : 0);
    const int akoff = (lane & 16) ? 8 : 0;
    const u32 aOff = (arow * STR + akoff) * 2;
    const int brow  = (lane & 7) + ((lane & 16) ? 8 : 0);
    const int bkoff = (lane & 8) ? 8 : 0;
    const u32 bOff = ((nh * 32 + brow) * STR + bkoff) * 2;

    const int gr = lane >> 2, c2l = (lane & 3) * 2;
    const int coff = cy * 64 + nh * 32;

    const int t0 = blockIdx.x;
    if (t0 < ntiles) stageA(t0, 0, 0);
    CPA_COMMIT();

    int buf = 0;
    float accF[4][4];
    u32 accH[4][2];

    for (int t = t0; t < ntiles; t += gridDim.x) {
        #pragma unroll
        for (int n = 0; n < 4; n++) {
            #pragma unroll
            for (int j = 0; j < 4; j++) accF[n][j] = 0.f;
            accH[n][0] = 0u; accH[n][1] = 0u;
        }

        #pragma unroll
        for (int kb = 0; kb < KB; kb++) {
            int nt = t, nkb = kb + 1;
            if (nkb == KB) { nkb = 0; nt = t + gridDim.x; }
            const bool hn = (nt < ntiles);
            if (hn) stageA(nt, nkb, buf ^ 1);
            CPA_COMMIT();
            if (hn) { CPA_WAIT_G1(); } else { CPA_WAIT0(); }
            __syncthreads();

            const u32 aH = AA + buf * 2 * APL + aOff;
            const u32 aL = aH + APL;
            const u32 bH = WA + kb * 2 * WPL + bOff;
            const u32 bL = bH + WPL;

            gemm_block_n(accF, accH, aH, aL, bH, bL);

            if (kb == KB - 1) {
                #pragma unroll
                for (int rs = 0; rs < 2; rs++) {
                    int row = 16*mrow + 8*rs + gr;
                    long long p = (long long)t * 128 + row;
                    #pragma unroll
                    for (int nb = 0; nb < 4; nb++) {
                        int c = nh * 32 + 8*nb + c2l;
                        float2 hc = dec(accH[nb][rs]);
                        float v0 = sbs[c]     * (accF[nb][2*rs]     + hc.x) + sbs[64 + c];
                        float v1 = sbs[c + 1] * (accF[nb][2*rs + 1] + hc.y) + sbs[64 + c + 1];
                        if (ACT == 0) { v0 = hswish(v0); v1 = hswish(v1); }
                        else { v0 = v0 >= 0.f ? v0 : 0.1f*v0; v1 = v1 >= 0.f ? v1 : 0.1f*v1; }
                        *(float2*)(of + p * 128 + coff + 8*nb + c2l) = make_float2(v0, v1);
                    }
                }
            }
            __syncthreads();
            buf ^= 1;
        }
    }
}

// ─── cv1f2: cv2p(x)->b ; cv1(x)->y ; fused m0_cv1(y)->t padded ─────────────
// Per 128-px tile. x staged+split ONCE. Phases reuse Wb (4 WPL) region.
__global__ void __launch_bounds__(512, 2) cv1f2(
    const float* __restrict__ xf,
    const u16* __restrict__ w2h, const u16* __restrict__ w2l,   // cv2p (2 kb)
    const u16* __restrict__ wh,  const u16* __restrict__ wl,    // cv1  (2 kb)
    const u16* __restrict__ w1h, const u16* __restrict__ w1l,   // m0_cv1
    const float* __restrict__ sb_b, const float* __restrict__ sb_y,
    const float* __restrict__ sb_t,
    u16* __restrict__ bh, u16* __restrict__ bl,
    u16* __restrict__ yh, u16* __restrict__ yl,
    u16* __restrict__ o2h, u16* __restrict__ o2l)
{
    constexpr int APL = 128 * STR * 2;   // 18432
    constexpr int WPL = 64 * STR * 2;    // 9216

    extern __shared__ char sm[];
    float* sbs = (float*)sm;             // 384 floats
    char* Ab = sm + 1536;                // x [kb][hi|lo] : 4 APL ; later y stash
    char* Wb = Ab + 4 * APL;             // W [kb][hi|lo] : 4 WPL (phase-reused)

    const int tid = threadIdx.x;
    const long long p0 = (long long)blockIdx.x * 128;

    for (int c = tid; c < 128; c += 512) {
        sbs[c] = sb_b[c]; sbs[128 + c] = sb_y[c]; sbs[256 + c] = sb_t[c];
    }

    const u32 AbA = smem_u32(Ab), WbA = smem_u32(Wb);

    // stage cv2p W (both kb, both planes)
    for (int i = tid; i < 1024; i += 512) {
        int kb = i >> 9, r = i & 511;
        int n = r >> 3, c8 = r & 7;
        u32 off = kb * 2 * WPL + (n * STR + c8 * 8) * 2;
        CPA16(WbA + off,       w2h + n * 128 + kb * 64 + c8 * 8);
        CPA16(WbA + off + WPL, w2l + n * 128 + kb * 64 + c8 * 8);
    }
    CPA_COMMIT();
    // split x into smem (synchronous stores)
    for (int i = tid; i < 2048; i += 512) {
        int row = i >> 4, c16 = i & 15;
        int kb = c16 >> 3, c8 = c16 & 7;
        const float* g = xf + (p0 + row) * 128 + c16 * 8;
        float4 f1 = *(const float4*)g, f2 = *(const float4*)(g + 4);
        uint4 H, L;
        sp2(f1.x, f1.y, H.x, L.x); sp2(f1.z, f1.w, H.y, L.y);
        sp2(f2.x, f2.y, H.z, L.z); sp2(f2.z, f2.w, H.w, L.w);
        u32 off = kb * 2 * APL + (row * STR + c8 * 8) * 2;
        *(uint4*)(Ab + off) = H; *(uint4*)(Ab + APL + off) = L;
    }
    CPA_WAIT0();
    __syncthreads();

    const int warp = tid >> 5, lane = tid & 31;
    const int mrow = warp >> 1;
    const int nh   = warp & 1;
    const int arow  = 16 * mrow + (lane & 7) + ((lane & 8) ? 8 : 0);
    const int akoff = (lane & 16) ? 8 : 0;
    const u32 aOff = (arow * STR + akoff) * 2;
    const int brow  = (lane & 7) + ((lane & 16) ? 8 : 0);
    const int bkoff = (lane & 8) ? 8 : 0;
    const u32 bOff = ((nh * 32 + brow) * STR + bkoff) * 2;
    const int gr = lane >> 2, c2l = (lane & 3) * 2;

    float accF[4][4];
    u32 accH[4][2];

    // ── phase 1: cv2p -> b (leaky with bn_cat[64:128]) ─────────────────────
    #pragma unroll
    for (int n = 0; n < 4; n++) {
        #pragma unroll
        for (int j = 0; j < 4; j++) accF[n][j] = 0.f;
        accH[n][0] = 0u; accH[n][1] = 0u;
    }
    #pragma unroll
    for (int kb = 0; kb < 2; kb++)
        gemm_block_n(accF, accH,
                     AbA + kb * 2 * APL + aOff, AbA + kb * 2 * APL + APL + aOff,
                     WbA + kb * 2 * WPL + bOff, WbA + kb * 2 * WPL + WPL + bOff);

    #pragma unroll
    for (int rs = 0; rs < 2; rs++) {
        long long p = p0 + 16 * mrow + 8*rs + gr;
        #pragma unroll
        for (int nb = 0; nb < 4; nb++) {
            int c = nh * 32 + 8*nb + c2l;
            float2 hc = dec(accH[nb][rs]);
            float v0 = sbs[c]     * (accF[nb][2*rs]     + hc.x) + sbs[64 + c];
            float v1 = sbs[c + 1] * (accF[nb][2*rs + 1] + hc.y) + sbs[64 + c + 1];
            v0 = v0 >= 0.f ? v0 : 0.1f*v0; v1 = v1 >= 0.f ? v1 : 0.1f*v1;
            u32 H, L; sp2(v0, v1, H, L);
            *(u32*)(bh + p * 64 + c) = H;
            *(u32*)(bl + p * 64 + c) = L;
        }
    }
    __syncthreads();   // all Wb reads done before overwrite

    // ── phase 2: cv1 -> y (hswish); stash y into Ab kb0 ────────────────────
    for (int i = tid; i < 1024; i += 512) {
        int kb = i >> 9, r = i & 511;
        int n = r >> 3, c8 = r & 7;
        u32 off = kb * 2 * WPL + (n * STR + c8 * 8) * 2;
        CPA16(WbA + off,       wh + n * 128 + kb * 64 + c8 * 8);
        CPA16(WbA + off + WPL, wl + n * 128 + kb * 64 + c8 * 8);
    }
    CPA_WAIT();
    __syncthreads();

    #pragma unroll
    for (int n = 0; n < 4; n++) {
        #pragma unroll
        for (int j = 0; j < 4; j++) accF[n][j] = 0.f;
        accH[n][0] = 0u; accH[n][1] = 0u;
    }
    #pragma unroll
    for (int kb = 0; kb < 2; kb++)
        gemm_block_n(accF, accH,
                     AbA + kb * 2 * APL + aOff, AbA + kb * 2 * APL + APL + aOff,
                     WbA + kb * 2 * WPL + bOff, WbA + kb * 2 * WPL + WPL + bOff);
    __syncthreads();   // all x reads done before y stash overwrites Ab kb0

    #pragma unroll
    for (int rs = 0; rs < 2; rs++) {
        int px = 16 * mrow + 8*rs + gr;
        long long p = p0 + px;
        #pragma unroll
        for (int nb = 0; nb < 4; nb++) {
            int c = nh * 32 + 8*nb + c2l;
            float2 hc = dec(accH[nb][rs]);
            float v0 = sbs[128 + c]     * (accF[nb][2*rs]     + hc.x) + sbs[192 + c];
            float v1 = sbs[128 + c + 1] * (accF[nb][2*rs + 1] + hc.y) + sbs[192 + c + 1];
            v0 = hswish(v0); v1 = hswish(v1);
            u32 H, L; sp2(v0, v1, H, L);
            *(u32*)(yh + p * 64 + c) = H;
            *(u32*)(yl + p * 64 + c) = L;
            u32 off = (px * STR + c) * 2;
            *(u32*)(Ab + off)       = H;
            *(u32*)(Ab + APL + off) = L;
        }
    }

    // ── phase 3: m0_cv1(y) -> t padded (hswish) ────────────────────────────
    for (int i = tid; i < 512; i += 512) {
        int n = i >> 3, c8 = i & 7;
        u32 off = (n * STR + c8 * 8) * 2;
        CPA16(WbA + off,       w1h + n*64 + c8*8);
        CPA16(WbA + WPL + off, w1l + n*64 + c8*8);
    }
    CPA_WAIT();
    __syncthreads();   // y stash + W1 visible

    #pragma unroll
    for (int n = 0; n < 4; n++) {
        #pragma unroll
        for (int j = 0; j < 4; j++) accF[n][j] = 0.f;
        accH[n][0] = 0u; accH[n][1] = 0u;
    }
    gemm_block_n(accF, accH, AbA + aOff, AbA + APL + aOff,
                 WbA + bOff, WbA + WPL + bOff);

    #pragma unroll
    for (int rs = 0; rs < 2; rs++) {
        int px = 16 * mrow + 8*rs + gr;
        long long p = p0 + px;
        int pi = (int)p;
        int img = pi / 25600, r = pi - img * 25600;
        int y = r / 160, x = r - y * 160;
        long long q2 = (((long long)img * 162 + y + 1) * 162 + (x + 1)) * 64;
        #pragma unroll
        for (int nb = 0; nb < 4; nb++) {
            int c = nh * 32 + 8*nb + c2l;
            float2 hc = dec(accH[nb][rs]);
            float v0 = sbs[256 + c]     * (accF[nb][2*rs]     + hc.x) + sbs[320 + c];
            float v1 = sbs[256 + c + 1] * (accF[nb][2*rs + 1] + hc.y) + sbs[320 + c + 1];
            v0 = hswish(v0); v1 = hswish(v1);
            u32 H, L; sp2(v0, v1, H, L);
            *(u32*)(o2h + q2 + c) = H;
            *(u32*)(o2l + q2 + c) = L;
        }
    }
}

// ─── fused 3x3 conv (+BN+hswish+residual) + tile-local 1x1 conv ────────────
template<int DST>
__global__ void __launch_bounds__(512, 2) c3x3f(
    const u16* __restrict__ th, const u16* __restrict__ tl,
    const u16* __restrict__ wh, const u16* __restrict__ wl,
    const u16* __restrict__ w1h, const u16* __restrict__ w1l,
    const float* __restrict__ sb, const float* __restrict__ sb2,
    u16* __restrict__ yh, u16* __restrict__ yl,
    u16* __restrict__ o2h, u16* __restrict__ o2l)
{
    constexpr int APL = 180 * STR * 2;
    constexpr int WPL = 64 * STR * 2;
    constexpr int YPL = 128 * STR * 2;

    extern __shared__ char sm[];
    float* sbs = (float*)sm;
    char* Ah = sm + 1024;
    char* Al = Ah + APL;
    char* Wb = Al + APL;

    const int tid = threadIdx.x;
    const int blk = blockIdx.x;
    const int img = blk / 200, t = blk - img * 200;
    const int ty = t / 10, tx = t - ty * 10;
    const int y0 = ty * 8, x0 = tx * 16;

    for (int c = tid; c < 128; c += 512) { sbs[c] = sb[c]; sbs[128 + c] = sb2[c]; }

    const u32 AhA = smem_u32(Ah), AlA = smem_u32(Al), WbA = smem_u32(Wb);

    for (int i = tid; i < 1440; i += 512) {
        int hr = i >> 3, c8 = i & 7;
        int hy = hr / 18, hx = hr - hy * 18;
        long long s = (((long long)img * 162 + y0 + hy) * 162 + (x0 + hx)) * 64 + c8 * 8;
        u32 off = (hr * STR + c8 * 8) * 2;
        CPA16(AhA + off, th + s);
        CPA16(AlA + off, tl + s);
    }
    for (int i = tid; i < 512; i += 512) {
        int n = i >> 3, c8 = i & 7;
        u32 off = (n * STR + c8 * 8) * 2;
        CPA16(WbA + off,       wh + n*64 + c8*8);
        CPA16(WbA + WPL + off, wl + n*64 + c8*8);
    }
    CPA_WAIT();
    __syncthreads();

    const int warp = tid >> 5, lane = tid & 31;
    const int row = warp >> 1;
    const int nh  = warp & 1;
    const int acol  = lane & 15;
    const int akoff = (lane & 16) ? 8 : 0;
    const int brow  = (lane & 7) + ((lane & 16) ? 8 : 0);
    const int bkoff = (lane & 8) ? 8 : 0;
    const u32 bOff = ((nh * 32 + brow) * STR + bkoff) * 2;

    float accF[4][4];
    u32 accH[4][2];
    #pragma unroll
    for (int n = 0; n < 4; n++) {
        #pragma unroll
        for (int j = 0; j < 4; j++) accF[n][j] = 0.f;
        accH[n][0] = 0u; accH[n][1] = 0u;
    }

    for (int tap = 0; tap < 9; tap++) {
        const int buf = tap & 1;
        if (tap < 8) {
            const u16* sh = wh + (tap+1)*4096;
            const u16* sl = wl + (tap+1)*4096;
            const u32 WA = WbA + (buf^1)*2*WPL;
            for (int i = tid; i < 512; i += 512) {
                int n = i >> 3, c8 = i & 7;
                u32 off = (n * STR + c8 * 8) * 2;
                CPA16(WA + off,       sh + n*64 + c8*8);
                CPA16(WA + WPL + off, sl + n*64 + c8*8);
            }
            CPA_COMMIT();
        }
        const int kh = tap / 3, kw = tap - kh * 3;
        const int hr = (row + kh) * 18 + acol + kw;
        const u32 aH = AhA + (hr * STR + akoff) * 2;
        const u32 aL = AlA + (hr * STR + akoff) * 2;
        const u32 bH = WbA + buf*2*WPL + bOff;
        const u32 bL = bH + WPL;

        gemm_block_n(accF, accH, aH, aL, bH, bL);

        if (tap < 8) {
            CPA_WAIT0();
            __syncthreads();
        }
    }
    __syncthreads();

    const int gr = lane >> 2, c2l = (lane & 3) * 2;
    #pragma unroll
    for (int rs = 0; rs < 2; rs++) {
        int xx = 8*rs + gr;
        int px = row * 16 + xx;
        long long q = ((long long)img * 25600 + (y0 + row) * 160 + (x0 + xx)) * 64;
        #pragma unroll
        for (int nb = 0; nb < 4; nb++) {
            int c = nh * 32 + 8*nb + c2l;
            float2 yv0 = dec(*(const u32*)(yh + q + c));
            float2 yv1 = dec(*(const u32*)(yl + q + c));
            float2 hc  = dec(accH[nb][rs]);
            float v0 = sbs[c]     * (accF[nb][2*rs]     + hc.x) + sbs[64 + c];
            float v1 = sbs[c + 1] * (accF[nb][2*rs + 1] + hc.y) + sbs[64 + c + 1];
            v0 = hswish(v0) + yv0.x + yv1.x;
            v1 = hswish(v1) + yv0.y + yv1.y;
            u32 H, L; sp2(v0, v1, H, L);
            if (DST == 0) {
                *(u32*)(yh + q + c) = H;
                *(u32*)(yl + q + c) = L;
            }
            u32 off = (px * STR + c) * 2;
            *(u32*)(Wb + off)       = H;
            *(u32*)(Wb + YPL + off) = L;
        }
    }

    for (int i = tid; i < 512; i += 512) {
        int n = i >> 3, c8 = i & 7;
        u32 off = (n * STR + c8 * 8) * 2;
        CPA16(AhA + off,       w1h + n*64 + c8*8);
        CPA16(AhA + WPL + off, w1l + n*64 + c8*8);
    }
    CPA_WAIT();
    __syncthreads();

    {
        const int mblk = warp >> 1;
        const int arow2 = 16 * mblk + (lane & 7) + ((lane & 8) ? 8 : 0);
        const u32 aOff2 = (arow2 * STR + akoff) * 2;
        #pragma unroll
        for (int n = 0; n < 4; n++) {
            #pragma unroll
            for (int j = 0; j < 4; j++) accF[n][j] = 0.f;
            accH[n][0] = 0u; accH[n][1] = 0u;
        }
        gemm_block_n(accF, accH, WbA + aOff2, WbA + YPL + aOff2,
                     AhA + bOff, AhA + WPL + bOff);

        #pragma unroll
        for (int rs = 0; rs < 2; rs++) {
            int px = 16 * mblk + 8*rs + gr;
            int yy = px >> 4, xx = px & 15;
            long long q2;
            if (DST == 0)
                q2 = (((long long)img * 162 + y0 + yy + 1) * 162 + (x0 + xx + 1)) * 64;
            else
                q2 = ((long long)img * 25600 + (y0 + yy) * 160 + (x0 + xx)) * 64;
            #pragma unroll
            for (int nb = 0; nb < 4; nb++) {
                int c = nh * 32 + 8*nb + c2l;
                float2 hc = dec(accH[nb][rs]);
                float v0 = sbs[128 + c]     * (accF[nb][2*rs]     + hc.x) + sbs[192 + c];
                float v1 = sbs[128 + c + 1] * (accF[nb][2*rs + 1] + hc.y) + sbs[192 + c + 1];
                if (DST == 0) { v0 = hswish(v0); v1 = hswish(v1); }
                else { v0 = v0 >= 0.f ? v0 : 0.1f*v0; v1 = v1 >= 0.f ? v1 : 0.1f*v1; }
                u32 H, L; sp2(v0, v1, H, L);
                *(u32*)(o2h + q2 + c) = H;
                *(u32*)(o2l + q2 + c) = L;
            }
        }
    }
}

// ─── host ──────────────────────────────────────────────────────────────────
extern "C" void kernel_launch(void* const* d_in, const int* in_sizes, int n_in,
                              void* d_out, int out_size)
{
    (void)in_sizes; (void)n_in; (void)out_size;
    const float* x         = (const float*)d_in[0];
    const float* cv1_w     = (const float*)d_in[1];
    const float* cv1_bn    = (const float*)d_in[2];
    const float* m0_cv1_w  = (const float*)d_in[3];
    const float* m0_cv1_bn = (const float*)d_in[4];
    const float* m0_cv2_w  = (const float*)d_in[5];
    const float* m0_cv2_bn = (const float*)d_in[6];
    const float* m1_cv1_w  = (const float*)d_in[7];
    const float* m1_cv1_bn = (const float*)d_in[8];
    const float* m1_cv2_w  = (const float*)d_in[9];
    const float* m1_cv2_bn = (const float*)d_in[10];
    const float* cv3_w     = (const float*)d_in[11];
    const float* cv2p_w    = (const float*)d_in[12];
    const float* bn_cat    = (const float*)d_in[13];
    const float* cv4_w     = (const float*)d_in[14];
    const float* cv4_bn    = (const float*)d_in[15];
    float* out = (float*)d_out;

    u16 *yh, *yl, *ah, *al, *bh, *bl, *th, *tl, *uh, *ul, *wh, *wl;
    float* sb;
    cudaGetSymbolAddress((void**)&yh, g_yh); cudaGetSymbolAddress((void**)&yl, g_yl);
    cudaGetSymbolAddress((void**)&ah, g_ah); cudaGetSymbolAddress((void**)&al, g_al);
    cudaGetSymbolAddress((void**)&bh, g_bh); cudaGetSymbolAddress((void**)&bl, g_bl);
    cudaGetSymbolAddress((void**)&th, g_th); cudaGetSymbolAddress((void**)&tl, g_tl);
    cudaGetSymbolAddress((void**)&uh, g_uh); cudaGetSymbolAddress((void**)&ul, g_ul);
    cudaGetSymbolAddress((void**)&wh, g_wh); cudaGetSymbolAddress((void**)&wl, g_wl);
    cudaGetSymbolAddress((void**)&sb, g_sb);

    constexpr int S1_128 = 512 + 2*2*9216 + 2*2*18432;     // 111104
    constexpr int SCF    = 1536 + 4*18432 + 4*9216;        // 112128
    constexpr int S3     = 1024 + 2*25920 + 4*9216;        // 89728
    constexpr int NT = 3200;
    constexpr int GP = 304;

    cudaFuncSetAttribute(cv1f2,           cudaFuncAttributeMaxDynamicSharedMemorySize, SCF);
    cudaFuncSetAttribute(g1x1<128,2,2,0>, cudaFuncAttributeMaxDynamicSharedMemorySize, S1_128);
    cudaFuncSetAttribute(c3x3f<0>,        cudaFuncAttributeMaxDynamicSharedMemorySize, S3);
    cudaFuncSetAttribute(c3x3f<1>,        cudaFuncAttributeMaxDynamicSharedMemorySize, S3);

    prep_all<<<71, 256>>>(cv1_w, m0_cv1_w, m0_cv2_w, m1_cv1_w, m1_cv2_w,
                          cv3_w, cv2p_w, cv4_w,
                          cv1_bn, m0_cv1_bn, m0_cv2_bn, m1_cv1_bn, m1_cv2_bn,
                          bn_cat, cv4_bn, wh, wl, sb, th, tl, uh, ul);

    // cv2p + cv1 + fused m0_cv1: x -> b planes, y planes, t padded
    cv1f2<<<3200,512,SCF>>>(x,
                            wh+WO_CV2P, wl+WO_CV2P,
                            wh+WO_CV1,  wl+WO_CV1,
                            wh+WO_M0A,  wl+WO_M0A,
                            sb+SB_CATB, sb+SB_CV1, sb+SB_M0A,
                            bh, bl, yh, yl, th, tl);
    // bottleneck0 3x3 + residual -> y ; fused m1_cv1(y) -> u (padded)
    c3x3f<0><<<3200,512,S3>>>(th, tl, wh+WO_M0B, wl+WO_M0B,
                              wh+WO_M1A, wl+WO_M1A,
                              sb+SB_M0B, sb+SB_M1A, yh, yl, uh, ul);
    // bottleneck1 3x3 (reads u) + residual -> y ; fused cv3(y)+bn_cat[0:64]+leaky -> a
    c3x3f<1><<<3200,512,S3>>>(uh, ul, wh+WO_M1B, wl+WO_M1B,
                              wh+WO_CV3, wl+WO_CV3,
                              sb+SB_M1B, sb+SB_CATA, yh, yl, ah, al);
    // cv4: concat(a,b) 128->128 BN+hswish -> out fp32
    g1x1<128,2,2,0><<<dim3(GP,2),512,S1_128>>>(0, ah,al, bh,bl, wh+WO_CV4, wl+WO_CV4, sb+SB_CV4, 0, 0, out, NT);
}

// round 16
// speedup vs baseline: 1.5639x; 1.0765x over previous
#include <cuda_runtime.h>
#include <cuda_fp16.h>
#include <cstdint>

typedef unsigned short u16;
typedef unsigned int   u32;

constexpr int STR = 72;   // smem row stride in halves (conflict-free for ldsm)

// ─── helpers ───────────────────────────────────────────────────────────────
__device__ __forceinline__ u32 smem_u32(const void* p){
    u32 a;
    asm("{ .reg .u64 t; cvta.to.shared.u64 t, %1; cvt.u32.u64 %0, t; }"
        : "=r"(a) : "l"(p));
    return a;
}
__device__ __forceinline__ void ldsm4(u32 addr, u32& r0, u32& r1, u32& r2, u32& r3){
    asm volatile("ldmatrix.sync.aligned.m8n8.x4.shared.b16 {%0,%1,%2,%3}, [%4];"
        : "=r"(r0), "=r"(r1), "=r"(r2), "=r"(r3) : "r"(addr));
}
__device__ __forceinline__ void mma_(float* c, const u32* a, u32 b0, u32 b1){
    asm volatile("mma.sync.aligned.m16n8k16.row.col.f32.f16.f16.f32 "
        "{%0,%1,%2,%3},{%4,%5,%6,%7},{%8,%9},{%0,%1,%2,%3};"
        : "+f"(c[0]), "+f"(c[1]), "+f"(c[2]), "+f"(c[3])
        : "r"(a[0]), "r"(a[1]), "r"(a[2]), "r"(a[3]), "r"(b0), "r"(b1));
}
__device__ __forceinline__ void mma_h(u32* c, const u32* a, u32 b0, u32 b1){
    asm volatile("mma.sync.aligned.m16n8k16.row.col.f16.f16.f16.f16 "
        "{%0,%1},{%2,%3,%4,%5},{%6,%7},{%0,%1};"
        : "+r"(c[0]), "+r"(c[1])
        : "r"(a[0]), "r"(a[1]), "r"(a[2]), "r"(a[3]), "r"(b0), "r"(b1));
}
#define CPA16(dst, src) \
    asm volatile("cp.async.cg.shared.global [%0], [%1], 16;" :: "r"(dst), "l"(src))
#define CPA_COMMIT()  asm volatile("cp.async.commit_group;" ::: "memory")
#define CPA_WAIT0()   asm volatile("cp.async.wait_group 0;" ::: "memory")
#define CPA_WAIT_G1() asm volatile("cp.async.wait_group 1;" ::: "memory")
#define CPA_WAIT() do { CPA_COMMIT(); CPA_WAIT0(); } while(0)

__device__ __forceinline__ void sp2(float a, float b, u32& H, u32& L){
    __half2 h = __floats2half2_rn(a, b);
    float2 hf = __half22float2(h);
    __half2 l = __floats2half2_rn(a - hf.x, b - hf.y);
    H = *(u32*)&h; L = *(u32*)&l;
}
__device__ __forceinline__ float2 dec(u32 v){
    __half2 h = *(__half2*)&v; return __half22float2(h);
}
__device__ __forceinline__ float hswish(float x){
    return x * __saturatef((x + 3.0f) * (1.0f / 6.0f));
}

// fragment loads: A = 8 regs (hi 4 + lo 4), B = 16 regs (hi 8 + lo 8) over N=32
__device__ __forceinline__ void ldA8(u32* A, u32 aH, u32 aL, int kc){
    ldsm4(aH + kc*32, A[0], A[1], A[2], A[3]);
    ldsm4(aL + kc*32, A[4], A[5], A[6], A[7]);
}
__device__ __forceinline__ void ldB16n(u32* B, u32 bH, u32 bL, int kc){
    const u32 off = kc*32;
    ldsm4(bH + off,            B[0],  B[1],  B[2],  B[3]);
    ldsm4(bH + off + 16*STR*2, B[4],  B[5],  B[6],  B[7]);
    ldsm4(bL + off,            B[8],  B[9],  B[10], B[11]);
    ldsm4(bL + off + 16*STR*2, B[12], B[13], B[14], B[15]);
}
__device__ __forceinline__ void ldB8n(u32* B, u32 bH, int kc){
    const u32 off = kc*32;
    ldsm4(bH + off,            B[0],  B[1],  B[2],  B[3]);
    ldsm4(bH + off + 16*STR*2, B[4],  B[5],  B[6],  B[7]);
}
__device__ __forceinline__ void mma12n(float accF[4][4], u32 accH[4][2],
                                       const u32* A, const u32* B){
    #pragma unroll
    for (int g = 0; g < 4; g++)
        mma_(accF[g], A, B[2*g], B[2*g+1]);
    #pragma unroll
    for (int g = 0; g < 4; g++)
        mma_h(accH[g], A+4, B[2*g], B[2*g+1]);
    #pragma unroll
    for (int g = 0; g < 4; g++)
        mma_h(accH[g], A, B[8+2*g], B[8+2*g+1]);
}
__device__ __forceinline__ void mma8n(float accF[4][4], u32 accH[4][2],
                                      const u32* A, const u32* B){
    #pragma unroll
    for (int g = 0; g < 4; g++)
        mma_(accF[g], A, B[2*g], B[2*g+1]);
    #pragma unroll
    for (int g = 0; g < 4; g++)
        mma_h(accH[g], A+4, B[2*g], B[2*g+1]);
}
// 3-term block (1x1 layers): full accuracy
__device__ __forceinline__ void gemm_block_n(float accF[4][4], u32 accH[4][2],
                                             u32 aH, u32 aL, u32 bH, u32 bL){
    u32 Ab[2][8], Bb[2][16];
    ldA8(Ab[0], aH, aL, 0);
    ldB16n(Bb[0], bH, bL, 0);
    #pragma unroll
    for (int kc = 0; kc < 4; kc++) {
        if (kc < 3) {
            ldA8(Ab[(kc+1) & 1], aH, aL, kc+1);
            ldB16n(Bb[(kc+1) & 1], bH, bL, kc+1);
        }
        mma12n(accF, accH, Ab[kc & 1], Bb[kc & 1]);
    }
}
// 2-term block (3x3 tap loops): drops Xh*Wl correction; half the B traffic
__device__ __forceinline__ void gemm_block_n2(float accF[4][4], u32 accH[4][2],
                                              u32 aH, u32 aL, u32 bH){
    u32 Ab[2][8], Bb[2][8];
    ldA8(Ab[0], aH, aL, 0);
    ldB8n(Bb[0], bH, 0);
    #pragma unroll
    for (int kc = 0; kc < 4; kc++) {
        if (kc < 3) {
            ldA8(Ab[(kc+1) & 1], aH, aL, kc+1);
            ldB8n(Bb[(kc+1) & 1], bH, kc+1);
        }
        mma8n(accF, accH, Ab[kc & 1], Bb[kc & 1]);
    }
}

// ─── global scratch ────────────────────────────────────────────────────────
#define PXT 409600
#define TPAD (16*162*162)
#define WTOT 118784

__device__ __align__(16) u16 g_yh[PXT*64], g_yl[PXT*64];
__device__ __align__(16) u16 g_ah[PXT*64], g_al[PXT*64];
__device__ __align__(16) u16 g_bh[PXT*64], g_bl[PXT*64];
__device__ __align__(16) u16 g_th[TPAD*64], g_tl[TPAD*64];
__device__ __align__(16) u16 g_uh[TPAD*64], g_ul[TPAD*64];
__device__ __align__(16) u16 g_wh[WTOT], g_wl[WTOT];
__device__ float g_sb[1280];

#define WO_CV1   0
#define WO_M0A   8192
#define WO_M0B   12288
#define WO_M1A   49152
#define WO_M1B   53248
#define WO_CV3   90112
#define WO_CV2P  94208
#define WO_CV4   102400

#define SB_CV1   0
#define SB_M0A   128
#define SB_M0B   256
#define SB_M1A   384
#define SB_M1B   512
#define SB_CATA  640
#define SB_CATB  768
#define SB_CV4   896

// ─── single fused prep kernel ──────────────────────────────────────────────
__global__ void prep_all(
    const float* cv1w, const float* m0a, const float* m0b,
    const float* m1a,  const float* m1b, const float* cv3,
    const float* cv2p, const float* cv4,
    const float* c1bn, const float* a0bn, const float* b0bn,
    const float* a1bn, const float* b1bn, const float* catbn, const float* c4bn,
    u16* wh, u16* wl, float* sb, u16* th, u16* tl, u16* uh, u16* ul)
{
    const int bid = blockIdx.x, tid = threadIdx.x;
    if (bid < 29) {
        const float* src; u16 *dh, *dl; int CIN = 64, COUT = 64, b0;
        if      (bid < 2)  { src = cv1w; dh = wh+WO_CV1;  dl = wl+WO_CV1;  CIN = 128; b0 = 0; }
        else if (bid < 3)  { src = m0a;  dh = wh+WO_M0A;  dl = wl+WO_M0A;  b0 = 2; }
        else if (bid < 12) { src = m0b;  dh = wh+WO_M0B;  dl = wl+WO_M0B;  b0 = 3; }
        else if (bid < 13) { src = m1a;  dh = wh+WO_M1A;  dl = wl+WO_M1A;  b0 = 12; }
        else if (bid < 22) { src = m1b;  dh = wh+WO_M1B;  dl = wl+WO_M1B;  b0 = 13; }
        else if (bid < 23) { src = cv3;  dh = wh+WO_CV3;  dl = wl+WO_CV3;  b0 = 22; }
        else if (bid < 25) { src = cv2p; dh = wh+WO_CV2P; dl = wl+WO_CV2P; CIN = 128; b0 = 23; }
        else               { src = cv4;  dh = wh+WO_CV4;  dl = wl+WO_CV4;  CIN = 128; COUT = 128; b0 = 25; }
        const int base = (bid - b0) * 4096;
        const int per = CIN * COUT;
        #pragma unroll 4
        for (int j = 0; j < 16; j++) {
            int e = base + tid + j * 256;
            int tap = e / per, r = e - tap * per;
            int ci = r / COUT, co = r - ci * COUT;
            float w = src[e];
            __half h = __float2half_rn(w);
            __half l = __float2half_rn(w - __half2float(h));
            int d = tap * per + co * CIN + ci;
            dh[d] = *(u16*)&h; dl[d] = *(u16*)&l;
        }
    } else if (bid == 29) {
        auto seg = [&](int off, const float* s, int C, int stride, int choff){
            for (int c = tid; c < C; c += 256) {
                float g = s[choff + c], b = s[stride + choff + c];
                float m = s[2*stride + choff + c], v = s[3*stride + choff + c];
                float sc = g * rsqrtf(v + 1e-3f);
                sb[off + c] = sc; sb[off + C + c] = b - m * sc;
            }
        };
        seg(SB_CV1,  c1bn, 64, 64, 0);
        seg(SB_M0A,  a0bn, 64, 64, 0);
        seg(SB_M0B,  b0bn, 64, 64, 0);
        seg(SB_M1A,  a1bn, 64, 64, 0);
        seg(SB_M1B,  b1bn, 64, 64, 0);
        seg(SB_CATA, catbn, 64, 128, 0);
        seg(SB_CATB, catbn, 64, 128, 64);
        seg(SB_CV4,       c4bn, 64, 128, 0);
        seg(SB_CV4 + 128, c4bn, 64, 128, 64);
    } else {
        int i = (bid - 30) * 256 + tid;
        if (i >= 16 * 644) return;
        int img = i / 644, r = i - img * 644;
        int y, x;
        if      (r < 162) { y = 0;   x = r; }
        else if (r < 324) { y = 161; x = r - 162; }
        else if (r < 484) { x = 0;   y = r - 324 + 1; }
        else              { x = 161; y = r - 484 + 1; }
        long long q = (((long long)img * 162 + y) * 162 + x) * 64;
        uint4 z = make_uint4(0,0,0,0);
        #pragma unroll
        for (int c = 0; c < 8; c++) {
            *(uint4*)(th + q + c*8) = z; *(uint4*)(tl + q + c*8) = z;
            *(uint4*)(uh + q + c*8) = z; *(uint4*)(ul + q + c*8) = z;
        }
    }
}

// ─── 1x1 conv GEMM (HMMA): persistent, 512 thr (cv4 only now) ──────────────
template<int CIN, int SRC, int OUTM, int ACT>
__global__ void __launch_bounds__(512, 2) g1x1(
    const float* __restrict__ xf,
    const u16* __restrict__ pah, const u16* __restrict__ pal,
    const u16* __restrict__ pbh, const u16* __restrict__ pbl,
    const u16* __restrict__ wh,  const u16* __restrict__ wl,
    const float* __restrict__ sb,
    u16* __restrict__ oh, u16* __restrict__ ol, float* __restrict__ of,
    int ntiles)
{
    constexpr int KB  = CIN / 64;
    constexpr int APL = 128 * STR * 2;
    constexpr int WPL = 64 * STR * 2;

    extern __shared__ char sm[];
    float* sbs  = (float*)sm;
    char* Wbase = sm + 512;
    char* Abase = Wbase + KB * 2 * WPL;

    const int tid = threadIdx.x;
    const int cy  = blockIdx.y;
    const u16* whp = wh + cy * 64 * CIN;
    const u16* wlp = wl + cy * 64 * CIN;

    for (int c = tid; c < 128; c += 512) sbs[c] = sb[cy * 128 + c];

    const u32 WA = smem_u32(Wbase), AA = smem_u32(Abase);

    #pragma unroll
    for (int kb = 0; kb < KB; kb++)
        for (int i = tid; i < 512; i += 512) {
            int n = i >> 3, c8 = i & 7;
            u32 off = kb * 2 * WPL + (n * STR + c8 * 8) * 2;
            CPA16(WA + off,       whp + n * CIN + kb * 64 + c8 * 8);
            CPA16(WA + off + WPL, wlp + n * CIN + kb * 64 + c8 * 8);
        }

    auto stageA = [&](int t, int kb, int buf){
        long long p0 = (long long)t * 128;
        const u32 AH = AA + buf * 2 * APL;
        for (int i = tid; i < 1024; i += 512) {
            int row = i >> 3, c8 = i & 7;
            u32 off = (row * STR + c8 * 8) * 2;
            const u16* shp = kb ? pbh : pah;
            const u16* slp = kb ? pbl : pal;
            long long so = (p0 + row) * 64 + c8 * 8;
            CPA16(AH + off,       shp + so);
            CPA16(AH + APL + off, slp + so);
        }
    };

    const int warp = tid >> 5, lane = tid & 31;
    const int mrow = warp >> 1;
    const int nh   = warp & 1;
    const int arow  = 16 * mrow + (lane & 7) + ((lane & 8) ? 8 : 0);
    const int akoff = (lane & 16) ? 8 : 0;
    const u32 aOff = (arow * STR + akoff) * 2;
    const int brow  = (lane & 7) + ((lane & 16) ? 8 : 0);
    const int bkoff = (lane & 8) ? 8 : 0;
    const u32 bOff = ((nh * 32 + brow) * STR + bkoff) * 2;

    const int gr = lane >> 2, c2l = (lane & 3) * 2;
    const int coff = cy * 64 + nh * 32;

    const int t0 = blockIdx.x;
    if (t0 < ntiles) stageA(t0, 0, 0);
    CPA_COMMIT();

    int buf = 0;
    float accF[4][4];
    u32 accH[4][2];

    for (int t = t0; t < ntiles; t += gridDim.x) {
        #pragma unroll
        for (int n = 0; n < 4; n++) {
            #pragma unroll
            for (int j = 0; j < 4; j++) accF[n][j] = 0.f;
            accH[n][0] = 0u; accH[n][1] = 0u;
        }

        #pragma unroll
        for (int kb = 0; kb < KB; kb++) {
            int nt = t, nkb = kb + 1;
            if (nkb == KB) { nkb = 0; nt = t + gridDim.x; }
            const bool hn = (nt < ntiles);
            if (hn) stageA(nt, nkb, buf ^ 1);
            CPA_COMMIT();
            if (hn) { CPA_WAIT_G1(); } else { CPA_WAIT0(); }
            __syncthreads();

            const u32 aH = AA + buf * 2 * APL + aOff;
            const u32 aL = aH + APL;
            const u32 bH = WA + kb * 2 * WPL + bOff;
            const u32 bL = bH + WPL;

            gemm_block_n(accF, accH, aH, aL, bH, bL);

            if (kb == KB - 1) {
                #pragma unroll
                for (int rs = 0; rs < 2; rs++) {
                    int row = 16*mrow + 8*rs + gr;
                    long long p = (long long)t * 128 + row;
                    #pragma unroll
                    for (int nb = 0; nb < 4; nb++) {
                        int c = nh * 32 + 8*nb + c2l;
                        float2 hc = dec(accH[nb][rs]);
                        float v0 = sbs[c]     * (accF[nb][2*rs]     + hc.x) + sbs[64 + c];
                        float v1 = sbs[c + 1] * (accF[nb][2*rs + 1] + hc.y) + sbs[64 + c + 1];
                        if (ACT == 0) { v0 = hswish(v0); v1 = hswish(v1); }
                        else { v0 = v0 >= 0.f ? v0 : 0.1f*v0; v1 = v1 >= 0.f ? v1 : 0.1f*v1; }
                        *(float2*)(of + p * 128 + coff + 8*nb + c2l) = make_float2(v0, v1);
                    }
                }
            }
            __syncthreads();
            buf ^= 1;
        }
    }
}

// ─── cv1f2: cv2p(x)->b ; cv1(x)->y ; fused m0_cv1(y)->t padded ─────────────
__global__ void __launch_bounds__(512, 2) cv1f2(
    const float* __restrict__ xf,
    const u16* __restrict__ w2h, const u16* __restrict__ w2l,
    const u16* __restrict__ wh,  const u16* __restrict__ wl,
    const u16* __restrict__ w1h, const u16* __restrict__ w1l,
    const float* __restrict__ sb_b, const float* __restrict__ sb_y,
    const float* __restrict__ sb_t,
    u16* __restrict__ bh, u16* __restrict__ bl,
    u16* __restrict__ yh, u16* __restrict__ yl,
    u16* __restrict__ o2h, u16* __restrict__ o2l)
{
    constexpr int APL = 128 * STR * 2;
    constexpr int WPL = 64 * STR * 2;

    extern __shared__ char sm[];
    float* sbs = (float*)sm;
    char* Ab = sm + 1536;
    char* Wb = Ab + 4 * APL;

    const int tid = threadIdx.x;
    const long long p0 = (long long)blockIdx.x * 128;

    for (int c = tid; c < 128; c += 512) {
        sbs[c] = sb_b[c]; sbs[128 + c] = sb_y[c]; sbs[256 + c] = sb_t[c];
    }

    const u32 AbA = smem_u32(Ab), WbA = smem_u32(Wb);

    for (int i = tid; i < 1024; i += 512) {
        int kb = i >> 9, r = i & 511;
        int n = r >> 3, c8 = r & 7;
        u32 off = kb * 2 * WPL + (n * STR + c8 * 8) * 2;
        CPA16(WbA + off,       w2h + n * 128 + kb * 64 + c8 * 8);
        CPA16(WbA + off + WPL, w2l + n * 128 + kb * 64 + c8 * 8);
    }
    CPA_COMMIT();
    for (int i = tid; i < 2048; i += 512) {
        int row = i >> 4, c16 = i & 15;
        int kb = c16 >> 3, c8 = c16 & 7;
        const float* g = xf + (p0 + row) * 128 + c16 * 8;
        float4 f1 = *(const float4*)g, f2 = *(const float4*)(g + 4);
        uint4 H, L;
        sp2(f1.x, f1.y, H.x, L.x); sp2(f1.z, f1.w, H.y, L.y);
        sp2(f2.x, f2.y, H.z, L.z); sp2(f2.z, f2.w, H.w, L.w);
        u32 off = kb * 2 * APL + (row * STR + c8 * 8) * 2;
        *(uint4*)(Ab + off) = H; *(uint4*)(Ab + APL + off) = L;
    }
    CPA_WAIT0();
    __syncthreads();

    const int warp = tid >> 5, lane = tid & 31;
    const int mrow = warp >> 1;
    const int nh   = warp & 1;
    const int arow  = 16 * mrow + (lane & 7) + ((lane & 8) ? 8 : 0);
    const int akoff = (lane & 16) ? 8 : 0;
    const u32 aOff = (arow * STR + akoff) * 2;
    const int brow  = (lane & 7) + ((lane & 16) ? 8 : 0);
    const int bkoff = (lane & 8) ? 8 : 0;
    const u32 bOff = ((nh * 32 + brow) * STR + bkoff) * 2;
    const int gr = lane >> 2, c2l = (lane & 3) * 2;

    float accF[4][4];
    u32 accH[4][2];

    // phase 1: cv2p -> b (leaky)
    #pragma unroll
    for (int n = 0; n < 4; n++) {
        #pragma unroll
        for (int j = 0; j < 4; j++) accF[n][j] = 0.f;
        accH[n][0] = 0u; accH[n][1] = 0u;
    }
    #pragma unroll
    for (int kb = 0; kb < 2; kb++)
        gemm_block_n(accF, accH,
                     AbA + kb * 2 * APL + aOff, AbA + kb * 2 * APL + APL + aOff,
                     WbA + kb * 2 * WPL + bOff, WbA + kb * 2 * WPL + WPL + bOff);

    #pragma unroll
    for (int rs = 0; rs < 2; rs++) {
        long long p = p0 + 16 * mrow + 8*rs + gr;
        #pragma unroll
        for (int nb = 0; nb < 4; nb++) {
            int c = nh * 32 + 8*nb + c2l;
            float2 hc = dec(accH[nb][rs]);
            float v0 = sbs[c]     * (accF[nb][2*rs]     + hc.x) + sbs[64 + c];
            float v1 = sbs[c + 1] * (accF[nb][2*rs + 1] + hc.y) + sbs[64 + c + 1];
            v0 = v0 >= 0.f ? v0 : 0.1f*v0; v1 = v1 >= 0.f ? v1 : 0.1f*v1;
            u32 H, L; sp2(v0, v1, H, L);
            *(u32*)(bh + p * 64 + c) = H;
            *(u32*)(bl + p * 64 + c) = L;
        }
    }
    __syncthreads();

    // phase 2: cv1 -> y (hswish); stash y into Ab kb0
    for (int i = tid; i < 1024; i += 512) {
        int kb = i >> 9, r = i & 511;
        int n = r >> 3, c8 = r & 7;
        u32 off = kb * 2 * WPL + (n * STR + c8 * 8) * 2;
        CPA16(WbA + off,       wh + n * 128 + kb * 64 + c8 * 8);
        CPA16(WbA + off + WPL, wl + n * 128 + kb * 64 + c8 * 8);
    }
    CPA_WAIT();
    __syncthreads();

    #pragma unroll
    for (int n = 0; n < 4; n++) {
        #pragma unroll
        for (int j = 0; j < 4; j++) accF[n][j] = 0.f;
        accH[n][0] = 0u; accH[n][1] = 0u;
    }
    #pragma unroll
    for (int kb = 0; kb < 2; kb++)
        gemm_block_n(accF, accH,
                     AbA + kb * 2 * APL + aOff, AbA + kb * 2 * APL + APL + aOff,
                     WbA + kb * 2 * WPL + bOff, WbA + kb * 2 * WPL + WPL + bOff);
    __syncthreads();

    #pragma unroll
    for (int rs = 0; rs < 2; rs++) {
        int px = 16 * mrow + 8*rs + gr;
        long long p = p0 + px;
        #pragma unroll
        for (int nb = 0; nb < 4; nb++) {
            int c = nh * 32 + 8*nb + c2l;
            float2 hc = dec(accH[nb][rs]);
            float v0 = sbs[128 + c]     * (accF[nb][2*rs]     + hc.x) + sbs[192 + c];
            float v1 = sbs[128 + c + 1] * (accF[nb][2*rs + 1] + hc.y) + sbs[192 + c + 1];
            v0 = hswish(v0); v1 = hswish(v1);
            u32 H, L; sp2(v0, v1, H, L);
            *(u32*)(yh + p * 64 + c) = H;
            *(u32*)(yl + p * 64 + c) = L;
            u32 off = (px * STR + c) * 2;
            *(u32*)(Ab + off)       = H;
            *(u32*)(Ab + APL + off) = L;
        }
    }

    // phase 3: m0_cv1(y) -> t padded (hswish)
    for (int i = tid; i < 512; i += 512) {
        int n = i >> 3, c8 = i & 7;
        u32 off = (n * STR + c8 * 8) * 2;
        CPA16(WbA + off,       w1h + n*64 + c8*8);
        CPA16(WbA + WPL + off, w1l + n*64 + c8*8);
    }
    CPA_WAIT();
    __syncthreads();

    #pragma unroll
    for (int n = 0; n < 4; n++) {
        #pragma unroll
        for (int j = 0; j < 4; j++) accF[n][j] = 0.f;
        accH[n][0] = 0u; accH[n][1] = 0u;
    }
    gemm_block_n(accF, accH, AbA + aOff, AbA + APL + aOff,
                 WbA + bOff, WbA + WPL + bOff);

    #pragma unroll
    for (int rs = 0; rs < 2; rs++) {
        int px = 16 * mrow + 8*rs + gr;
        long long p = p0 + px;
        int pi = (int)p;
        int img = pi / 25600, r = pi - img * 25600;
        int y = r / 160, x = r - y * 160;
        long long q2 = (((long long)img * 162 + y + 1) * 162 + (x + 1)) * 64;
        #pragma unroll
        for (int nb = 0; nb < 4; nb++) {
            int c = nh * 32 + 8*nb + c2l;
            float2 hc = dec(accH[nb][rs]);
            float v0 = sbs[256 + c]     * (accF[nb][2*rs]     + hc.x) + sbs[320 + c];
            float v1 = sbs[256 + c + 1] * (accF[nb][2*rs + 1] + hc.y) + sbs[320 + c + 1];
            v0 = hswish(v0); v1 = hswish(v1);
            u32 H, L; sp2(v0, v1, H, L);
            *(u32*)(o2h + q2 + c) = H;
            *(u32*)(o2l + q2 + c) = L;
        }
    }
}

// ─── fused 3x3 conv (2-term taps) + tile-local 1x1 conv (3-term) ───────────
template<int DST>
__global__ void __launch_bounds__(512, 2) c3x3f(
    const u16* __restrict__ th, const u16* __restrict__ tl,
    const u16* __restrict__ wh,                              // tap hi only
    const u16* __restrict__ w1h, const u16* __restrict__ w1l,
    const float* __restrict__ sb, const float* __restrict__ sb2,
    u16* __restrict__ yh, u16* __restrict__ yl,
    u16* __restrict__ o2h, u16* __restrict__ o2l)
{
    constexpr int APL = 180 * STR * 2;
    constexpr int WPL = 64 * STR * 2;
    constexpr int YPL = 128 * STR * 2;

    extern __shared__ char sm[];
    float* sbs = (float*)sm;
    char* Ah = sm + 1024;
    char* Al = Ah + APL;
    char* Wb = Al + APL;                 // taps: [buf] hi-only; later y stash (2 YPL)

    const int tid = threadIdx.x;
    const int blk = blockIdx.x;
    const int img = blk / 200, t = blk - img * 200;
    const int ty = t / 10, tx = t - ty * 10;
    const int y0 = ty * 8, x0 = tx * 16;

    for (int c = tid; c < 128; c += 512) { sbs[c] = sb[c]; sbs[128 + c] = sb2[c]; }

    const u32 AhA = smem_u32(Ah), AlA = smem_u32(Al), WbA = smem_u32(Wb);

    for (int i = tid; i < 1440; i += 512) {
        int hr = i >> 3, c8 = i & 7;
        int hy = hr / 18, hx = hr - hy * 18;
        long long s = (((long long)img * 162 + y0 + hy) * 162 + (x0 + hx)) * 64 + c8 * 8;
        u32 off = (hr * STR + c8 * 8) * 2;
        CPA16(AhA + off, th + s);
        CPA16(AlA + off, tl + s);
    }
    for (int i = tid; i < 512; i += 512) {
        int n = i >> 3, c8 = i & 7;
        u32 off = (n * STR + c8 * 8) * 2;
        CPA16(WbA + off, wh + n*64 + c8*8);
    }
    CPA_WAIT();
    __syncthreads();

    const int warp = tid >> 5, lane = tid & 31;
    const int row = warp >> 1;
    const int nh  = warp & 1;
    const int acol  = lane & 15;
    const int akoff = (lane & 16) ? 8 : 0;
    const int brow  = (lane & 7) + ((lane & 16) ? 8 : 0);
    const int bkoff = (lane & 8) ? 8 : 0;
    const u32 bOff = ((nh * 32 + brow) * STR + bkoff) * 2;

    float accF[4][4];
    u32 accH[4][2];
    #pragma unroll
    for (int n = 0; n < 4; n++) {
        #pragma unroll
        for (int j = 0; j < 4; j++) accF[n][j] = 0.f;
        accH[n][0] = 0u; accH[n][1] = 0u;
    }

    for (int tap = 0; tap < 9; tap++) {
        const int buf = tap & 1;
        if (tap < 8) {
            const u16* sh = wh + (tap+1)*4096;
            const u32 WA = WbA + (buf^1)*WPL;
            for (int i = tid; i < 512; i += 512) {
                int n = i >> 3, c8 = i & 7;
                u32 off = (n * STR + c8 * 8) * 2;
                CPA16(WA + off, sh + n*64 + c8*8);
            }
            CPA_COMMIT();
        }
        const int kh = tap / 3, kw = tap - kh * 3;
        const int hr = (row + kh) * 18 + acol + kw;
        const u32 aH = AhA + (hr * STR + akoff) * 2;
        const u32 aL = AlA + (hr * STR + akoff) * 2;
        const u32 bH = WbA + buf*WPL + bOff;

        gemm_block_n2(accF, accH, aH, aL, bH);

        if (tap < 8) {
            CPA_WAIT0();
            __syncthreads();
        }
    }
    __syncthreads();

    const int gr = lane >> 2, c2l = (lane & 3) * 2;
    #pragma unroll
    for (int rs = 0; rs < 2; rs++) {
        int xx = 8*rs + gr;
        int px = row * 16 + xx;
        long long q = ((long long)img * 25600 + (y0 + row) * 160 + (x0 + xx)) * 64;
        #pragma unroll
        for (int nb = 0; nb < 4; nb++) {
            int c = nh * 32 + 8*nb + c2l;
            float2 yv0 = dec(*(const u32*)(yh + q + c));
            float2 yv1 = dec(*(const u32*)(yl + q + c));
            float2 hc  = dec(accH[nb][rs]);
            float v0 = sbs[c]     * (accF[nb][2*rs]     + hc.x) + sbs[64 + c];
            float v1 = sbs[c + 1] * (accF[nb][2*rs + 1] + hc.y) + sbs[64 + c + 1];
            v0 = hswish(v0) + yv0.x + yv1.x;
            v1 = hswish(v1) + yv0.y + yv1.y;
            u32 H, L; sp2(v0, v1, H, L);
            if (DST == 0) {
                *(u32*)(yh + q + c) = H;
                *(u32*)(yl + q + c) = L;
            }
            u32 off = (px * STR + c) * 2;
            *(u32*)(Wb + off)       = H;
            *(u32*)(Wb + YPL + off) = L;
        }
    }

    for (int i = tid; i < 512; i += 512) {
        int n = i >> 3, c8 = i & 7;
        u32 off = (n * STR + c8 * 8) * 2;
        CPA16(AhA + off,       w1h + n*64 + c8*8);
        CPA16(AhA + WPL + off, w1l + n*64 + c8*8);
    }
    CPA_WAIT();
    __syncthreads();

    {
        const int mblk = warp >> 1;
        const int arow2 = 16 * mblk + (lane & 7) + ((lane & 8) ? 8 : 0);
        const u32 aOff2 = (arow2 * STR + akoff) * 2;
        #pragma unroll
        for (int n = 0; n < 4; n++) {
            #pragma unroll
            for (int j = 0; j < 4; j++) accF[n][j] = 0.f;
            accH[n][0] = 0u; accH[n][1] = 0u;
        }
        gemm_block_n(accF, accH, WbA + aOff2, WbA + YPL + aOff2,
                     AhA + bOff, AhA + WPL + bOff);

        #pragma unroll
        for (int rs = 0; rs < 2; rs++) {
            int px = 16 * mblk + 8*rs + gr;
            int yy = px >> 4, xx = px & 15;
            long long q2;
            if (DST == 0)
                q2 = (((long long)img * 162 + y0 + yy + 1) * 162 + (x0 + xx + 1)) * 64;
            else
                q2 = ((long long)img * 25600 + (y0 + yy) * 160 + (x0 + xx)) * 64;
            #pragma unroll
            for (int nb = 0; nb < 4; nb++) {
                int c = nh * 32 + 8*nb + c2l;
                float2 hc = dec(accH[nb][rs]);
                float v0 = sbs[128 + c]     * (accF[nb][2*rs]     + hc.x) + sbs[192 + c];
                float v1 = sbs[128 + c + 1] * (accF[nb][2*rs + 1] + hc.y) + sbs[192 + c + 1];
                if (DST == 0) { v0 = hswish(v0); v1 = hswish(v1); }
                else { v0 = v0 >= 0.f ? v0 : 0.1f*v0; v1 = v1 >= 0.f ? v1 : 0.1f*v1; }
                u32 H, L; sp2(v0, v1, H, L);
                *(u32*)(o2h + q2 + c) = H;
                *(u32*)(o2l + q2 + c) = L;
            }
        }
    }
}

// ─── host ──────────────────────────────────────────────────────────────────
extern "C" void kernel_launch(void* const* d_in, const int* in_sizes, int n_in,
                              void* d_out, int out_size)
{
    (void)in_sizes; (void)n_in; (void)out_size;
    const float* x         = (const float*)d_in[0];
    const float* cv1_w     = (const float*)d_in[1];
    const float* cv1_bn    = (const float*)d_in[2];
    const float* m0_cv1_w  = (const float*)d_in[3];
    const float* m0_cv1_bn = (const float*)d_in[4];
    const float* m0_cv2_w  = (const float*)d_in[5];
    const float* m0_cv2_bn = (const float*)d_in[6];
    const float* m1_cv1_w  = (const float*)d_in[7];
    const float* m1_cv1_bn = (const float*)d_in[8];
    const float* m1_cv2_w  = (const float*)d_in[9];
    const float* m1_cv2_bn = (const float*)d_in[10];
    const float* cv3_w     = (const float*)d_in[11];
    const float* cv2p_w    = (const float*)d_in[12];
    const float* bn_cat    = (const float*)d_in[13];
    const float* cv4_w     = (const float*)d_in[14];
    const float* cv4_bn    = (const float*)d_in[15];
    float* out = (float*)d_out;

    u16 *yh, *yl, *ah, *al, *bh, *bl, *th, *tl, *uh, *ul, *wh, *wl;
    float* sb;
    cudaGetSymbolAddress((void**)&yh, g_yh); cudaGetSymbolAddress((void**)&yl, g_yl);
    cudaGetSymbolAddress((void**)&ah, g_ah); cudaGetSymbolAddress((void**)&al, g_al);
    cudaGetSymbolAddress((void**)&bh, g_bh); cudaGetSymbolAddress((void**)&bl, g_bl);
    cudaGetSymbolAddress((void**)&th, g_th); cudaGetSymbolAddress((void**)&tl, g_tl);
    cudaGetSymbolAddress((void**)&uh, g_uh); cudaGetSymbolAddress((void**)&ul, g_ul);
    cudaGetSymbolAddress((void**)&wh, g_wh); cudaGetSymbolAddress((void**)&wl, g_wl);
    cudaGetSymbolAddress((void**)&sb, g_sb);

    constexpr int S1_128 = 512 + 2*2*9216 + 2*2*18432;     // 111104
    constexpr int SCF    = 1536 + 4*18432 + 4*9216;        // 112128
    constexpr int S3     = 1024 + 2*25920 + 4*9216;        // 89728
    constexpr int NT = 3200;
    constexpr int GP = 304;

    cudaFuncSetAttribute(cv1f2,           cudaFuncAttributeMaxDynamicSharedMemorySize, SCF);
    cudaFuncSetAttribute(g1x1<128,2,2,0>, cudaFuncAttributeMaxDynamicSharedMemorySize, S1_128);
    cudaFuncSetAttribute(c3x3f<0>,        cudaFuncAttributeMaxDynamicSharedMemorySize, S3);
    cudaFuncSetAttribute(c3x3f<1>,        cudaFuncAttributeMaxDynamicSharedMemorySize, S3);

    prep_all<<<71, 256>>>(cv1_w, m0_cv1_w, m0_cv2_w, m1_cv1_w, m1_cv2_w,
                          cv3_w, cv2p_w, cv4_w,
                          cv1_bn, m0_cv1_bn, m0_cv2_bn, m1_cv1_bn, m1_cv2_bn,
                          bn_cat, cv4_bn, wh, wl, sb, th, tl, uh, ul);

    // cv2p + cv1 + fused m0_cv1: x -> b planes, y planes, t padded
    cv1f2<<<3200,512,SCF>>>(x,
                            wh+WO_CV2P, wl+WO_CV2P,
                            wh+WO_CV1,  wl+WO_CV1,
                            wh+WO_M0A,  wl+WO_M0A,
                            sb+SB_CATB, sb+SB_CV1, sb+SB_M0A,
                            bh, bl, yh, yl, th, tl);
    // bottleneck0 3x3 (2-term taps) + residual -> y ; fused m1_cv1(y) -> u
    c3x3f<0><<<3200,512,S3>>>(th, tl, wh+WO_M0B,
                              wh+WO_M1A, wl+WO_M1A,
                              sb+SB_M0B, sb+SB_M1A, yh, yl, uh, ul);
    // bottleneck1 3x3 (reads u) + residual -> y ; fused cv3(y)+bn_cat+leaky -> a
    c3x3f<1><<<3200,512,S3>>>(uh, ul, wh+WO_M1B,
                              wh+WO_CV3, wl+WO_CV3,
                              sb+SB_M1B, sb+SB_CATA, yh, yl, ah, al);
    // cv4: concat(a,b) 128->128 BN+hswish -> out fp32
    g1x1<128,2,2,0><<<dim3(GP,2),512,S1_128>>>(0, ah,al, bh,bl, wh+WO_CV4, wl+WO_CV4, sb+SB_CV4, 0, 0, out, NT);
}

// round 17
// speedup vs baseline: 1.7003x; 1.0872x over previous
#include <cuda_runtime.h>
#include <cuda_fp16.h>
#include <cstdint>

typedef unsigned short u16;
typedef unsigned int   u32;

constexpr int STR = 72;   // smem row stride in halves (conflict-free for ldsm)

// ─── helpers ───────────────────────────────────────────────────────────────
__device__ __forceinline__ u32 smem_u32(const void* p){
    u32 a;
    asm("{ .reg .u64 t; cvta.to.shared.u64 t, %1; cvt.u32.u64 %0, t; }"
        : "=r"(a) : "l"(p));
    return a;
}
__device__ __forceinline__ void ldsm4(u32 addr, u32& r0, u32& r1, u32& r2, u32& r3){
    asm volatile("ldmatrix.sync.aligned.m8n8.x4.shared.b16 {%0,%1,%2,%3}, [%4];"
        : "=r"(r0), "=r"(r1), "=r"(r2), "=r"(r3) : "r"(addr));
}
__device__ __forceinline__ void mma_(float* c, const u32* a, u32 b0, u32 b1){
    asm volatile("mma.sync.aligned.m16n8k16.row.col.f32.f16.f16.f32 "
        "{%0,%1,%2,%3},{%4,%5,%6,%7},{%8,%9},{%0,%1,%2,%3};"
        : "+f"(c[0]), "+f"(c[1]), "+f"(c[2]), "+f"(c[3])
        : "r"(a[0]), "r"(a[1]), "r"(a[2]), "r"(a[3]), "r"(b0), "r"(b1));
}
__device__ __forceinline__ void mma_h(u32* c, const u32* a, u32 b0, u32 b1){
    asm volatile("mma.sync.aligned.m16n8k16.row.col.f16.f16.f16.f16 "
        "{%0,%1},{%2,%3,%4,%5},{%6,%7},{%0,%1};"
        : "+r"(c[0]), "+r"(c[1])
        : "r"(a[0]), "r"(a[1]), "r"(a[2]), "r"(a[3]), "r"(b0), "r"(b1));
}
#define CPA16(dst, src) \
    asm volatile("cp.async.cg.shared.global [%0], [%1], 16;" :: "r"(dst), "l"(src))
#define CPA_COMMIT()  asm volatile("cp.async.commit_group;" ::: "memory")
#define CPA_WAIT0()   asm volatile("cp.async.wait_group 0;" ::: "memory")
#define CPA_WAIT_G1() asm volatile("cp.async.wait_group 1;" ::: "memory")
#define CPA_WAIT() do { CPA_COMMIT(); CPA_WAIT0(); } while(0)

__device__ __forceinline__ void sp2(float a, float b, u32& H, u32& L){
    __half2 h = __floats2half2_rn(a, b);
    float2 hf = __half22float2(h);
    __half2 l = __floats2half2_rn(a - hf.x, b - hf.y);
    H = *(u32*)&h; L = *(u32*)&l;
}
__device__ __forceinline__ float2 dec(u32 v){
    __half2 h = *(__half2*)&v; return __half22float2(h);
}
__device__ __forceinline__ float hswish(float x){
    return x * __saturatef((x + 3.0f) * (1.0f / 6.0f));
}

// fragment loads: A = 8 regs (hi 4 + lo 4), B = 8 regs (hi) over N=32
__device__ __forceinline__ void ldA8(u32* A, u32 aH, u32 aL, int kc){
    ldsm4(aH + kc*32, A[0], A[1], A[2], A[3]);
    ldsm4(aL + kc*32, A[4], A[5], A[6], A[7]);
}
__device__ __forceinline__ void ldB8n(u32* B, u32 bH, int kc){
    const u32 off = kc*32;
    ldsm4(bH + off,            B[0],  B[1],  B[2],  B[3]);
    ldsm4(bH + off + 16*STR*2, B[4],  B[5],  B[6],  B[7]);
}
__device__ __forceinline__ void mma8n(float accF[4][4], u32 accH[4][2],
                                      const u32* A, const u32* B){
    #pragma unroll
    for (int g = 0; g < 4; g++)
        mma_(accF[g], A, B[2*g], B[2*g+1]);
    #pragma unroll
    for (int g = 0; g < 4; g++)
        mma_h(accH[g], A+4, B[2*g], B[2*g+1]);
}
// 2-term block: Xh*Wh (fp32 acc) + Xl*Wh (fp16 acc)
__device__ __forceinline__ void gemm_block_n2(float accF[4][4], u32 accH[4][2],
                                              u32 aH, u32 aL, u32 bH){
    u32 Ab[2][8], Bb[2][8];
    ldA8(Ab[0], aH, aL, 0);
    ldB8n(Bb[0], bH, 0);
    #pragma unroll
    for (int kc = 0; kc < 4; kc++) {
        if (kc < 3) {
            ldA8(Ab[(kc+1) & 1], aH, aL, kc+1);
            ldB8n(Bb[(kc+1) & 1], bH, kc+1);
        }
        mma8n(accF, accH, Ab[kc & 1], Bb[kc & 1]);
    }
}

// ─── global scratch ────────────────────────────────────────────────────────
#define PXT 409600
#define TPAD (16*162*162)
#define WTOT 118784

__device__ __align__(16) u16 g_yh[PXT*64], g_yl[PXT*64];
__device__ __align__(16) u16 g_ah[PXT*64], g_al[PXT*64];
__device__ __align__(16) u16 g_bh[PXT*64], g_bl[PXT*64];
__device__ __align__(16) u16 g_th[TPAD*64], g_tl[TPAD*64];
__device__ __align__(16) u16 g_uh[TPAD*64], g_ul[TPAD*64];
__device__ __align__(16) u16 g_wh[WTOT], g_wl[WTOT];
__device__ float g_sb[1280];

#define WO_CV1   0
#define WO_M0A   8192
#define WO_M0B   12288
#define WO_M1A   49152
#define WO_M1B   53248
#define WO_CV3   90112
#define WO_CV2P  94208
#define WO_CV4   102400

#define SB_CV1   0
#define SB_M0A   128
#define SB_M0B   256
#define SB_M1A   384
#define SB_M1B   512
#define SB_CATA  640
#define SB_CATB  768
#define SB_CV4   896

// ─── single fused prep kernel ──────────────────────────────────────────────
__global__ void prep_all(
    const float* cv1w, const float* m0a, const float* m0b,
    const float* m1a,  const float* m1b, const float* cv3,
    const float* cv2p, const float* cv4,
    const float* c1bn, const float* a0bn, const float* b0bn,
    const float* a1bn, const float* b1bn, const float* catbn, const float* c4bn,
    u16* wh, u16* wl, float* sb, u16* th, u16* tl, u16* uh, u16* ul)
{
    const int bid = blockIdx.x, tid = threadIdx.x;
    if (bid < 29) {
        const float* src; u16 *dh, *dl; int CIN = 64, COUT = 64, b0;
        if      (bid < 2)  { src = cv1w; dh = wh+WO_CV1;  dl = wl+WO_CV1;  CIN = 128; b0 = 0; }
        else if (bid < 3)  { src = m0a;  dh = wh+WO_M0A;  dl = wl+WO_M0A;  b0 = 2; }
        else if (bid < 12) { src = m0b;  dh = wh+WO_M0B;  dl = wl+WO_M0B;  b0 = 3; }
        else if (bid < 13) { src = m1a;  dh = wh+WO_M1A;  dl = wl+WO_M1A;  b0 = 12; }
        else if (bid < 22) { src = m1b;  dh = wh+WO_M1B;  dl = wl+WO_M1B;  b0 = 13; }
        else if (bid < 23) { src = cv3;  dh = wh+WO_CV3;  dl = wl+WO_CV3;  b0 = 22; }
        else if (bid < 25) { src = cv2p; dh = wh+WO_CV2P; dl = wl+WO_CV2P; CIN = 128; b0 = 23; }
        else               { src = cv4;  dh = wh+WO_CV4;  dl = wl+WO_CV4;  CIN = 128; COUT = 128; b0 = 25; }
        const int base = (bid - b0) * 4096;
        const int per = CIN * COUT;
        #pragma unroll 4
        for (int j = 0; j < 16; j++) {
            int e = base + tid + j * 256;
            int tap = e / per, r = e - tap * per;
            int ci = r / COUT, co = r - ci * COUT;
            float w = src[e];
            __half h = __float2half_rn(w);
            __half l = __float2half_rn(w - __half2float(h));
            int d = tap * per + co * CIN + ci;
            dh[d] = *(u16*)&h; dl[d] = *(u16*)&l;
        }
    } else if (bid == 29) {
        auto seg = [&](int off, const float* s, int C, int stride, int choff){
            for (int c = tid; c < C; c += 256) {
                float g = s[choff + c], b = s[stride + choff + c];
                float m = s[2*stride + choff + c], v = s[3*stride + choff + c];
                float sc = g * rsqrtf(v + 1e-3f);
                sb[off + c] = sc; sb[off + C + c] = b - m * sc;
            }
        };
        seg(SB_CV1,  c1bn, 64, 64, 0);
        seg(SB_M0A,  a0bn, 64, 64, 0);
        seg(SB_M0B,  b0bn, 64, 64, 0);
        seg(SB_M1A,  a1bn, 64, 64, 0);
        seg(SB_M1B,  b1bn, 64, 64, 0);
        seg(SB_CATA, catbn, 64, 128, 0);
        seg(SB_CATB, catbn, 64, 128, 64);
        seg(SB_CV4,       c4bn, 64, 128, 0);
        seg(SB_CV4 + 128, c4bn, 64, 128, 64);
    } else {
        int i = (bid - 30) * 256 + tid;
        if (i >= 16 * 644) return;
        int img = i / 644, r = i - img * 644;
        int y, x;
        if      (r < 162) { y = 0;   x = r; }
        else if (r < 324) { y = 161; x = r - 162; }
        else if (r < 484) { x = 0;   y = r - 324 + 1; }
        else              { x = 161; y = r - 484 + 1; }
        long long q = (((long long)img * 162 + y) * 162 + x) * 64;
        uint4 z = make_uint4(0,0,0,0);
        #pragma unroll
        for (int c = 0; c < 8; c++) {
            *(uint4*)(th + q + c*8) = z; *(uint4*)(tl + q + c*8) = z;
            *(uint4*)(uh + q + c*8) = z; *(uint4*)(ul + q + c*8) = z;
        }
    }
}

// ─── 1x1 conv GEMM (HMMA, 2-term): persistent; cv4 only ────────────────────
template<int CIN, int OUTM, int ACT>
__global__ void __launch_bounds__(512, 2) g1x1(
    const u16* __restrict__ pah, const u16* __restrict__ pal,
    const u16* __restrict__ pbh, const u16* __restrict__ pbl,
    const u16* __restrict__ wh,
    const float* __restrict__ sb,
    float* __restrict__ of, int ntiles)
{
    constexpr int KB  = CIN / 64;
    constexpr int APL = 128 * STR * 2;
    constexpr int WPL = 64 * STR * 2;

    extern __shared__ char sm[];
    float* sbs  = (float*)sm;
    char* Wbase = sm + 512;                 // [kb] hi only
    char* Abase = Wbase + KB * WPL;

    const int tid = threadIdx.x;
    const int cy  = blockIdx.y;
    const u16* whp = wh + cy * 64 * CIN;

    for (int c = tid; c < 128; c += 512) sbs[c] = sb[cy * 128 + c];

    const u32 WA = smem_u32(Wbase), AA = smem_u32(Abase);

    #pragma unroll
    for (int kb = 0; kb < KB; kb++)
        for (int i = tid; i < 512; i += 512) {
            int n = i >> 3, c8 = i & 7;
            u32 off = kb * WPL + (n * STR + c8 * 8) * 2;
            CPA16(WA + off, whp + n * CIN + kb * 64 + c8 * 8);
        }

    auto stageA = [&](int t, int kb, int buf){
        long long p0 = (long long)t * 128;
        const u32 AH = AA + buf * 2 * APL;
        for (int i = tid; i < 1024; i += 512) {
            int row = i >> 3, c8 = i & 7;
            u32 off = (row * STR + c8 * 8) * 2;
            const u16* shp = kb ? pbh : pah;
            const u16* slp = kb ? pbl : pal;
            long long so = (p0 + row) * 64 + c8 * 8;
            CPA16(AH + off,       shp + so);
            CPA16(AH + APL + off, slp + so);
        }
    };

    const int warp = tid >> 5, lane = tid & 31;
    const int mrow = warp >> 1;
    const int nh   = warp & 1;
    const int arow  = 16 * mrow + (lane & 7) + ((lane & 8) ? 8 : 0);
    const int akoff = (lane & 16) ? 8 : 0;
    const u32 aOff = (arow * STR + akoff) * 2;
    const int brow  = (lane & 7) + ((lane & 16) ? 8 : 0);
    const int bkoff = (lane & 8) ? 8 : 0;
    const u32 bOff = ((nh * 32 + brow) * STR + bkoff) * 2;

    const int gr = lane >> 2, c2l = (lane & 3) * 2;
    const int coff = cy * 64 + nh * 32;

    const int t0 = blockIdx.x;
    if (t0 < ntiles) stageA(t0, 0, 0);
    CPA_COMMIT();

    int buf = 0;
    float accF[4][4];
    u32 accH[4][2];

    for (int t = t0; t < ntiles; t += gridDim.x) {
        #pragma unroll
        for (int n = 0; n < 4; n++) {
            #pragma unroll
            for (int j = 0; j < 4; j++) accF[n][j] = 0.f;
            accH[n][0] = 0u; accH[n][1] = 0u;
        }

        #pragma unroll
        for (int kb = 0; kb < KB; kb++) {
            int nt = t, nkb = kb + 1;
            if (nkb == KB) { nkb = 0; nt = t + gridDim.x; }
            const bool hn = (nt < ntiles);
            if (hn) stageA(nt, nkb, buf ^ 1);
            CPA_COMMIT();
            if (hn) { CPA_WAIT_G1(); } else { CPA_WAIT0(); }
            __syncthreads();

            const u32 aH = AA + buf * 2 * APL + aOff;
            const u32 aL = aH + APL;
            const u32 bH = WA + kb * WPL + bOff;

            gemm_block_n2(accF, accH, aH, aL, bH);

            if (kb == KB - 1) {
                #pragma unroll
                for (int rs = 0; rs < 2; rs++) {
                    int row = 16*mrow + 8*rs + gr;
                    long long p = (long long)t * 128 + row;
                    #pragma unroll
                    for (int nb = 0; nb < 4; nb++) {
                        int c = nh * 32 + 8*nb + c2l;
                        float2 hc = dec(accH[nb][rs]);
                        float v0 = sbs[c]     * (accF[nb][2*rs]     + hc.x) + sbs[64 + c];
                        float v1 = sbs[c + 1] * (accF[nb][2*rs + 1] + hc.y) + sbs[64 + c + 1];
                        if (ACT == 0) { v0 = hswish(v0); v1 = hswish(v1); }
                        else { v0 = v0 >= 0.f ? v0 : 0.1f*v0; v1 = v1 >= 0.f ? v1 : 0.1f*v1; }
                        *(float2*)(of + p * 128 + coff + 8*nb + c2l) = make_float2(v0, v1);
                    }
                }
            }
            __syncthreads();
            buf ^= 1;
        }
    }
}

// ─── cv1f2: cv2p(x)->b ; cv1(x)->y ; fused m0_cv1(y)->t padded (2-term) ────
__global__ void __launch_bounds__(512, 2) cv1f2(
    const float* __restrict__ xf,
    const u16* __restrict__ w2h, const u16* __restrict__ wh,
    const u16* __restrict__ w1h,
    const float* __restrict__ sb_b, const float* __restrict__ sb_y,
    const float* __restrict__ sb_t,
    u16* __restrict__ bh, u16* __restrict__ bl,
    u16* __restrict__ yh, u16* __restrict__ yl,
    u16* __restrict__ o2h, u16* __restrict__ o2l)
{
    constexpr int APL = 128 * STR * 2;
    constexpr int WPL = 64 * STR * 2;

    extern __shared__ char sm[];
    float* sbs = (float*)sm;
    char* Ab = sm + 1536;
    char* Wb = Ab + 4 * APL;             // [kb] hi only (2 WPL)

    const int tid = threadIdx.x;
    const long long p0 = (long long)blockIdx.x * 128;

    for (int c = tid; c < 128; c += 512) {
        sbs[c] = sb_b[c]; sbs[128 + c] = sb_y[c]; sbs[256 + c] = sb_t[c];
    }

    const u32 AbA = smem_u32(Ab), WbA = smem_u32(Wb);

    for (int i = tid; i < 1024; i += 512) {
        int kb = i >> 9, r = i & 511;
        int n = r >> 3, c8 = r & 7;
        u32 off = kb * WPL + (n * STR + c8 * 8) * 2;
        CPA16(WbA + off, w2h + n * 128 + kb * 64 + c8 * 8);
    }
    CPA_COMMIT();
    for (int i = tid; i < 2048; i += 512) {
        int row = i >> 4, c16 = i & 15;
        int kb = c16 >> 3, c8 = c16 & 7;
        const float* g = xf + (p0 + row) * 128 + c16 * 8;
        float4 f1 = *(const float4*)g, f2 = *(const float4*)(g + 4);
        uint4 H, L;
        sp2(f1.x, f1.y, H.x, L.x); sp2(f1.z, f1.w, H.y, L.y);
        sp2(f2.x, f2.y, H.z, L.z); sp2(f2.z, f2.w, H.w, L.w);
        u32 off = kb * 2 * APL + (row * STR + c8 * 8) * 2;
        *(uint4*)(Ab + off) = H; *(uint4*)(Ab + APL + off) = L;
    }
    CPA_WAIT0();
    __syncthreads();

    const int warp = tid >> 5, lane = tid & 31;
    const int mrow = warp >> 1;
    const int nh   = warp & 1;
    const int arow  = 16 * mrow + (lane & 7) + ((lane & 8) ? 8 : 0);
    const int akoff = (lane & 16) ? 8 : 0;
    const u32 aOff = (arow * STR + akoff) * 2;
    const int brow  = (lane & 7) + ((lane & 16) ? 8 : 0);
    const int bkoff = (lane & 8) ? 8 : 0;
    const u32 bOff = ((nh * 32 + brow) * STR + bkoff) * 2;
    const int gr = lane >> 2, c2l = (lane & 3) * 2;

    float accF[4][4];
    u32 accH[4][2];

    // phase 1: cv2p -> b (leaky)
    #pragma unroll
    for (int n = 0; n < 4; n++) {
        #pragma unroll
        for (int j = 0; j < 4; j++) accF[n][j] = 0.f;
        accH[n][0] = 0u; accH[n][1] = 0u;
    }
    #pragma unroll
    for (int kb = 0; kb < 2; kb++)
        gemm_block_n2(accF, accH,
                      AbA + kb * 2 * APL + aOff, AbA + kb * 2 * APL + APL + aOff,
                      WbA + kb * WPL + bOff);

    #pragma unroll
    for (int rs = 0; rs < 2; rs++) {
        long long p = p0 + 16 * mrow + 8*rs + gr;
        #pragma unroll
        for (int nb = 0; nb < 4; nb++) {
            int c = nh * 32 + 8*nb + c2l;
            float2 hc = dec(accH[nb][rs]);
            float v0 = sbs[c]     * (accF[nb][2*rs]     + hc.x) + sbs[64 + c];
            float v1 = sbs[c + 1] * (accF[nb][2*rs + 1] + hc.y) + sbs[64 + c + 1];
            v0 = v0 >= 0.f ? v0 : 0.1f*v0; v1 = v1 >= 0.f ? v1 : 0.1f*v1;
            u32 H, L; sp2(v0, v1, H, L);
            *(u32*)(bh + p * 64 + c) = H;
            *(u32*)(bl + p * 64 + c) = L;
        }
    }
    __syncthreads();

    // phase 2: cv1 -> y (hswish); stash y into Ab kb0
    for (int i = tid; i < 1024; i += 512) {
        int kb = i >> 9, r = i & 511;
        int n = r >> 3, c8 = r & 7;
        u32 off = kb * WPL + (n * STR + c8 * 8) * 2;
        CPA16(WbA + off, wh + n * 128 + kb * 64 + c8 * 8);
    }
    CPA_WAIT();
    __syncthreads();

    #pragma unroll
    for (int n = 0; n < 4; n++) {
        #pragma unroll
        for (int j = 0; j < 4; j++) accF[n][j] = 0.f;
        accH[n][0] = 0u; accH[n][1] = 0u;
    }
    #pragma unroll
    for (int kb = 0; kb < 2; kb++)
        gemm_block_n2(accF, accH,
                      AbA + kb * 2 * APL + aOff, AbA + kb * 2 * APL + APL + aOff,
                      WbA + kb * WPL + bOff);
    __syncthreads();

    #pragma unroll
    for (int rs = 0; rs < 2; rs++) {
        int px = 16 * mrow + 8*rs + gr;
        long long p = p0 + px;
        #pragma unroll
        for (int nb = 0; nb < 4; nb++) {
            int c = nh * 32 + 8*nb + c2l;
            float2 hc = dec(accH[nb][rs]);
            float v0 = sbs[128 + c]     * (accF[nb][2*rs]     + hc.x) + sbs[192 + c];
            float v1 = sbs[128 + c + 1] * (accF[nb][2*rs + 1] + hc.y) + sbs[192 + c + 1];
            v0 = hswish(v0); v1 = hswish(v1);
            u32 H, L; sp2(v0, v1, H, L);
            *(u32*)(yh + p * 64 + c) = H;
            *(u32*)(yl + p * 64 + c) = L;
            u32 off = (px * STR + c) * 2;
            *(u32*)(Ab + off)       = H;
            *(u32*)(Ab + APL + off) = L;
        }
    }

    // phase 3: m0_cv1(y) -> t padded (hswish)
    for (int i = tid; i < 512; i += 512) {
        int n = i >> 3, c8 = i & 7;
        u32 off = (n * STR + c8 * 8) * 2;
        CPA16(WbA + off, w1h + n*64 + c8*8);
    }
    CPA_WAIT();
    __syncthreads();

    #pragma unroll
    for (int n = 0; n < 4; n++) {
        #pragma unroll
        for (int j = 0; j < 4; j++) accF[n][j] = 0.f;
        accH[n][0] = 0u; accH[n][1] = 0u;
    }
    gemm_block_n2(accF, accH, AbA + aOff, AbA + APL + aOff, WbA + bOff);

    #pragma unroll
    for (int rs = 0; rs < 2; rs++) {
        int px = 16 * mrow + 8*rs + gr;
        long long p = p0 + px;
        int pi = (int)p;
        int img = pi / 25600, r = pi - img * 25600;
        int y = r / 160, x = r - y * 160;
        long long q2 = (((long long)img * 162 + y + 1) * 162 + (x + 1)) * 64;
        #pragma unroll
        for (int nb = 0; nb < 4; nb++) {
            int c = nh * 32 + 8*nb + c2l;
            float2 hc = dec(accH[nb][rs]);
            float v0 = sbs[256 + c]     * (accF[nb][2*rs]     + hc.x) + sbs[320 + c];
            float v1 = sbs[256 + c + 1] * (accF[nb][2*rs + 1] + hc.y) + sbs[320 + c + 1];
            v0 = hswish(v0); v1 = hswish(v1);
            u32 H, L; sp2(v0, v1, H, L);
            *(u32*)(o2h + q2 + c) = H;
            *(u32*)(o2l + q2 + c) = L;
        }
    }
}

// ─── fused 3x3 conv (2-term taps) + tile-local 1x1 conv (2-term) ───────────
template<int DST>
__global__ void __launch_bounds__(512, 2) c3x3f(
    const u16* __restrict__ th, const u16* __restrict__ tl,
    const u16* __restrict__ wh,
    const u16* __restrict__ w1h,
    const float* __restrict__ sb, const float* __restrict__ sb2,
    u16* __restrict__ yh, u16* __restrict__ yl,
    u16* __restrict__ o2h, u16* __restrict__ o2l)
{
    constexpr int APL = 180 * STR * 2;
    constexpr int WPL = 64 * STR * 2;
    constexpr int YPL = 128 * STR * 2;

    extern __shared__ char sm[];
    float* sbs = (float*)sm;
    char* Ah = sm + 1024;
    char* Al = Ah + APL;
    char* Wb = Al + APL;                 // taps: [buf] hi-only; later y stash (2 YPL)

    const int tid = threadIdx.x;
    const int blk = blockIdx.x;
    const int img = blk / 200, t = blk - img * 200;
    const int ty = t / 10, tx = t - ty * 10;
    const int y0 = ty * 8, x0 = tx * 16;

    for (int c = tid; c < 128; c += 512) { sbs[c] = sb[c]; sbs[128 + c] = sb2[c]; }

    const u32 AhA = smem_u32(Ah), AlA = smem_u32(Al), WbA = smem_u32(Wb);

    for (int i = tid; i < 1440; i += 512) {
        int hr = i >> 3, c8 = i & 7;
        int hy = hr / 18, hx = hr - hy * 18;
        long long s = (((long long)img * 162 + y0 + hy) * 162 + (x0 + hx)) * 64 + c8 * 8;
        u32 off = (hr * STR + c8 * 8) * 2;
        CPA16(AhA + off, th + s);
        CPA16(AlA + off, tl + s);
    }
    for (int i = tid; i < 512; i += 512) {
        int n = i >> 3, c8 = i & 7;
        u32 off = (n * STR + c8 * 8) * 2;
        CPA16(WbA + off, wh + n*64 + c8*8);
    }
    CPA_WAIT();
    __syncthreads();

    const int warp = tid >> 5, lane = tid & 31;
    const int row = warp >> 1;
    const int nh  = warp & 1;
    const int acol  = lane & 15;
    const int akoff = (lane & 16) ? 8 : 0;
    const int brow  = (lane & 7) + ((lane & 16) ? 8 : 0);
    const int bkoff = (lane & 8) ? 8 : 0;
    const u32 bOff = ((nh * 32 + brow) * STR + bkoff) * 2;

    float accF[4][4];
    u32 accH[4][2];
    #pragma unroll
    for (int n = 0; n < 4; n++) {
        #pragma unroll
        for (int j = 0; j < 4; j++) accF[n][j] = 0.f;
        accH[n][0] = 0u; accH[n][1] = 0u;
    }

    for (int tap = 0; tap < 9; tap++) {
        const int buf = tap & 1;
        if (tap < 8) {
            const u16* sh = wh + (tap+1)*4096;
            const u32 WA = WbA + (buf^1)*WPL;
            for (int i = tid; i < 512; i += 512) {
                int n = i >> 3, c8 = i & 7;
                u32 off = (n * STR + c8 * 8) * 2;
                CPA16(WA + off, sh + n*64 + c8*8);
            }
            CPA_COMMIT();
        }
        const int kh = tap / 3, kw = tap - kh * 3;
        const int hr = (row + kh) * 18 + acol + kw;
        const u32 aH = AhA + (hr * STR + akoff) * 2;
        const u32 aL = AlA + (hr * STR + akoff) * 2;
        const u32 bH = WbA + buf*WPL + bOff;

        gemm_block_n2(accF, accH, aH, aL, bH);

        if (tap < 8) {
            CPA_WAIT0();
            __syncthreads();
        }
    }
    __syncthreads();

    const int gr = lane >> 2, c2l = (lane & 3) * 2;
    #pragma unroll
    for (int rs = 0; rs < 2; rs++) {
        int xx = 8*rs + gr;
        int px = row * 16 + xx;
        long long q = ((long long)img * 25600 + (y0 + row) * 160 + (x0 + xx)) * 64;
        #pragma unroll
        for (int nb = 0; nb < 4; nb++) {
            int c = nh * 32 + 8*nb + c2l;
            float2 yv0 = dec(*(const u32*)(yh + q + c));
            float2 yv1 = dec(*(const u32*)(yl + q + c));
            float2 hc  = dec(accH[nb][rs]);
            float v0 = sbs[c]     * (accF[nb][2*rs]     + hc.x) + sbs[64 + c];
            float v1 = sbs[c + 1] * (accF[nb][2*rs + 1] + hc.y) + sbs[64 + c + 1];
            v0 = hswish(v0) + yv0.x + yv1.x;
            v1 = hswish(v1) + yv0.y + yv1.y;
            u32 H, L; sp2(v0, v1, H, L);
            if (DST == 0) {
                *(u32*)(yh + q + c) = H;
                *(u32*)(yl + q + c) = L;
            }
            u32 off = (px * STR + c) * 2;
            *(u32*)(Wb + off)       = H;
            *(u32*)(Wb + YPL + off) = L;
        }
    }

    for (int i = tid; i < 512; i += 512) {
        int n = i >> 3, c8 = i & 7;
        u32 off = (n * STR + c8 * 8) * 2;
        CPA16(AhA + off, w1h + n*64 + c8*8);
    }
    CPA_WAIT();
    __syncthreads();

    {
        const int mblk = warp >> 1;
        const int arow2 = 16 * mblk + (lane & 7) + ((lane & 8) ? 8 : 0);
        const u32 aOff2 = (arow2 * STR + akoff) * 2;
        #pragma unroll
        for (int n = 0; n < 4; n++) {
            #pragma unroll
            for (int j = 0; j < 4; j++) accF[n][j] = 0.f;
            accH[n][0] = 0u; accH[n][1] = 0u;
        }
        gemm_block_n2(accF, accH, WbA + aOff2, WbA + YPL + aOff2, AhA + bOff);

        #pragma unroll
        for (int rs = 0; rs < 2; rs++) {
            int px = 16 * mblk + 8*rs + gr;
            int yy = px >> 4, xx = px & 15;
            long long q2;
            if (DST == 0)
                q2 = (((long long)img * 162 + y0 + yy + 1) * 162 + (x0 + xx + 1)) * 64;
            else
                q2 = ((long long)img * 25600 + (y0 + yy) * 160 + (x0 + xx)) * 64;
            #pragma unroll
            for (int nb = 0; nb < 4; nb++) {
                int c = nh * 32 + 8*nb + c2l;
                float2 hc = dec(accH[nb][rs]);
                float v0 = sbs[128 + c]     * (accF[nb][2*rs]     + hc.x) + sbs[192 + c];
                float v1 = sbs[128 + c + 1] * (accF[nb][2*rs + 1] + hc.y) + sbs[192 + c + 1];
                if (DST == 0) { v0 = hswish(v0); v1 = hswish(v1); }
                else { v0 = v0 >= 0.f ? v0 : 0.1f*v0; v1 = v1 >= 0.f ? v1 : 0.1f*v1; }
                u32 H, L; sp2(v0, v1, H, L);
                *(u32*)(o2h + q2 + c) = H;
                *(u32*)(o2l + q2 + c) = L;
            }
        }
    }
}

// ─── host ──────────────────────────────────────────────────────────────────
extern "C" void kernel_launch(void* const* d_in, const int* in_sizes, int n_in,
                              void* d_out, int out_size)
{
    (void)in_sizes; (void)n_in; (void)out_size;
    const float* x         = (const float*)d_in[0];
    const float* cv1_w     = (const float*)d_in[1];
    const float* cv1_bn    = (const float*)d_in[2];
    const float* m0_cv1_w  = (const float*)d_in[3];
    const float* m0_cv1_bn = (const float*)d_in[4];
    const float* m0_cv2_w  = (const float*)d_in[5];
    const float* m0_cv2_bn = (const float*)d_in[6];
    const float* m1_cv1_w  = (const float*)d_in[7];
    const float* m1_cv1_bn = (const float*)d_in[8];
    const float* m1_cv2_w  = (const float*)d_in[9];
    const float* m1_cv2_bn = (const float*)d_in[10];
    const float* cv3_w     = (const float*)d_in[11];
    const float* cv2p_w    = (const float*)d_in[12];
    const float* bn_cat    = (const float*)d_in[13];
    const float* cv4_w     = (const float*)d_in[14];
    const float* cv4_bn    = (const float*)d_in[15];
    float* out = (float*)d_out;

    u16 *yh, *yl, *ah, *al, *bh, *bl, *th, *tl, *uh, *ul, *wh, *wl;
    float* sb;
    cudaGetSymbolAddress((void**)&yh, g_yh); cudaGetSymbolAddress((void**)&yl, g_yl);
    cudaGetSymbolAddress((void**)&ah, g_ah); cudaGetSymbolAddress((void**)&al, g_al);
    cudaGetSymbolAddress((void**)&bh, g_bh); cudaGetSymbolAddress((void**)&bl, g_bl);
    cudaGetSymbolAddress((void**)&th, g_th); cudaGetSymbolAddress((void**)&tl, g_tl);
    cudaGetSymbolAddress((void**)&uh, g_uh); cudaGetSymbolAddress((void**)&ul, g_ul);
    cudaGetSymbolAddress((void**)&wh, g_wh); cudaGetSymbolAddress((void**)&wl, g_wl);
    cudaGetSymbolAddress((void**)&sb, g_sb);

    constexpr int S1_128 = 512 + 2*9216 + 2*2*18432;       // 92672
    constexpr int SCF    = 1536 + 4*18432 + 2*9216;        // 93696
    constexpr int S3     = 1024 + 2*25920 + 4*9216;        // 89728
    constexpr int NT = 3200;
    constexpr int GP = 304;

    cudaFuncSetAttribute(cv1f2,        cudaFuncAttributeMaxDynamicSharedMemorySize, SCF);
    cudaFuncSetAttribute(g1x1<128,2,0>, cudaFuncAttributeMaxDynamicSharedMemorySize, S1_128);
    cudaFuncSetAttribute(c3x3f<0>,     cudaFuncAttributeMaxDynamicSharedMemorySize, S3);
    cudaFuncSetAttribute(c3x3f<1>,     cudaFuncAttributeMaxDynamicSharedMemorySize, S3);

    prep_all<<<71, 256>>>(cv1_w, m0_cv1_w, m0_cv2_w, m1_cv1_w, m1_cv2_w,
                          cv3_w, cv2p_w, cv4_w,
                          cv1_bn, m0_cv1_bn, m0_cv2_bn, m1_cv1_bn, m1_cv2_bn,
                          bn_cat, cv4_bn, wh, wl, sb, th, tl, uh, ul);

    // cv2p + cv1 + fused m0_cv1: x -> b planes, y planes, t padded
    cv1f2<<<3200,512,SCF>>>(x,
                            wh+WO_CV2P, wh+WO_CV1, wh+WO_M0A,
                            sb+SB_CATB, sb+SB_CV1, sb+SB_M0A,
                            bh, bl, yh, yl, th, tl);
    // bottleneck0 3x3 + residual -> y ; fused m1_cv1(y) -> u
    c3x3f<0><<<3200,512,S3>>>(th, tl, wh+WO_M0B, wh+WO_M1A,
                              sb+SB_M0B, sb+SB_M1A, yh, yl, uh, ul);
    // bottleneck1 3x3 (reads u) + residual -> y ; fused cv3(y)+bn_cat+leaky -> a
    c3x3f<1><<<3200,512,S3>>>(uh, ul, wh+WO_M1B, wh+WO_CV3,
                              sb+SB_M1B, sb+SB_CATA, yh, yl, ah, al);
    // cv4: concat(a,b) 128->128 BN+hswish -> out fp32
    g1x1<128,2,0><<<dim3(GP,2),512,S1_128>>>(ah,al, bh,bl, wh+WO_CV4, sb+SB_CV4, out, NT);
}